// round 2
// baseline (speedup 1.0000x reference)
#include <cuda_runtime.h>
#include <math.h>

#define NN 100000
#define NE 1600000
#define NB 64
#define FD 128
#define NC 16

// ---------------- scratch (device globals; no allocations) ----------------
__device__ float    g_bufA[NN * FD];
__device__ float    g_bufB[NN * FD];
__device__ float    g_dinv[NN];
__device__ int      g_indeg[NN];
__device__ int      g_ctr[NN];
__device__ int      g_rowptr[NN + 1];
__device__ int      g_esrc[NE];
__device__ float    g_gate[NN];
__device__ unsigned g_gmaxU[NB];
__device__ float    g_denom[NB];
__device__ float    g_pooled[NB * FD];

// ---------------- helpers ----------------
__device__ __forceinline__ unsigned long long pk2(float lo, float hi) {
    unsigned long long r;
    asm("mov.b64 %0, {%1,%2};" : "=l"(r) : "f"(lo), "f"(hi));
    return r;
}
__device__ __forceinline__ void upk2(unsigned long long v, float& lo, float& hi) {
    asm("mov.b64 {%0,%1}, %2;" : "=f"(lo), "=f"(hi) : "l"(v));
}
__device__ __forceinline__ void fma2(unsigned long long& acc, unsigned long long a,
                                     unsigned long long b) {
    asm("fma.rn.f32x2 %0, %1, %2, %0;" : "+l"(acc) : "l"(a), "l"(b));
}
// order-preserving float<->uint key for atomicMax over signed floats
__device__ __forceinline__ unsigned fkey(float f) {
    unsigned u = __float_as_uint(f);
    return (u & 0x80000000u) ? ~u : (u | 0x80000000u);
}
__device__ __forceinline__ float fdekey(unsigned k) {
    unsigned u = (k & 0x80000000u) ? (k ^ 0x80000000u) : ~k;
    return __uint_as_float(u);
}

// ---------------- kernels ----------------
__global__ __launch_bounds__(256) void init_kernel() {
    int i = blockIdx.x * blockDim.x + threadIdx.x;
    if (i < NN) { g_indeg[i] = 0; g_ctr[i] = 0; }
    if (i < NB * FD) g_pooled[i] = 0.f;
    if (i < NB) { g_denom[i] = 0.f; g_gmaxU[i] = 0x007FFFFFu; /* key(-inf) */ }
}

__global__ __launch_bounds__(256) void deg_kernel(const int* __restrict__ dst) {
    int e = blockIdx.x * blockDim.x + threadIdx.x;
    if (e < NE) atomicAdd(&g_indeg[dst[e]], 1);
}

__global__ __launch_bounds__(256) void dinv_kernel() {
    int n = blockIdx.x * blockDim.x + threadIdx.x;
    if (n < NN) g_dinv[n] = rsqrtf((float)(g_indeg[n] + 1));
}

__global__ __launch_bounds__(1024) void scan_kernel() {
    __shared__ int s[1024];
    const int CH = 98;  // 1024*98 = 100352 >= NN
    int t = threadIdx.x;
    int start = t * CH;
    int sum = 0;
    for (int i = 0; i < CH; i++) {
        int idx = start + i;
        if (idx < NN) sum += g_indeg[idx];
    }
    s[t] = sum;
    __syncthreads();
    for (int off = 1; off < 1024; off <<= 1) {
        int v = 0;
        if (t >= off) v = s[t - off];
        __syncthreads();
        s[t] += v;
        __syncthreads();
    }
    int run = s[t] - sum;  // exclusive
    for (int i = 0; i < CH; i++) {
        int idx = start + i;
        if (idx < NN) { g_rowptr[idx] = run; run += g_indeg[idx]; }
    }
    if (t == 1023) g_rowptr[NN] = s[1023];
}

__global__ __launch_bounds__(256) void fill_kernel(const int* __restrict__ src,
                                                   const int* __restrict__ dst) {
    int e = blockIdx.x * blockDim.x + threadIdx.x;
    if (e < NE) {
        int d = dst[e];
        int p = g_rowptr[d] + atomicAdd(&g_ctr[d], 1);
        g_esrc[p] = src[e];
    }
}

// Y[n,:] = X[n,:] @ W  (128x128), W staged in 64KB dynamic smem, f32x2 packed FMA
__global__ __launch_bounds__(256) void gemm_kernel(const float* __restrict__ X,
                                                   const float* __restrict__ W,
                                                   float* __restrict__ Y) {
    extern __shared__ float4 sW[];  // [128][32] float4 = 64KB: sW[k*32+l] = W[k][4l..4l+3]
    int tid = threadIdx.x;
    const float4* W4 = (const float4*)W;
    for (int i = tid; i < FD * 32; i += 256) sW[i] = W4[i];
    __syncthreads();

    int warp = (blockIdx.x * blockDim.x + tid) >> 5;
    int nwarps = (gridDim.x * blockDim.x) >> 5;
    int lane = tid & 31;
    const float4* X4 = (const float4*)X;
    float4* Y4 = (float4*)Y;

    for (int row = warp; row < NN; row += nwarps) {
        float4 xv = X4[row * 32 + lane];
        unsigned long long a01 = pk2(0.f, 0.f), a23 = pk2(0.f, 0.f);
#pragma unroll
        for (int kl = 0; kl < 32; kl++) {
            float b0 = __shfl_sync(0xffffffffu, xv.x, kl);
            float b1 = __shfl_sync(0xffffffffu, xv.y, kl);
            float b2 = __shfl_sync(0xffffffffu, xv.z, kl);
            float b3 = __shfl_sync(0xffffffffu, xv.w, kl);
#define STEP(V, E)                                               \
            {                                                    \
                float4 w = sW[(kl * 4 + (E)) * 32 + lane];       \
                unsigned long long xx = pk2((V), (V));           \
                fma2(a01, pk2(w.x, w.y), xx);                    \
                fma2(a23, pk2(w.z, w.w), xx);                    \
            }
            STEP(b0, 0) STEP(b1, 1) STEP(b2, 2) STEP(b3, 3)
#undef STEP
        }
        float4 o;
        upk2(a01, o.x, o.y);
        upk2(a23, o.z, o.w);
        Y4[row * 32 + lane] = o;
    }
}

// per-node CSR aggregation + bias + layernorm + relu (one warp per node)
__global__ __launch_bounds__(256) void agg_ln_relu_kernel(const float* __restrict__ H,
                                                          float* __restrict__ Z,
                                                          const float* __restrict__ bias,
                                                          const float* __restrict__ gam,
                                                          const float* __restrict__ bet) {
    int gw = (blockIdx.x * blockDim.x + threadIdx.x) >> 5;
    if (gw >= NN) return;
    int lane = threadIdx.x & 31;
    int n = gw;
    int r0 = g_rowptr[n], r1 = g_rowptr[n + 1];
    float dn = g_dinv[n];
    const float4* H4 = (const float4*)H;

    float4 self = H4[n * 32 + lane];
    float4 acc;
    acc.x = dn * self.x; acc.y = dn * self.y; acc.z = dn * self.z; acc.w = dn * self.w;

    int i = r0;
    for (; i + 4 <= r1; i += 4) {
        int s0 = g_esrc[i], s1 = g_esrc[i + 1], s2 = g_esrc[i + 2], s3 = g_esrc[i + 3];
        float w0 = g_dinv[s0], w1 = g_dinv[s1], w2 = g_dinv[s2], w3 = g_dinv[s3];
        float4 h0 = H4[s0 * 32 + lane];
        float4 h1 = H4[s1 * 32 + lane];
        float4 h2 = H4[s2 * 32 + lane];
        float4 h3 = H4[s3 * 32 + lane];
        acc.x += w0 * h0.x + w1 * h1.x + w2 * h2.x + w3 * h3.x;
        acc.y += w0 * h0.y + w1 * h1.y + w2 * h2.y + w3 * h3.y;
        acc.z += w0 * h0.z + w1 * h1.z + w2 * h2.z + w3 * h3.z;
        acc.w += w0 * h0.w + w1 * h1.w + w2 * h2.w + w3 * h3.w;
    }
    for (; i < r1; i++) {
        int s = g_esrc[i];
        float w = g_dinv[s];
        float4 h = H4[s * 32 + lane];
        acc.x += w * h.x; acc.y += w * h.y; acc.z += w * h.z; acc.w += w * h.w;
    }

    const float4* b4p = (const float4*)bias;
    float4 b4 = b4p[lane];
    acc.x = acc.x * dn + b4.x;
    acc.y = acc.y * dn + b4.y;
    acc.z = acc.z * dn + b4.z;
    acc.w = acc.w * dn + b4.w;

    // layernorm over 128 features (4 per lane)
    float s = acc.x + acc.y + acc.z + acc.w;
#pragma unroll
    for (int o = 16; o; o >>= 1) s += __shfl_xor_sync(0xffffffffu, s, o);
    float mean = s * (1.0f / FD);
    float dx = acc.x - mean, dy = acc.y - mean, dz = acc.z - mean, dw = acc.w - mean;
    float ss = dx * dx + dy * dy + dz * dz + dw * dw;
#pragma unroll
    for (int o = 16; o; o >>= 1) ss += __shfl_xor_sync(0xffffffffu, ss, o);
    float rstd = rsqrtf(ss * (1.0f / FD) + 1e-5f);

    const float4* g4p = (const float4*)gam;
    const float4* e4p = (const float4*)bet;
    float4 g4 = g4p[lane], e4 = e4p[lane];
    float4 out;
    out.x = fmaxf(dx * rstd * g4.x + e4.x, 0.f);
    out.y = fmaxf(dy * rstd * g4.y + e4.y, 0.f);
    out.z = fmaxf(dz * rstd * g4.z + e4.z, 0.f);
    out.w = fmaxf(dw * rstd * g4.w + e4.w, 0.f);
    ((float4*)Z)[n * 32 + lane] = out;
}

// gate[n] = relu(z[n]@Wg1 + bg1) @ Wg2 + bg2 ; segment max via uint atomicMax
__global__ __launch_bounds__(256) void gate_kernel(const float* __restrict__ Z,
                                                   const float* __restrict__ Wg1,
                                                   const float* __restrict__ bg1,
                                                   const float* __restrict__ Wg2,
                                                   const float* __restrict__ bg2,
                                                   const int* __restrict__ batch) {
    __shared__ float sW1[FD * 64];
    __shared__ float sW2[64];
    __shared__ float sB1[64];
    int tid = threadIdx.x;
    for (int i = tid; i < FD * 64; i += 256) sW1[i] = Wg1[i];
    if (tid < 64) { sW2[tid] = Wg2[tid]; sB1[tid] = bg1[tid]; }
    __syncthreads();

    int warp = (blockIdx.x * blockDim.x + tid) >> 5;
    int nwarps = (gridDim.x * blockDim.x) >> 5;
    int lane = tid & 31;
    int j0 = lane * 2;
    const float4* Z4 = (const float4*)Z;
    float bg2v = bg2[0];

    for (int n = warp; n < NN; n += nwarps) {
        float4 xv = Z4[n * 32 + lane];
        unsigned long long acc = pk2(0.f, 0.f);
#pragma unroll
        for (int kl = 0; kl < 32; kl++) {
            float b0 = __shfl_sync(0xffffffffu, xv.x, kl);
            float b1 = __shfl_sync(0xffffffffu, xv.y, kl);
            float b2 = __shfl_sync(0xffffffffu, xv.z, kl);
            float b3 = __shfl_sync(0xffffffffu, xv.w, kl);
#define GSTEP(V, E)                                                      \
            {                                                            \
                const float2 w = *(const float2*)&sW1[(kl * 4 + (E)) * 64 + j0]; \
                fma2(acc, pk2(w.x, w.y), pk2((V), (V)));                 \
            }
            GSTEP(b0, 0) GSTEP(b1, 1) GSTEP(b2, 2) GSTEP(b3, 3)
#undef GSTEP
        }
        float h0, h1;
        upk2(acc, h0, h1);
        h0 = fmaxf(h0 + sB1[j0], 0.f);
        h1 = fmaxf(h1 + sB1[j0 + 1], 0.f);
        float part = h0 * sW2[j0] + h1 * sW2[j0 + 1];
#pragma unroll
        for (int o = 16; o; o >>= 1) part += __shfl_xor_sync(0xffffffffu, part, o);
        if (lane == 0) {
            float gt = part + bg2v;
            g_gate[n] = gt;
            atomicMax(&g_gmaxU[batch[n]], fkey(gt));
        }
    }
}

__global__ __launch_bounds__(256) void denom_kernel(const int* __restrict__ batch) {
    int n = blockIdx.x * blockDim.x + threadIdx.x;
    if (n < NN) {
        int b = batch[n];
        float m = fdekey(g_gmaxU[b]);
        atomicAdd(&g_denom[b], expf(g_gate[n] - m));
    }
}

// weighted pooling: batch is sorted -> warp accumulates a 64-node chunk, flushes on
// graph boundary (few thousand float atomics total)
__global__ __launch_bounds__(256) void pooled_kernel(const float* __restrict__ Z,
                                                     const int* __restrict__ batch) {
    const int C = 64;
    int warp = (blockIdx.x * blockDim.x + threadIdx.x) >> 5;
    int lane = threadIdx.x & 31;
    int n0 = warp * C;
    if (n0 >= NN) return;
    int nend = min(n0 + C, NN);
    const float4* Z4 = (const float4*)Z;

    float4 acc = make_float4(0.f, 0.f, 0.f, 0.f);
    int curb = -1;
    float m = 0.f, den = 1.f;
    for (int n = n0; n < nend; n++) {
        int b = batch[n];
        if (b != curb) {
            if (curb >= 0) {
                float* p = &g_pooled[curb * FD + lane * 4];
                atomicAdd(p + 0, acc.x); atomicAdd(p + 1, acc.y);
                atomicAdd(p + 2, acc.z); atomicAdd(p + 3, acc.w);
                acc = make_float4(0.f, 0.f, 0.f, 0.f);
            }
            curb = b;
            m = fdekey(g_gmaxU[b]);
            den = g_denom[b];
        }
        float alpha = expf(g_gate[n] - m) / den;
        float4 z = Z4[n * 32 + lane];
        acc.x += alpha * z.x; acc.y += alpha * z.y;
        acc.z += alpha * z.z; acc.w += alpha * z.w;
    }
    if (curb >= 0) {
        float* p = &g_pooled[curb * FD + lane * 4];
        atomicAdd(p + 0, acc.x); atomicAdd(p + 1, acc.y);
        atomicAdd(p + 2, acc.z); atomicAdd(p + 3, acc.w);
    }
}

__global__ __launch_bounds__(256) void cls_kernel(const float* __restrict__ Wc,
                                                  const float* __restrict__ bc,
                                                  float* __restrict__ out) {
    int t = blockIdx.x * blockDim.x + threadIdx.x;
    if (t < NB * NC) {
        int b = t >> 4, c = t & 15;
        float s = bc[c];
        const float* p = &g_pooled[b * FD];
#pragma unroll 16
        for (int j = 0; j < FD; j++) s += p[j] * Wc[j * NC + c];
        out[t] = s;
    }
}

// ---------------- launch ----------------
extern "C" void kernel_launch(void* const* d_in, const int* in_sizes, int n_in,
                              void* d_out, int out_size) {
    const float* x    = (const float*)d_in[0];
    const int*   ei   = (const int*)d_in[1];
    const int*   batch= (const int*)d_in[2];
    const float* W1   = (const float*)d_in[3];
    const float* b1   = (const float*)d_in[4];
    const float* g1   = (const float*)d_in[5];
    const float* be1  = (const float*)d_in[6];
    const float* W2   = (const float*)d_in[7];
    const float* b2   = (const float*)d_in[8];
    const float* g2   = (const float*)d_in[9];
    const float* be2  = (const float*)d_in[10];
    const float* Wg1  = (const float*)d_in[11];
    const float* bg1  = (const float*)d_in[12];
    const float* Wg2  = (const float*)d_in[13];
    const float* bg2  = (const float*)d_in[14];
    const float* Wc   = (const float*)d_in[15];
    const float* bc   = (const float*)d_in[16];
    float* out = (float*)d_out;

    const int* src = ei;
    const int* dst = ei + NE;

    static bool attr_done = false;
    if (!attr_done) {
        cudaFuncSetAttribute(gemm_kernel, cudaFuncAttributeMaxDynamicSharedMemorySize, 65536);
        attr_done = true;
    }

    float* bufA; cudaGetSymbolAddress((void**)&bufA, g_bufA);
    float* bufB; cudaGetSymbolAddress((void**)&bufB, g_bufB);

    init_kernel<<<(NN + 255) / 256, 256>>>();
    deg_kernel<<<(NE + 255) / 256, 256>>>(dst);
    dinv_kernel<<<(NN + 255) / 256, 256>>>();
    scan_kernel<<<1, 1024>>>();
    fill_kernel<<<(NE + 255) / 256, 256>>>(src, dst);

    // layer 1
    gemm_kernel<<<444, 256, 65536>>>(x, W1, bufA);
    agg_ln_relu_kernel<<<(NN * 32 + 255) / 256, 256>>>(bufA, bufB, b1, g1, be1);
    // layer 2
    gemm_kernel<<<444, 256, 65536>>>(bufB, W2, bufA);
    agg_ln_relu_kernel<<<(NN * 32 + 255) / 256, 256>>>(bufA, bufB, b2, g2, be2);

    // attention pooling
    gate_kernel<<<592, 256>>>(bufB, Wg1, bg1, Wg2, bg2, batch);
    denom_kernel<<<(NN + 255) / 256, 256>>>(batch);
    pooled_kernel<<<(((NN + 63) / 64) * 32 + 255) / 256, 256>>>(bufB, batch);

    // classifier
    cls_kernel<<<(NB * NC + 255) / 256, 256>>>(Wc, bc, out);
}

// round 3
// speedup vs baseline: 1.8494x; 1.8494x over previous
#include <cuda_runtime.h>
#include <math.h>

#define NN 100000
#define NE 1600000
#define NB 64
#define FD 128
#define NC 16
#define NPB 196  // ceil(NN/512) scan blocks

// ---------------- scratch (device globals; no allocations) ----------------
__device__ float    g_bufA[NN * FD];
__device__ float    g_bufB[NN * FD];
__device__ float    g_dinv[NN];
__device__ int      g_indeg[NN];
__device__ int      g_ctr[NN];
__device__ int      g_rowptr[NN + 1];
__device__ int      g_part[NPB];
__device__ int      g_partoff[NPB];
__device__ int      g_esrc[NE];
__device__ float    g_gate[NN];
__device__ unsigned g_gmaxU[NB];
__device__ float    g_denom[NB];
__device__ float    g_pooled[NB * FD];

// ---------------- helpers ----------------
__device__ __forceinline__ unsigned long long pk2(float lo, float hi) {
    unsigned long long r;
    asm("mov.b64 %0, {%1,%2};" : "=l"(r) : "f"(lo), "f"(hi));
    return r;
}
__device__ __forceinline__ void upk2(unsigned long long v, float& lo, float& hi) {
    asm("mov.b64 {%0,%1}, %2;" : "=f"(lo), "=f"(hi) : "l"(v));
}
__device__ __forceinline__ void fma2(unsigned long long& acc, unsigned long long a,
                                     unsigned long long b) {
    asm("fma.rn.f32x2 %0, %1, %2, %0;" : "+l"(acc) : "l"(a), "l"(b));
}
__device__ __forceinline__ unsigned fkey(float f) {
    unsigned u = __float_as_uint(f);
    return (u & 0x80000000u) ? ~u : (u | 0x80000000u);
}
__device__ __forceinline__ float fdekey(unsigned k) {
    unsigned u = (k & 0x80000000u) ? (k ^ 0x80000000u) : ~k;
    return __uint_as_float(u);
}

// ---------------- setup kernels ----------------
__global__ __launch_bounds__(256) void init_kernel() {
    int i = blockIdx.x * blockDim.x + threadIdx.x;
    if (i < NN) { g_indeg[i] = 0; g_ctr[i] = 0; }
    if (i < NB * FD) g_pooled[i] = 0.f;
    if (i < NB) { g_denom[i] = 0.f; g_gmaxU[i] = 0x007FFFFFu; /* key(-inf) */ }
    if (i == 0) g_rowptr[NN] = NE;
}

__global__ __launch_bounds__(256) void deg_kernel(const int* __restrict__ dst) {
    int e = blockIdx.x * blockDim.x + threadIdx.x;
    if (e < NE) atomicAdd(&g_indeg[dst[e]], 1);
}

// phase A: per-block partial sums of indeg (+ fused dinv)
__global__ __launch_bounds__(512) void scanA_kernel() {
    int t = threadIdx.x, b = blockIdx.x;
    int idx = b * 512 + t;
    int v = (idx < NN) ? g_indeg[idx] : 0;
    if (idx < NN) g_dinv[idx] = rsqrtf((float)(v + 1));
    int x = v;
#pragma unroll
    for (int o = 16; o; o >>= 1) x += __shfl_xor_sync(0xffffffffu, x, o);
    __shared__ int wsum[16];
    int lane = t & 31, wid = t >> 5;
    if (lane == 0) wsum[wid] = x;
    __syncthreads();
    if (t == 0) {
        int s = 0;
#pragma unroll
        for (int w = 0; w < 16; w++) s += wsum[w];
        g_part[b] = s;
    }
}

// phase B: exclusive scan of NPB partials (single small block)
__global__ __launch_bounds__(256) void scanB_kernel() {
    int t = threadIdx.x;
    int v = (t < NPB) ? g_part[t] : 0;
    int lane = t & 31, wid = t >> 5;
    int x = v;
#pragma unroll
    for (int o = 1; o < 32; o <<= 1) {
        int y = __shfl_up_sync(0xffffffffu, x, o);
        if (lane >= o) x += y;
    }
    __shared__ int wsum[8];
    if (lane == 31) wsum[wid] = x;
    __syncthreads();
    if (wid == 0) {
        int s = (lane < 8) ? wsum[lane] : 0;
#pragma unroll
        for (int o = 1; o < 8; o <<= 1) {
            int y = __shfl_up_sync(0xffffffffu, s, o);
            if (lane >= o) s += y;
        }
        if (lane < 8) wsum[lane] = s;
    }
    __syncthreads();
    int excl = x - v + (wid > 0 ? wsum[wid - 1] : 0);
    if (t < NPB) g_partoff[t] = excl;
}

// phase C: per-block exclusive scan + offset -> rowptr
__global__ __launch_bounds__(512) void scanC_kernel() {
    int t = threadIdx.x, b = blockIdx.x;
    int idx = b * 512 + t;
    int v = (idx < NN) ? g_indeg[idx] : 0;
    int lane = t & 31, wid = t >> 5;
    int x = v;
#pragma unroll
    for (int o = 1; o < 32; o <<= 1) {
        int y = __shfl_up_sync(0xffffffffu, x, o);
        if (lane >= o) x += y;
    }
    __shared__ int wsum[16];
    if (lane == 31) wsum[wid] = x;
    __syncthreads();
    if (wid == 0) {
        int s = (lane < 16) ? wsum[lane] : 0;
#pragma unroll
        for (int o = 1; o < 16; o <<= 1) {
            int y = __shfl_up_sync(0xffffffffu, s, o);
            if (lane >= o) s += y;
        }
        if (lane < 16) wsum[lane] = s;
    }
    __syncthreads();
    int excl = x - v + (wid > 0 ? wsum[wid - 1] : 0);
    if (idx < NN) g_rowptr[idx] = g_partoff[b] + excl;
}

__global__ __launch_bounds__(256) void fill_kernel(const int* __restrict__ src,
                                                   const int* __restrict__ dst) {
    int e = blockIdx.x * blockDim.x + threadIdx.x;
    if (e < NE) {
        int d = dst[e];
        int p = g_rowptr[d] + atomicAdd(&g_ctr[d], 1);
        g_esrc[p] = src[e];
    }
}

// ---------------- GEMM: Y = X @ W (128x128), 8 rows per warp per iter ----------------
__global__ __launch_bounds__(256, 2) void gemm_kernel(const float* __restrict__ X,
                                                      const float* __restrict__ W,
                                                      float* __restrict__ Y) {
    extern __shared__ float4 sW[];  // sW[k*32+l] = W[k][4l..4l+3], 64KB
    int tid = threadIdx.x;
    const float4* W4 = (const float4*)W;
    for (int i = tid; i < FD * 32; i += 256) sW[i] = W4[i];
    __syncthreads();

    int warp = (blockIdx.x * 256 + tid) >> 5;
    int nwarps = (gridDim.x * 256) >> 5;
    int lane = tid & 31;
    const float4* X4 = (const float4*)X;
    float4* Y4 = (float4*)Y;

    for (int base = warp * 8; base < NN; base += nwarps * 8) {
        float4 xv[8];
#pragma unroll
        for (int r = 0; r < 8; r++) xv[r] = X4[(base + r) * 32 + lane];
        unsigned long long a0[8], a1[8];
#pragma unroll
        for (int r = 0; r < 8; r++) { a0[r] = pk2(0.f, 0.f); a1[r] = pk2(0.f, 0.f); }

#pragma unroll
        for (int kl = 0; kl < 32; kl++) {
            float4 w0 = sW[(kl * 4 + 0) * 32 + lane];
            float4 w1 = sW[(kl * 4 + 1) * 32 + lane];
            float4 w2 = sW[(kl * 4 + 2) * 32 + lane];
            float4 w3 = sW[(kl * 4 + 3) * 32 + lane];
            unsigned long long w0a = pk2(w0.x, w0.y), w0b = pk2(w0.z, w0.w);
            unsigned long long w1a = pk2(w1.x, w1.y), w1b = pk2(w1.z, w1.w);
            unsigned long long w2a = pk2(w2.x, w2.y), w2b = pk2(w2.z, w2.w);
            unsigned long long w3a = pk2(w3.x, w3.y), w3b = pk2(w3.z, w3.w);
#pragma unroll
            for (int r = 0; r < 8; r++) {
                float b0 = __shfl_sync(0xffffffffu, xv[r].x, kl);
                float b1 = __shfl_sync(0xffffffffu, xv[r].y, kl);
                float b2 = __shfl_sync(0xffffffffu, xv[r].z, kl);
                float b3 = __shfl_sync(0xffffffffu, xv[r].w, kl);
                unsigned long long bb0 = pk2(b0, b0), bb1 = pk2(b1, b1);
                unsigned long long bb2 = pk2(b2, b2), bb3 = pk2(b3, b3);
                fma2(a0[r], w0a, bb0); fma2(a1[r], w0b, bb0);
                fma2(a0[r], w1a, bb1); fma2(a1[r], w1b, bb1);
                fma2(a0[r], w2a, bb2); fma2(a1[r], w2b, bb2);
                fma2(a0[r], w3a, bb3); fma2(a1[r], w3b, bb3);
            }
        }
#pragma unroll
        for (int r = 0; r < 8; r++) {
            float4 o;
            upk2(a0[r], o.x, o.y);
            upk2(a1[r], o.z, o.w);
            Y4[(base + r) * 32 + lane] = o;
        }
    }
}

// ---------------- per-node CSR aggregation + bias + LN + ReLU ----------------
__global__ __launch_bounds__(256) void agg_ln_relu_kernel(const float* __restrict__ H,
                                                          float* __restrict__ Z,
                                                          const float* __restrict__ bias,
                                                          const float* __restrict__ gam,
                                                          const float* __restrict__ bet) {
    int gw = (blockIdx.x * blockDim.x + threadIdx.x) >> 5;
    if (gw >= NN) return;
    int lane = threadIdx.x & 31;
    int n = gw;
    int r0 = g_rowptr[n], r1 = g_rowptr[n + 1];
    float dn = g_dinv[n];
    const float4* H4 = (const float4*)H;

    float4 self = H4[n * 32 + lane];
    float4 acc;
    acc.x = dn * self.x; acc.y = dn * self.y; acc.z = dn * self.z; acc.w = dn * self.w;

    int i = r0;
    for (; i + 4 <= r1; i += 4) {
        int s0 = g_esrc[i], s1 = g_esrc[i + 1], s2 = g_esrc[i + 2], s3 = g_esrc[i + 3];
        float w0 = g_dinv[s0], w1 = g_dinv[s1], w2 = g_dinv[s2], w3 = g_dinv[s3];
        float4 h0 = H4[s0 * 32 + lane];
        float4 h1 = H4[s1 * 32 + lane];
        float4 h2 = H4[s2 * 32 + lane];
        float4 h3 = H4[s3 * 32 + lane];
        acc.x += w0 * h0.x + w1 * h1.x + w2 * h2.x + w3 * h3.x;
        acc.y += w0 * h0.y + w1 * h1.y + w2 * h2.y + w3 * h3.y;
        acc.z += w0 * h0.z + w1 * h1.z + w2 * h2.z + w3 * h3.z;
        acc.w += w0 * h0.w + w1 * h1.w + w2 * h2.w + w3 * h3.w;
    }
    for (; i < r1; i++) {
        int s = g_esrc[i];
        float w = g_dinv[s];
        float4 h = H4[s * 32 + lane];
        acc.x += w * h.x; acc.y += w * h.y; acc.z += w * h.z; acc.w += w * h.w;
    }

    const float4* b4p = (const float4*)bias;
    float4 b4 = b4p[lane];
    acc.x = acc.x * dn + b4.x;
    acc.y = acc.y * dn + b4.y;
    acc.z = acc.z * dn + b4.z;
    acc.w = acc.w * dn + b4.w;

    float s = acc.x + acc.y + acc.z + acc.w;
#pragma unroll
    for (int o = 16; o; o >>= 1) s += __shfl_xor_sync(0xffffffffu, s, o);
    float mean = s * (1.0f / FD);
    float dx = acc.x - mean, dy = acc.y - mean, dz = acc.z - mean, dw = acc.w - mean;
    float ss = dx * dx + dy * dy + dz * dz + dw * dw;
#pragma unroll
    for (int o = 16; o; o >>= 1) ss += __shfl_xor_sync(0xffffffffu, ss, o);
    float rstd = rsqrtf(ss * (1.0f / FD) + 1e-5f);

    const float4* g4p = (const float4*)gam;
    const float4* e4p = (const float4*)bet;
    float4 g4 = g4p[lane], e4 = e4p[lane];
    float4 out;
    out.x = fmaxf(dx * rstd * g4.x + e4.x, 0.f);
    out.y = fmaxf(dy * rstd * g4.y + e4.y, 0.f);
    out.z = fmaxf(dz * rstd * g4.z + e4.z, 0.f);
    out.w = fmaxf(dw * rstd * g4.w + e4.w, 0.f);
    ((float4*)Z)[n * 32 + lane] = out;
}

// ---------------- gate MLP (4 rows per warp per iter) ----------------
__global__ __launch_bounds__(256) void gate_kernel(const float* __restrict__ Z,
                                                   const float* __restrict__ Wg1,
                                                   const float* __restrict__ bg1,
                                                   const float* __restrict__ Wg2,
                                                   const float* __restrict__ bg2,
                                                   const int* __restrict__ batch) {
    __shared__ float sW1[FD * 64];
    __shared__ float sW2[64];
    __shared__ float sB1[64];
    int tid = threadIdx.x;
    for (int i = tid; i < FD * 64; i += 256) sW1[i] = Wg1[i];
    if (tid < 64) { sW2[tid] = Wg2[tid]; sB1[tid] = bg1[tid]; }
    __syncthreads();

    int warp = (blockIdx.x * 256 + tid) >> 5;
    int nwarps = (gridDim.x * 256) >> 5;
    int lane = tid & 31;
    int j0 = lane * 2;
    const float4* Z4 = (const float4*)Z;
    float bg2v = bg2[0];
    float s2a = sW2[j0], s2b = sW2[j0 + 1];
    float b1a = sB1[j0], b1b = sB1[j0 + 1];

    for (int base = warp * 4; base < NN; base += nwarps * 4) {
        float4 xv[4];
#pragma unroll
        for (int r = 0; r < 4; r++) xv[r] = Z4[(base + r) * 32 + lane];
        unsigned long long acc[4];
#pragma unroll
        for (int r = 0; r < 4; r++) acc[r] = pk2(0.f, 0.f);

#pragma unroll
        for (int kl = 0; kl < 32; kl++) {
            float2 w0 = *(const float2*)&sW1[(kl * 4 + 0) * 64 + j0];
            float2 w1 = *(const float2*)&sW1[(kl * 4 + 1) * 64 + j0];
            float2 w2 = *(const float2*)&sW1[(kl * 4 + 2) * 64 + j0];
            float2 w3 = *(const float2*)&sW1[(kl * 4 + 3) * 64 + j0];
            unsigned long long p0 = pk2(w0.x, w0.y), p1 = pk2(w1.x, w1.y);
            unsigned long long p2 = pk2(w2.x, w2.y), p3 = pk2(w3.x, w3.y);
#pragma unroll
            for (int r = 0; r < 4; r++) {
                float b0 = __shfl_sync(0xffffffffu, xv[r].x, kl);
                float b1 = __shfl_sync(0xffffffffu, xv[r].y, kl);
                float b2 = __shfl_sync(0xffffffffu, xv[r].z, kl);
                float b3 = __shfl_sync(0xffffffffu, xv[r].w, kl);
                fma2(acc[r], p0, pk2(b0, b0));
                fma2(acc[r], p1, pk2(b1, b1));
                fma2(acc[r], p2, pk2(b2, b2));
                fma2(acc[r], p3, pk2(b3, b3));
            }
        }
#pragma unroll
        for (int r = 0; r < 4; r++) {
            float h0, h1;
            upk2(acc[r], h0, h1);
            h0 = fmaxf(h0 + b1a, 0.f);
            h1 = fmaxf(h1 + b1b, 0.f);
            float part = h0 * s2a + h1 * s2b;
#pragma unroll
            for (int o = 16; o; o >>= 1) part += __shfl_xor_sync(0xffffffffu, part, o);
            if (lane == 0) {
                float gt = part + bg2v;
                g_gate[base + r] = gt;
                atomicMax(&g_gmaxU[batch[base + r]], fkey(gt));
            }
        }
    }
}

__global__ __launch_bounds__(256) void denom_kernel(const int* __restrict__ batch) {
    int n = blockIdx.x * blockDim.x + threadIdx.x;
    if (n < NN) {
        int b = batch[n];
        float m = fdekey(g_gmaxU[b]);
        atomicAdd(&g_denom[b], expf(g_gate[n] - m));
    }
}

__global__ __launch_bounds__(256) void pooled_kernel(const float* __restrict__ Z,
                                                     const int* __restrict__ batch) {
    const int C = 64;
    int warp = (blockIdx.x * blockDim.x + threadIdx.x) >> 5;
    int lane = threadIdx.x & 31;
    int n0 = warp * C;
    if (n0 >= NN) return;
    int nend = min(n0 + C, NN);
    const float4* Z4 = (const float4*)Z;

    float4 acc = make_float4(0.f, 0.f, 0.f, 0.f);
    int curb = -1;
    float m = 0.f, den = 1.f;
    for (int n = n0; n < nend; n++) {
        int b = batch[n];
        if (b != curb) {
            if (curb >= 0) {
                float* p = &g_pooled[curb * FD + lane * 4];
                atomicAdd(p + 0, acc.x); atomicAdd(p + 1, acc.y);
                atomicAdd(p + 2, acc.z); atomicAdd(p + 3, acc.w);
                acc = make_float4(0.f, 0.f, 0.f, 0.f);
            }
            curb = b;
            m = fdekey(g_gmaxU[b]);
            den = g_denom[b];
        }
        float alpha = expf(g_gate[n] - m) / den;
        float4 z = Z4[n * 32 + lane];
        acc.x += alpha * z.x; acc.y += alpha * z.y;
        acc.z += alpha * z.z; acc.w += alpha * z.w;
    }
    if (curb >= 0) {
        float* p = &g_pooled[curb * FD + lane * 4];
        atomicAdd(p + 0, acc.x); atomicAdd(p + 1, acc.y);
        atomicAdd(p + 2, acc.z); atomicAdd(p + 3, acc.w);
    }
}

__global__ __launch_bounds__(256) void cls_kernel(const float* __restrict__ Wc,
                                                  const float* __restrict__ bc,
                                                  float* __restrict__ out) {
    int t = blockIdx.x * blockDim.x + threadIdx.x;
    if (t < NB * NC) {
        int b = t >> 4, c = t & 15;
        float s = bc[c];
        const float* p = &g_pooled[b * FD];
#pragma unroll 16
        for (int j = 0; j < FD; j++) s += p[j] * Wc[j * NC + c];
        out[t] = s;
    }
}

// ---------------- launch ----------------
extern "C" void kernel_launch(void* const* d_in, const int* in_sizes, int n_in,
                              void* d_out, int out_size) {
    const float* x    = (const float*)d_in[0];
    const int*   ei   = (const int*)d_in[1];
    const int*   batch= (const int*)d_in[2];
    const float* W1   = (const float*)d_in[3];
    const float* b1   = (const float*)d_in[4];
    const float* g1   = (const float*)d_in[5];
    const float* be1  = (const float*)d_in[6];
    const float* W2   = (const float*)d_in[7];
    const float* b2   = (const float*)d_in[8];
    const float* g2   = (const float*)d_in[9];
    const float* be2  = (const float*)d_in[10];
    const float* Wg1  = (const float*)d_in[11];
    const float* bg1  = (const float*)d_in[12];
    const float* Wg2  = (const float*)d_in[13];
    const float* bg2  = (const float*)d_in[14];
    const float* Wc   = (const float*)d_in[15];
    const float* bc   = (const float*)d_in[16];
    float* out = (float*)d_out;

    const int* src = ei;
    const int* dst = ei + NE;

    static bool attr_done = false;
    if (!attr_done) {
        cudaFuncSetAttribute(gemm_kernel, cudaFuncAttributeMaxDynamicSharedMemorySize, 65536);
        attr_done = true;
    }

    float* bufA; cudaGetSymbolAddress((void**)&bufA, g_bufA);
    float* bufB; cudaGetSymbolAddress((void**)&bufB, g_bufB);

    init_kernel<<<(NN + 255) / 256, 256>>>();
    deg_kernel<<<(NE + 255) / 256, 256>>>(dst);
    scanA_kernel<<<NPB, 512>>>();
    scanB_kernel<<<1, 256>>>();
    scanC_kernel<<<NPB, 512>>>();
    fill_kernel<<<(NE + 255) / 256, 256>>>(src, dst);

    // layer 1
    gemm_kernel<<<296, 256, 65536>>>(x, W1, bufA);
    agg_ln_relu_kernel<<<(NN * 32 + 255) / 256, 256>>>(bufA, bufB, b1, g1, be1);
    // layer 2
    gemm_kernel<<<296, 256, 65536>>>(bufB, W2, bufA);
    agg_ln_relu_kernel<<<(NN * 32 + 255) / 256, 256>>>(bufA, bufB, b2, g2, be2);

    // attention pooling
    gate_kernel<<<592, 256>>>(bufB, Wg1, bg1, Wg2, bg2, batch);
    denom_kernel<<<(NN + 255) / 256, 256>>>(batch);
    pooled_kernel<<<(((NN + 63) / 64) * 32 + 255) / 256, 256>>>(bufB, batch);

    // classifier
    cls_kernel<<<(NB * NC + 255) / 256, 256>>>(Wc, bc, out);
}

// round 4
// speedup vs baseline: 1.9098x; 1.0327x over previous
#include <cuda_runtime.h>
#include <cuda_fp16.h>
#include <math.h>

#define NN 100000
#define NE 1600000
#define NB 64
#define FD 128
#define NC 16
#define NPB 196  // ceil(NN/512) scan blocks

// ---------------- scratch (device globals; no allocations) ----------------
__device__ __half   g_h16[NN * FD];   // fp16 intermediate h = X@W (gather target)
__device__ float    g_bufB[NN * FD];  // fp32 Z = relu(LN(agg))
__device__ float    g_dinv[NN];
__device__ int      g_indeg[NN];
__device__ int      g_ctr[NN];
__device__ int      g_rowptr[NN + 1];
__device__ int      g_part[NPB];
__device__ int      g_partoff[NPB];
__device__ int      g_esrc[NE];
__device__ float    g_gate[NN];
__device__ unsigned g_gmaxU[NB];
__device__ float    g_denom[NB];
__device__ float    g_pooled[NB * FD];

// ---------------- helpers ----------------
__device__ __forceinline__ unsigned long long pk2(float lo, float hi) {
    unsigned long long r;
    asm("mov.b64 %0, {%1,%2};" : "=l"(r) : "f"(lo), "f"(hi));
    return r;
}
__device__ __forceinline__ void upk2(unsigned long long v, float& lo, float& hi) {
    asm("mov.b64 {%0,%1}, %2;" : "=f"(lo), "=f"(hi) : "l"(v));
}
__device__ __forceinline__ void fma2(unsigned long long& acc, unsigned long long a,
                                     unsigned long long b) {
    asm("fma.rn.f32x2 %0, %1, %2, %0;" : "+l"(acc) : "l"(a), "l"(b));
}
__device__ __forceinline__ unsigned fkey(float f) {
    unsigned u = __float_as_uint(f);
    return (u & 0x80000000u) ? ~u : (u | 0x80000000u);
}
__device__ __forceinline__ float fdekey(unsigned k) {
    unsigned u = (k & 0x80000000u) ? (k ^ 0x80000000u) : ~k;
    return __uint_as_float(u);
}

// ---------------- setup kernels ----------------
__global__ __launch_bounds__(256) void init_kernel() {
    int i = blockIdx.x * blockDim.x + threadIdx.x;
    if (i < NN) { g_indeg[i] = 0; g_ctr[i] = 0; }
    if (i < NB * FD) g_pooled[i] = 0.f;
    if (i < NB) { g_denom[i] = 0.f; g_gmaxU[i] = 0x007FFFFFu; /* key(-inf) */ }
    if (i == 0) g_rowptr[NN] = NE;
}

__global__ __launch_bounds__(256) void deg_kernel(const int* __restrict__ dst) {
    int e = blockIdx.x * blockDim.x + threadIdx.x;
    if (e < NE) atomicAdd(&g_indeg[dst[e]], 1);
}

// phase A: per-block partial sums of indeg (+ fused dinv)
__global__ __launch_bounds__(512) void scanA_kernel() {
    int t = threadIdx.x, b = blockIdx.x;
    int idx = b * 512 + t;
    int v = (idx < NN) ? g_indeg[idx] : 0;
    if (idx < NN) g_dinv[idx] = rsqrtf((float)(v + 1));
    int x = v;
#pragma unroll
    for (int o = 16; o; o >>= 1) x += __shfl_xor_sync(0xffffffffu, x, o);
    __shared__ int wsum[16];
    int lane = t & 31, wid = t >> 5;
    if (lane == 0) wsum[wid] = x;
    __syncthreads();
    if (t == 0) {
        int s = 0;
#pragma unroll
        for (int w = 0; w < 16; w++) s += wsum[w];
        g_part[b] = s;
    }
}

// phase B: exclusive scan of NPB partials (single small block)
__global__ __launch_bounds__(256) void scanB_kernel() {
    int t = threadIdx.x;
    int v = (t < NPB) ? g_part[t] : 0;
    int lane = t & 31, wid = t >> 5;
    int x = v;
#pragma unroll
    for (int o = 1; o < 32; o <<= 1) {
        int y = __shfl_up_sync(0xffffffffu, x, o);
        if (lane >= o) x += y;
    }
    __shared__ int wsum[8];
    if (lane == 31) wsum[wid] = x;
    __syncthreads();
    if (wid == 0) {
        int s = (lane < 8) ? wsum[lane] : 0;
#pragma unroll
        for (int o = 1; o < 8; o <<= 1) {
            int y = __shfl_up_sync(0xffffffffu, s, o);
            if (lane >= o) s += y;
        }
        if (lane < 8) wsum[lane] = s;
    }
    __syncthreads();
    int excl = x - v + (wid > 0 ? wsum[wid - 1] : 0);
    if (t < NPB) g_partoff[t] = excl;
}

// phase C: per-block exclusive scan + offset -> rowptr
__global__ __launch_bounds__(512) void scanC_kernel() {
    int t = threadIdx.x, b = blockIdx.x;
    int idx = b * 512 + t;
    int v = (idx < NN) ? g_indeg[idx] : 0;
    int lane = t & 31, wid = t >> 5;
    int x = v;
#pragma unroll
    for (int o = 1; o < 32; o <<= 1) {
        int y = __shfl_up_sync(0xffffffffu, x, o);
        if (lane >= o) x += y;
    }
    __shared__ int wsum[16];
    if (lane == 31) wsum[wid] = x;
    __syncthreads();
    if (wid == 0) {
        int s = (lane < 16) ? wsum[lane] : 0;
#pragma unroll
        for (int o = 1; o < 16; o <<= 1) {
            int y = __shfl_up_sync(0xffffffffu, s, o);
            if (lane >= o) s += y;
        }
        if (lane < 16) wsum[lane] = s;
    }
    __syncthreads();
    int excl = x - v + (wid > 0 ? wsum[wid - 1] : 0);
    if (idx < NN) g_rowptr[idx] = g_partoff[b] + excl;
}

__global__ __launch_bounds__(256) void fill_kernel(const int* __restrict__ src,
                                                   const int* __restrict__ dst) {
    int e = blockIdx.x * blockDim.x + threadIdx.x;
    if (e < NE) {
        int d = dst[e];
        int p = g_rowptr[d] + atomicAdd(&g_ctr[d], 1);
        g_esrc[p] = src[e];
    }
}

// ---------------- GEMM: H16 = X @ W (128x128), 8 rows per warp, fp16 output ----------------
__global__ __launch_bounds__(256, 2) void gemm_kernel(const float* __restrict__ X,
                                                      const float* __restrict__ W,
                                                      __half* __restrict__ Y) {
    extern __shared__ float4 sW[];  // sW[k*32+l] = W[k][4l..4l+3], 64KB
    int tid = threadIdx.x;
    const float4* W4 = (const float4*)W;
    for (int i = tid; i < FD * 32; i += 256) sW[i] = W4[i];
    __syncthreads();

    int warp = (blockIdx.x * 256 + tid) >> 5;
    int nwarps = (gridDim.x * 256) >> 5;
    int lane = tid & 31;
    const float4* X4 = (const float4*)X;
    uint2* Y2 = (uint2*)Y;

    for (int base = warp * 8; base < NN; base += nwarps * 8) {
        float4 xv[8];
#pragma unroll
        for (int r = 0; r < 8; r++) xv[r] = X4[(base + r) * 32 + lane];
        unsigned long long a0[8], a1[8];
#pragma unroll
        for (int r = 0; r < 8; r++) { a0[r] = pk2(0.f, 0.f); a1[r] = pk2(0.f, 0.f); }

#pragma unroll
        for (int kl = 0; kl < 32; kl++) {
            float4 w0 = sW[(kl * 4 + 0) * 32 + lane];
            float4 w1 = sW[(kl * 4 + 1) * 32 + lane];
            float4 w2 = sW[(kl * 4 + 2) * 32 + lane];
            float4 w3 = sW[(kl * 4 + 3) * 32 + lane];
            unsigned long long w0a = pk2(w0.x, w0.y), w0b = pk2(w0.z, w0.w);
            unsigned long long w1a = pk2(w1.x, w1.y), w1b = pk2(w1.z, w1.w);
            unsigned long long w2a = pk2(w2.x, w2.y), w2b = pk2(w2.z, w2.w);
            unsigned long long w3a = pk2(w3.x, w3.y), w3b = pk2(w3.z, w3.w);
#pragma unroll
            for (int r = 0; r < 8; r++) {
                float b0 = __shfl_sync(0xffffffffu, xv[r].x, kl);
                float b1 = __shfl_sync(0xffffffffu, xv[r].y, kl);
                float b2 = __shfl_sync(0xffffffffu, xv[r].z, kl);
                float b3 = __shfl_sync(0xffffffffu, xv[r].w, kl);
                unsigned long long bb0 = pk2(b0, b0), bb1 = pk2(b1, b1);
                unsigned long long bb2 = pk2(b2, b2), bb3 = pk2(b3, b3);
                fma2(a0[r], w0a, bb0); fma2(a1[r], w0b, bb0);
                fma2(a0[r], w1a, bb1); fma2(a1[r], w1b, bb1);
                fma2(a0[r], w2a, bb2); fma2(a1[r], w2b, bb2);
                fma2(a0[r], w3a, bb3); fma2(a1[r], w3b, bb3);
            }
        }
#pragma unroll
        for (int r = 0; r < 8; r++) {
            float ox, oy, oz, ow;
            upk2(a0[r], ox, oy);
            upk2(a1[r], oz, ow);
            __half2 p0 = __floats2half2_rn(ox, oy);
            __half2 p1 = __floats2half2_rn(oz, ow);
            uint2 st;
            st.x = *(unsigned*)&p0;
            st.y = *(unsigned*)&p1;
            Y2[(base + r) * 32 + lane] = st;
        }
    }
}

// ---------------- per-node CSR aggregation (fp16 gathers) + bias + LN + ReLU ----------------
__global__ __launch_bounds__(256) void agg_ln_relu_kernel(const __half* __restrict__ H,
                                                          float* __restrict__ Z,
                                                          const float* __restrict__ bias,
                                                          const float* __restrict__ gam,
                                                          const float* __restrict__ bet) {
    int gw = (blockIdx.x * blockDim.x + threadIdx.x) >> 5;
    if (gw >= NN) return;
    int lane = threadIdx.x & 31;
    int n = gw;
    int r0 = g_rowptr[n], r1 = g_rowptr[n + 1];
    float dn = g_dinv[n];
    const uint2* H2 = (const uint2*)H;

    uint2 sv = H2[n * 32 + lane];
    float2 sf0 = __half22float2(*(__half2*)&sv.x);
    float2 sf1 = __half22float2(*(__half2*)&sv.y);
    float4 acc;
    acc.x = dn * sf0.x; acc.y = dn * sf0.y; acc.z = dn * sf1.x; acc.w = dn * sf1.y;

    int i = r0;
    for (; i + 4 <= r1; i += 4) {
        int s0 = g_esrc[i], s1 = g_esrc[i + 1], s2 = g_esrc[i + 2], s3 = g_esrc[i + 3];
        float w0 = g_dinv[s0], w1 = g_dinv[s1], w2 = g_dinv[s2], w3 = g_dinv[s3];
        uint2 v0 = H2[s0 * 32 + lane];
        uint2 v1 = H2[s1 * 32 + lane];
        uint2 v2 = H2[s2 * 32 + lane];
        uint2 v3 = H2[s3 * 32 + lane];
        float2 f0a = __half22float2(*(__half2*)&v0.x), f0b = __half22float2(*(__half2*)&v0.y);
        float2 f1a = __half22float2(*(__half2*)&v1.x), f1b = __half22float2(*(__half2*)&v1.y);
        float2 f2a = __half22float2(*(__half2*)&v2.x), f2b = __half22float2(*(__half2*)&v2.y);
        float2 f3a = __half22float2(*(__half2*)&v3.x), f3b = __half22float2(*(__half2*)&v3.y);
        acc.x += w0 * f0a.x + w1 * f1a.x + w2 * f2a.x + w3 * f3a.x;
        acc.y += w0 * f0a.y + w1 * f1a.y + w2 * f2a.y + w3 * f3a.y;
        acc.z += w0 * f0b.x + w1 * f1b.x + w2 * f2b.x + w3 * f3b.x;
        acc.w += w0 * f0b.y + w1 * f1b.y + w2 * f2b.y + w3 * f3b.y;
    }
    for (; i < r1; i++) {
        int s = g_esrc[i];
        float w = g_dinv[s];
        uint2 v = H2[s * 32 + lane];
        float2 fa = __half22float2(*(__half2*)&v.x), fb = __half22float2(*(__half2*)&v.y);
        acc.x += w * fa.x; acc.y += w * fa.y; acc.z += w * fb.x; acc.w += w * fb.y;
    }

    const float4* b4p = (const float4*)bias;
    float4 b4 = b4p[lane];
    acc.x = acc.x * dn + b4.x;
    acc.y = acc.y * dn + b4.y;
    acc.z = acc.z * dn + b4.z;
    acc.w = acc.w * dn + b4.w;

    float s = acc.x + acc.y + acc.z + acc.w;
#pragma unroll
    for (int o = 16; o; o >>= 1) s += __shfl_xor_sync(0xffffffffu, s, o);
    float mean = s * (1.0f / FD);
    float dx = acc.x - mean, dy = acc.y - mean, dz = acc.z - mean, dw = acc.w - mean;
    float ss = dx * dx + dy * dy + dz * dz + dw * dw;
#pragma unroll
    for (int o = 16; o; o >>= 1) ss += __shfl_xor_sync(0xffffffffu, ss, o);
    float rstd = rsqrtf(ss * (1.0f / FD) + 1e-5f);

    const float4* g4p = (const float4*)gam;
    const float4* e4p = (const float4*)bet;
    float4 g4 = g4p[lane], e4 = e4p[lane];
    float4 out;
    out.x = fmaxf(dx * rstd * g4.x + e4.x, 0.f);
    out.y = fmaxf(dy * rstd * g4.y + e4.y, 0.f);
    out.z = fmaxf(dz * rstd * g4.z + e4.z, 0.f);
    out.w = fmaxf(dw * rstd * g4.w + e4.w, 0.f);
    ((float4*)Z)[n * 32 + lane] = out;
}

// ---------------- gate MLP (4 rows per warp per iter) ----------------
__global__ __launch_bounds__(256) void gate_kernel(const float* __restrict__ Z,
                                                   const float* __restrict__ Wg1,
                                                   const float* __restrict__ bg1,
                                                   const float* __restrict__ Wg2,
                                                   const float* __restrict__ bg2,
                                                   const int* __restrict__ batch) {
    __shared__ float sW1[FD * 64];
    __shared__ float sW2[64];
    __shared__ float sB1[64];
    int tid = threadIdx.x;
    for (int i = tid; i < FD * 64; i += 256) sW1[i] = Wg1[i];
    if (tid < 64) { sW2[tid] = Wg2[tid]; sB1[tid] = bg1[tid]; }
    __syncthreads();

    int warp = (blockIdx.x * 256 + tid) >> 5;
    int nwarps = (gridDim.x * 256) >> 5;
    int lane = tid & 31;
    int j0 = lane * 2;
    const float4* Z4 = (const float4*)Z;
    float bg2v = bg2[0];
    float s2a = sW2[j0], s2b = sW2[j0 + 1];
    float b1a = sB1[j0], b1b = sB1[j0 + 1];

    for (int base = warp * 4; base < NN; base += nwarps * 4) {
        float4 xv[4];
#pragma unroll
        for (int r = 0; r < 4; r++) xv[r] = Z4[(base + r) * 32 + lane];
        unsigned long long acc[4];
#pragma unroll
        for (int r = 0; r < 4; r++) acc[r] = pk2(0.f, 0.f);

#pragma unroll
        for (int kl = 0; kl < 32; kl++) {
            float2 w0 = *(const float2*)&sW1[(kl * 4 + 0) * 64 + j0];
            float2 w1 = *(const float2*)&sW1[(kl * 4 + 1) * 64 + j0];
            float2 w2 = *(const float2*)&sW1[(kl * 4 + 2) * 64 + j0];
            float2 w3 = *(const float2*)&sW1[(kl * 4 + 3) * 64 + j0];
            unsigned long long p0 = pk2(w0.x, w0.y), p1 = pk2(w1.x, w1.y);
            unsigned long long p2 = pk2(w2.x, w2.y), p3 = pk2(w3.x, w3.y);
#pragma unroll
            for (int r = 0; r < 4; r++) {
                float b0 = __shfl_sync(0xffffffffu, xv[r].x, kl);
                float b1 = __shfl_sync(0xffffffffu, xv[r].y, kl);
                float b2 = __shfl_sync(0xffffffffu, xv[r].z, kl);
                float b3 = __shfl_sync(0xffffffffu, xv[r].w, kl);
                fma2(acc[r], p0, pk2(b0, b0));
                fma2(acc[r], p1, pk2(b1, b1));
                fma2(acc[r], p2, pk2(b2, b2));
                fma2(acc[r], p3, pk2(b3, b3));
            }
        }
#pragma unroll
        for (int r = 0; r < 4; r++) {
            float h0, h1;
            upk2(acc[r], h0, h1);
            h0 = fmaxf(h0 + b1a, 0.f);
            h1 = fmaxf(h1 + b1b, 0.f);
            float part = h0 * s2a + h1 * s2b;
#pragma unroll
            for (int o = 16; o; o >>= 1) part += __shfl_xor_sync(0xffffffffu, part, o);
            if (lane == 0) {
                float gt = part + bg2v;
                g_gate[base + r] = gt;
                atomicMax(&g_gmaxU[batch[base + r]], fkey(gt));
            }
        }
    }
}

__global__ __launch_bounds__(256) void denom_kernel(const int* __restrict__ batch) {
    int n = blockIdx.x * blockDim.x + threadIdx.x;
    if (n < NN) {
        int b = batch[n];
        float m = fdekey(g_gmaxU[b]);
        atomicAdd(&g_denom[b], expf(g_gate[n] - m));
    }
}

__global__ __launch_bounds__(256) void pooled_kernel(const float* __restrict__ Z,
                                                     const int* __restrict__ batch) {
    const int C = 64;
    int warp = (blockIdx.x * blockDim.x + threadIdx.x) >> 5;
    int lane = threadIdx.x & 31;
    int n0 = warp * C;
    if (n0 >= NN) return;
    int nend = min(n0 + C, NN);
    const float4* Z4 = (const float4*)Z;

    float4 acc = make_float4(0.f, 0.f, 0.f, 0.f);
    int curb = -1;
    float m = 0.f, den = 1.f;
    for (int n = n0; n < nend; n++) {
        int b = batch[n];
        if (b != curb) {
            if (curb >= 0) {
                float* p = &g_pooled[curb * FD + lane * 4];
                atomicAdd(p + 0, acc.x); atomicAdd(p + 1, acc.y);
                atomicAdd(p + 2, acc.z); atomicAdd(p + 3, acc.w);
                acc = make_float4(0.f, 0.f, 0.f, 0.f);
            }
            curb = b;
            m = fdekey(g_gmaxU[b]);
            den = g_denom[b];
        }
        float alpha = expf(g_gate[n] - m) / den;
        float4 z = Z4[n * 32 + lane];
        acc.x += alpha * z.x; acc.y += alpha * z.y;
        acc.z += alpha * z.z; acc.w += alpha * z.w;
    }
    if (curb >= 0) {
        float* p = &g_pooled[curb * FD + lane * 4];
        atomicAdd(p + 0, acc.x); atomicAdd(p + 1, acc.y);
        atomicAdd(p + 2, acc.z); atomicAdd(p + 3, acc.w);
    }
}

__global__ __launch_bounds__(256) void cls_kernel(const float* __restrict__ Wc,
                                                  const float* __restrict__ bc,
                                                  float* __restrict__ out) {
    int t = blockIdx.x * blockDim.x + threadIdx.x;
    if (t < NB * NC) {
        int b = t >> 4, c = t & 15;
        float s = bc[c];
        const float* p = &g_pooled[b * FD];
#pragma unroll 16
        for (int j = 0; j < FD; j++) s += p[j] * Wc[j * NC + c];
        out[t] = s;
    }
}

// ---------------- launch ----------------
extern "C" void kernel_launch(void* const* d_in, const int* in_sizes, int n_in,
                              void* d_out, int out_size) {
    const float* x    = (const float*)d_in[0];
    const int*   ei   = (const int*)d_in[1];
    const int*   batch= (const int*)d_in[2];
    const float* W1   = (const float*)d_in[3];
    const float* b1   = (const float*)d_in[4];
    const float* g1   = (const float*)d_in[5];
    const float* be1  = (const float*)d_in[6];
    const float* W2   = (const float*)d_in[7];
    const float* b2   = (const float*)d_in[8];
    const float* g2   = (const float*)d_in[9];
    const float* be2  = (const float*)d_in[10];
    const float* Wg1  = (const float*)d_in[11];
    const float* bg1  = (const float*)d_in[12];
    const float* Wg2  = (const float*)d_in[13];
    const float* bg2  = (const float*)d_in[14];
    const float* Wc   = (const float*)d_in[15];
    const float* bc   = (const float*)d_in[16];
    float* out = (float*)d_out;

    const int* src = ei;
    const int* dst = ei + NE;

    static bool attr_done = false;
    if (!attr_done) {
        cudaFuncSetAttribute(gemm_kernel, cudaFuncAttributeMaxDynamicSharedMemorySize, 65536);
        attr_done = true;
    }

    __half* h16; cudaGetSymbolAddress((void**)&h16, g_h16);
    float* bufB; cudaGetSymbolAddress((void**)&bufB, g_bufB);

    init_kernel<<<(NN + 255) / 256, 256>>>();
    deg_kernel<<<(NE + 255) / 256, 256>>>(dst);
    scanA_kernel<<<NPB, 512>>>();
    scanB_kernel<<<1, 256>>>();
    scanC_kernel<<<NPB, 512>>>();
    fill_kernel<<<(NE + 255) / 256, 256>>>(src, dst);

    // layer 1
    gemm_kernel<<<296, 256, 65536>>>(x, W1, h16);
    agg_ln_relu_kernel<<<(NN * 32 + 255) / 256, 256>>>(h16, bufB, b1, g1, be1);
    // layer 2
    gemm_kernel<<<296, 256, 65536>>>(bufB, W2, h16);
    agg_ln_relu_kernel<<<(NN * 32 + 255) / 256, 256>>>(h16, bufB, b2, g2, be2);

    // attention pooling
    gate_kernel<<<592, 256>>>(bufB, Wg1, bg1, Wg2, bg2, batch);
    denom_kernel<<<(NN + 255) / 256, 256>>>(batch);
    pooled_kernel<<<(((NN + 63) / 64) * 32 + 255) / 256, 256>>>(bufB, batch);

    // classifier
    cls_kernel<<<(NB * NC + 255) / 256, 256>>>(Wc, bc, out);
}

// round 5
// speedup vs baseline: 1.9754x; 1.0343x over previous
#include <cuda_runtime.h>
#include <cuda_fp16.h>
#include <math.h>

#define NN 100000
#define NE 1600000
#define NB 64
#define FD 128
#define NC 16
#define NPB 196  // ceil(NN/512) scan blocks

// ---------------- scratch (device globals; no allocations) ----------------
__device__ __half   g_h16[NN * FD];   // fp16 intermediate h = X@W (gather target)
__device__ float    g_bufB[NN * FD];  // fp32 Z = relu(LN(agg))
__device__ float    g_dinv[NN];
__device__ int      g_indeg[NN];
__device__ int      g_ctr[NN];
__device__ int      g_rowptr[NN + 1];
__device__ int      g_part[NPB];
__device__ int      g_partoff[NPB];
__device__ int      g_esrc[NE];
__device__ float    g_gate[NN];
__device__ unsigned g_gmaxU[NB];
__device__ float    g_denom[NB];
__device__ float    g_pooled[NB * FD];

// ---------------- helpers ----------------
__device__ __forceinline__ unsigned long long pk2(float lo, float hi) {
    unsigned long long r;
    asm("mov.b64 %0, {%1,%2};" : "=l"(r) : "f"(lo), "f"(hi));
    return r;
}
__device__ __forceinline__ void upk2(unsigned long long v, float& lo, float& hi) {
    asm("mov.b64 {%0,%1}, %2;" : "=f"(lo), "=f"(hi) : "l"(v));
}
__device__ __forceinline__ void fma2(unsigned long long& acc, unsigned long long a,
                                     unsigned long long b) {
    asm("fma.rn.f32x2 %0, %1, %2, %0;" : "+l"(acc) : "l"(a), "l"(b));
}
__device__ __forceinline__ unsigned fkey(float f) {
    unsigned u = __float_as_uint(f);
    return (u & 0x80000000u) ? ~u : (u | 0x80000000u);
}
__device__ __forceinline__ float fdekey(unsigned k) {
    unsigned u = (k & 0x80000000u) ? (k ^ 0x80000000u) : ~k;
    return __uint_as_float(u);
}

// ---------------- setup kernels ----------------
__global__ __launch_bounds__(256) void init_kernel() {
    int i = blockIdx.x * blockDim.x + threadIdx.x;
    if (i < NN) { g_indeg[i] = 0; g_ctr[i] = 0; }
    if (i < NB * FD) g_pooled[i] = 0.f;
    if (i < NB) { g_denom[i] = 0.f; g_gmaxU[i] = 0x007FFFFFu; /* key(-inf) */ }
    if (i == 0) g_rowptr[NN] = NE;
}

__global__ __launch_bounds__(256) void deg_kernel(const int* __restrict__ dst) {
    int e = blockIdx.x * blockDim.x + threadIdx.x;
    if (e < NE) atomicAdd(&g_indeg[dst[e]], 1);
}

// phase A: per-block partial sums of indeg (+ fused dinv)
__global__ __launch_bounds__(512) void scanA_kernel() {
    int t = threadIdx.x, b = blockIdx.x;
    int idx = b * 512 + t;
    int v = (idx < NN) ? g_indeg[idx] : 0;
    if (idx < NN) g_dinv[idx] = rsqrtf((float)(v + 1));
    int x = v;
#pragma unroll
    for (int o = 16; o; o >>= 1) x += __shfl_xor_sync(0xffffffffu, x, o);
    __shared__ int wsum[16];
    int lane = t & 31, wid = t >> 5;
    if (lane == 0) wsum[wid] = x;
    __syncthreads();
    if (t == 0) {
        int s = 0;
#pragma unroll
        for (int w = 0; w < 16; w++) s += wsum[w];
        g_part[b] = s;
    }
}

// phase B: exclusive scan of NPB partials (single small block)
__global__ __launch_bounds__(256) void scanB_kernel() {
    int t = threadIdx.x;
    int v = (t < NPB) ? g_part[t] : 0;
    int lane = t & 31, wid = t >> 5;
    int x = v;
#pragma unroll
    for (int o = 1; o < 32; o <<= 1) {
        int y = __shfl_up_sync(0xffffffffu, x, o);
        if (lane >= o) x += y;
    }
    __shared__ int wsum[8];
    if (lane == 31) wsum[wid] = x;
    __syncthreads();
    if (wid == 0) {
        int s = (lane < 8) ? wsum[lane] : 0;
#pragma unroll
        for (int o = 1; o < 8; o <<= 1) {
            int y = __shfl_up_sync(0xffffffffu, s, o);
            if (lane >= o) s += y;
        }
        if (lane < 8) wsum[lane] = s;
    }
    __syncthreads();
    int excl = x - v + (wid > 0 ? wsum[wid - 1] : 0);
    if (t < NPB) g_partoff[t] = excl;
}

// phase C: per-block exclusive scan + offset -> rowptr
__global__ __launch_bounds__(512) void scanC_kernel() {
    int t = threadIdx.x, b = blockIdx.x;
    int idx = b * 512 + t;
    int v = (idx < NN) ? g_indeg[idx] : 0;
    int lane = t & 31, wid = t >> 5;
    int x = v;
#pragma unroll
    for (int o = 1; o < 32; o <<= 1) {
        int y = __shfl_up_sync(0xffffffffu, x, o);
        if (lane >= o) x += y;
    }
    __shared__ int wsum[16];
    if (lane == 31) wsum[wid] = x;
    __syncthreads();
    if (wid == 0) {
        int s = (lane < 16) ? wsum[lane] : 0;
#pragma unroll
        for (int o = 1; o < 16; o <<= 1) {
            int y = __shfl_up_sync(0xffffffffu, s, o);
            if (lane >= o) s += y;
        }
        if (lane < 16) wsum[lane] = s;
    }
    __syncthreads();
    int excl = x - v + (wid > 0 ? wsum[wid - 1] : 0);
    if (idx < NN) g_rowptr[idx] = g_partoff[b] + excl;
}

__global__ __launch_bounds__(256) void fill_kernel(const int* __restrict__ src,
                                                   const int* __restrict__ dst) {
    int e = blockIdx.x * blockDim.x + threadIdx.x;
    if (e < NE) {
        int d = dst[e];
        int p = g_rowptr[d] + atomicAdd(&g_ctr[d], 1);
        g_esrc[p] = src[e];
    }
}

// ---------------- GEMM: H16 = X @ W (128x128), 8 rows per warp, fp16 output ----------------
__global__ __launch_bounds__(256, 2) void gemm_kernel(const float* __restrict__ X,
                                                      const float* __restrict__ W,
                                                      __half* __restrict__ Y) {
    extern __shared__ float4 sW[];  // sW[k*32+l] = W[k][4l..4l+3], 64KB
    int tid = threadIdx.x;
    const float4* W4 = (const float4*)W;
    for (int i = tid; i < FD * 32; i += 256) sW[i] = W4[i];
    __syncthreads();

    int warp = (blockIdx.x * 256 + tid) >> 5;
    int nwarps = (gridDim.x * 256) >> 5;
    int lane = tid & 31;
    const float4* X4 = (const float4*)X;
    uint2* Y2 = (uint2*)Y;

    for (int base = warp * 8; base < NN; base += nwarps * 8) {
        float4 xv[8];
#pragma unroll
        for (int r = 0; r < 8; r++) xv[r] = X4[(base + r) * 32 + lane];
        unsigned long long a0[8], a1[8];
#pragma unroll
        for (int r = 0; r < 8; r++) { a0[r] = pk2(0.f, 0.f); a1[r] = pk2(0.f, 0.f); }

#pragma unroll
        for (int kl = 0; kl < 32; kl++) {
            float4 w0 = sW[(kl * 4 + 0) * 32 + lane];
            float4 w1 = sW[(kl * 4 + 1) * 32 + lane];
            float4 w2 = sW[(kl * 4 + 2) * 32 + lane];
            float4 w3 = sW[(kl * 4 + 3) * 32 + lane];
            unsigned long long w0a = pk2(w0.x, w0.y), w0b = pk2(w0.z, w0.w);
            unsigned long long w1a = pk2(w1.x, w1.y), w1b = pk2(w1.z, w1.w);
            unsigned long long w2a = pk2(w2.x, w2.y), w2b = pk2(w2.z, w2.w);
            unsigned long long w3a = pk2(w3.x, w3.y), w3b = pk2(w3.z, w3.w);
#pragma unroll
            for (int r = 0; r < 8; r++) {
                float b0 = __shfl_sync(0xffffffffu, xv[r].x, kl);
                float b1 = __shfl_sync(0xffffffffu, xv[r].y, kl);
                float b2 = __shfl_sync(0xffffffffu, xv[r].z, kl);
                float b3 = __shfl_sync(0xffffffffu, xv[r].w, kl);
                unsigned long long bb0 = pk2(b0, b0), bb1 = pk2(b1, b1);
                unsigned long long bb2 = pk2(b2, b2), bb3 = pk2(b3, b3);
                fma2(a0[r], w0a, bb0); fma2(a1[r], w0b, bb0);
                fma2(a0[r], w1a, bb1); fma2(a1[r], w1b, bb1);
                fma2(a0[r], w2a, bb2); fma2(a1[r], w2b, bb2);
                fma2(a0[r], w3a, bb3); fma2(a1[r], w3b, bb3);
            }
        }
#pragma unroll
        for (int r = 0; r < 8; r++) {
            float ox, oy, oz, ow;
            upk2(a0[r], ox, oy);
            upk2(a1[r], oz, ow);
            __half2 p0 = __floats2half2_rn(ox, oy);
            __half2 p1 = __floats2half2_rn(oz, ow);
            uint2 st;
            st.x = *(unsigned*)&p0;
            st.y = *(unsigned*)&p1;
            Y2[(base + r) * 32 + lane] = st;
        }
    }
}

// ---------------- per-node CSR aggregation (fp16 gathers) + bias + LN + ReLU ----------------
__global__ __launch_bounds__(256) void agg_ln_relu_kernel(const __half* __restrict__ H,
                                                          float* __restrict__ Z,
                                                          const float* __restrict__ bias,
                                                          const float* __restrict__ gam,
                                                          const float* __restrict__ bet) {
    int gw = (blockIdx.x * blockDim.x + threadIdx.x) >> 5;
    if (gw >= NN) return;
    int lane = threadIdx.x & 31;
    int n = gw;
    int r0 = g_rowptr[n], r1 = g_rowptr[n + 1];
    float dn = g_dinv[n];
    const uint2* H2 = (const uint2*)H;

    uint2 sv = H2[n * 32 + lane];
    float2 sf0 = __half22float2(*(__half2*)&sv.x);
    float2 sf1 = __half22float2(*(__half2*)&sv.y);
    float4 acc;
    acc.x = dn * sf0.x; acc.y = dn * sf0.y; acc.z = dn * sf1.x; acc.w = dn * sf1.y;

    int i = r0;
    for (; i + 4 <= r1; i += 4) {
        int s0 = g_esrc[i], s1 = g_esrc[i + 1], s2 = g_esrc[i + 2], s3 = g_esrc[i + 3];
        float w0 = g_dinv[s0], w1 = g_dinv[s1], w2 = g_dinv[s2], w3 = g_dinv[s3];
        uint2 v0 = H2[s0 * 32 + lane];
        uint2 v1 = H2[s1 * 32 + lane];
        uint2 v2 = H2[s2 * 32 + lane];
        uint2 v3 = H2[s3 * 32 + lane];
        float2 f0a = __half22float2(*(__half2*)&v0.x), f0b = __half22float2(*(__half2*)&v0.y);
        float2 f1a = __half22float2(*(__half2*)&v1.x), f1b = __half22float2(*(__half2*)&v1.y);
        float2 f2a = __half22float2(*(__half2*)&v2.x), f2b = __half22float2(*(__half2*)&v2.y);
        float2 f3a = __half22float2(*(__half2*)&v3.x), f3b = __half22float2(*(__half2*)&v3.y);
        acc.x += w0 * f0a.x + w1 * f1a.x + w2 * f2a.x + w3 * f3a.x;
        acc.y += w0 * f0a.y + w1 * f1a.y + w2 * f2a.y + w3 * f3a.y;
        acc.z += w0 * f0b.x + w1 * f1b.x + w2 * f2b.x + w3 * f3b.x;
        acc.w += w0 * f0b.y + w1 * f1b.y + w2 * f2b.y + w3 * f3b.y;
    }
    for (; i < r1; i++) {
        int s = g_esrc[i];
        float w = g_dinv[s];
        uint2 v = H2[s * 32 + lane];
        float2 fa = __half22float2(*(__half2*)&v.x), fb = __half22float2(*(__half2*)&v.y);
        acc.x += w * fa.x; acc.y += w * fa.y; acc.z += w * fb.x; acc.w += w * fb.y;
    }

    const float4* b4p = (const float4*)bias;
    float4 b4 = b4p[lane];
    acc.x = acc.x * dn + b4.x;
    acc.y = acc.y * dn + b4.y;
    acc.z = acc.z * dn + b4.z;
    acc.w = acc.w * dn + b4.w;

    float s = acc.x + acc.y + acc.z + acc.w;
#pragma unroll
    for (int o = 16; o; o >>= 1) s += __shfl_xor_sync(0xffffffffu, s, o);
    float mean = s * (1.0f / FD);
    float dx = acc.x - mean, dy = acc.y - mean, dz = acc.z - mean, dw = acc.w - mean;
    float ss = dx * dx + dy * dy + dz * dz + dw * dw;
#pragma unroll
    for (int o = 16; o; o >>= 1) ss += __shfl_xor_sync(0xffffffffu, ss, o);
    float rstd = rsqrtf(ss * (1.0f / FD) + 1e-5f);

    const float4* g4p = (const float4*)gam;
    const float4* e4p = (const float4*)bet;
    float4 g4 = g4p[lane], e4 = e4p[lane];
    float4 out;
    out.x = fmaxf(dx * rstd * g4.x + e4.x, 0.f);
    out.y = fmaxf(dy * rstd * g4.y + e4.y, 0.f);
    out.z = fmaxf(dz * rstd * g4.z + e4.z, 0.f);
    out.w = fmaxf(dw * rstd * g4.w + e4.w, 0.f);
    ((float4*)Z)[n * 32 + lane] = out;
}

// ---------------- gate MLP (4 rows per warp per iter) ----------------
__global__ __launch_bounds__(256) void gate_kernel(const float* __restrict__ Z,
                                                   const float* __restrict__ Wg1,
                                                   const float* __restrict__ bg1,
                                                   const float* __restrict__ Wg2,
                                                   const float* __restrict__ bg2,
                                                   const int* __restrict__ batch) {
    __shared__ float sW1[FD * 64];
    __shared__ float sW2[64];
    __shared__ float sB1[64];
    int tid = threadIdx.x;
    for (int i = tid; i < FD * 64; i += 256) sW1[i] = Wg1[i];
    if (tid < 64) { sW2[tid] = Wg2[tid]; sB1[tid] = bg1[tid]; }
    __syncthreads();

    int warp = (blockIdx.x * 256 + tid) >> 5;
    int nwarps = (gridDim.x * 256) >> 5;
    int lane = tid & 31;
    int j0 = lane * 2;
    const float4* Z4 = (const float4*)Z;
    float bg2v = bg2[0];
    float s2a = sW2[j0], s2b = sW2[j0 + 1];
    float b1a = sB1[j0], b1b = sB1[j0 + 1];

    for (int base = warp * 4; base < NN; base += nwarps * 4) {
        float4 xv[4];
#pragma unroll
        for (int r = 0; r < 4; r++) xv[r] = Z4[(base + r) * 32 + lane];
        unsigned long long acc[4];
#pragma unroll
        for (int r = 0; r < 4; r++) acc[r] = pk2(0.f, 0.f);

#pragma unroll
        for (int kl = 0; kl < 32; kl++) {
            float2 w0 = *(const float2*)&sW1[(kl * 4 + 0) * 64 + j0];
            float2 w1 = *(const float2*)&sW1[(kl * 4 + 1) * 64 + j0];
            float2 w2 = *(const float2*)&sW1[(kl * 4 + 2) * 64 + j0];
            float2 w3 = *(const float2*)&sW1[(kl * 4 + 3) * 64 + j0];
            unsigned long long p0 = pk2(w0.x, w0.y), p1 = pk2(w1.x, w1.y);
            unsigned long long p2 = pk2(w2.x, w2.y), p3 = pk2(w3.x, w3.y);
#pragma unroll
            for (int r = 0; r < 4; r++) {
                float b0 = __shfl_sync(0xffffffffu, xv[r].x, kl);
                float b1 = __shfl_sync(0xffffffffu, xv[r].y, kl);
                float b2 = __shfl_sync(0xffffffffu, xv[r].z, kl);
                float b3 = __shfl_sync(0xffffffffu, xv[r].w, kl);
                fma2(acc[r], p0, pk2(b0, b0));
                fma2(acc[r], p1, pk2(b1, b1));
                fma2(acc[r], p2, pk2(b2, b2));
                fma2(acc[r], p3, pk2(b3, b3));
            }
        }
#pragma unroll
        for (int r = 0; r < 4; r++) {
            float h0, h1;
            upk2(acc[r], h0, h1);
            h0 = fmaxf(h0 + b1a, 0.f);
            h1 = fmaxf(h1 + b1b, 0.f);
            float part = h0 * s2a + h1 * s2b;
#pragma unroll
            for (int o = 16; o; o >>= 1) part += __shfl_xor_sync(0xffffffffu, part, o);
            if (lane == 0) {
                float gt = part + bg2v;
                g_gate[base + r] = gt;
                atomicMax(&g_gmaxU[batch[base + r]], fkey(gt));
            }
        }
    }
}

__global__ __launch_bounds__(256) void denom_kernel(const int* __restrict__ batch) {
    int n = blockIdx.x * blockDim.x + threadIdx.x;
    if (n < NN) {
        int b = batch[n];
        float m = fdekey(g_gmaxU[b]);
        atomicAdd(&g_denom[b], expf(g_gate[n] - m));
    }
}

__global__ __launch_bounds__(256) void pooled_kernel(const float* __restrict__ Z,
                                                     const int* __restrict__ batch) {
    const int C = 64;
    int warp = (blockIdx.x * blockDim.x + threadIdx.x) >> 5;
    int lane = threadIdx.x & 31;
    int n0 = warp * C;
    if (n0 >= NN) return;
    int nend = min(n0 + C, NN);
    const float4* Z4 = (const float4*)Z;

    float4 acc = make_float4(0.f, 0.f, 0.f, 0.f);
    int curb = -1;
    float m = 0.f, den = 1.f;
    for (int n = n0; n < nend; n++) {
        int b = batch[n];
        if (b != curb) {
            if (curb >= 0) {
                float* p = &g_pooled[curb * FD + lane * 4];
                atomicAdd(p + 0, acc.x); atomicAdd(p + 1, acc.y);
                atomicAdd(p + 2, acc.z); atomicAdd(p + 3, acc.w);
                acc = make_float4(0.f, 0.f, 0.f, 0.f);
            }
            curb = b;
            m = fdekey(g_gmaxU[b]);
            den = g_denom[b];
        }
        float alpha = expf(g_gate[n] - m) / den;
        float4 z = Z4[n * 32 + lane];
        acc.x += alpha * z.x; acc.y += alpha * z.y;
        acc.z += alpha * z.z; acc.w += alpha * z.w;
    }
    if (curb >= 0) {
        float* p = &g_pooled[curb * FD + lane * 4];
        atomicAdd(p + 0, acc.x); atomicAdd(p + 1, acc.y);
        atomicAdd(p + 2, acc.z); atomicAdd(p + 3, acc.w);
    }
}

__global__ __launch_bounds__(256) void cls_kernel(const float* __restrict__ Wc,
                                                  const float* __restrict__ bc,
                                                  float* __restrict__ out) {
    int t = blockIdx.x * blockDim.x + threadIdx.x;
    if (t < NB * NC) {
        int b = t >> 4, c = t & 15;
        float s = bc[c];
        const float* p = &g_pooled[b * FD];
#pragma unroll 16
        for (int j = 0; j < FD; j++) s += p[j] * Wc[j * NC + c];
        out[t] = s;
    }
}

// ---------------- launch ----------------
extern "C" void kernel_launch(void* const* d_in, const int* in_sizes, int n_in,
                              void* d_out, int out_size) {
    const float* x    = (const float*)d_in[0];
    const int*   ei   = (const int*)d_in[1];
    const int*   batch= (const int*)d_in[2];
    const float* W1   = (const float*)d_in[3];
    const float* b1   = (const float*)d_in[4];
    const float* g1   = (const float*)d_in[5];
    const float* be1  = (const float*)d_in[6];
    const float* W2   = (const float*)d_in[7];
    const float* b2   = (const float*)d_in[8];
    const float* g2   = (const float*)d_in[9];
    const float* be2  = (const float*)d_in[10];
    const float* Wg1  = (const float*)d_in[11];
    const float* bg1  = (const float*)d_in[12];
    const float* Wg2  = (const float*)d_in[13];
    const float* bg2  = (const float*)d_in[14];
    const float* Wc   = (const float*)d_in[15];
    const float* bc   = (const float*)d_in[16];
    float* out = (float*)d_out;

    const int* src = ei;
    const int* dst = ei + NE;

    static cudaStream_t s1 = nullptr;
    static cudaEvent_t evFork = nullptr, evJoin = nullptr;
    static bool attr_done = false;
    if (!attr_done) {
        cudaFuncSetAttribute(gemm_kernel, cudaFuncAttributeMaxDynamicSharedMemorySize, 65536);
        cudaStreamCreateWithFlags(&s1, cudaStreamNonBlocking);
        cudaEventCreateWithFlags(&evFork, cudaEventDisableTiming);
        cudaEventCreateWithFlags(&evJoin, cudaEventDisableTiming);
        attr_done = true;
    }

    __half* h16; cudaGetSymbolAddress((void**)&h16, g_h16);
    float* bufB; cudaGetSymbolAddress((void**)&bufB, g_bufB);

    // fork: GEMM-1 (independent of CSR build) runs on s1
    cudaEventRecord(evFork, 0);
    cudaStreamWaitEvent(s1, evFork, 0);
    gemm_kernel<<<296, 256, 65536, s1>>>(x, W1, h16);
    cudaEventRecord(evJoin, s1);

    // CSR build chain on the main (capture-origin) stream
    init_kernel<<<(NN + 255) / 256, 256>>>();
    deg_kernel<<<(NE + 255) / 256, 256>>>(dst);
    scanA_kernel<<<NPB, 512>>>();
    scanB_kernel<<<1, 256>>>();
    scanC_kernel<<<NPB, 512>>>();
    fill_kernel<<<(NE + 255) / 256, 256>>>(src, dst);

    // join: agg1 needs both CSR and GEMM-1 output
    cudaStreamWaitEvent(0, evJoin, 0);
    agg_ln_relu_kernel<<<(NN * 32 + 255) / 256, 256>>>(h16, bufB, b1, g1, be1);
    // layer 2
    gemm_kernel<<<296, 256, 65536>>>(bufB, W2, h16);
    agg_ln_relu_kernel<<<(NN * 32 + 255) / 256, 256>>>(h16, bufB, b2, g2, be2);

    // attention pooling
    gate_kernel<<<592, 256>>>(bufB, Wg1, bg1, Wg2, bg2, batch);
    denom_kernel<<<(NN + 255) / 256, 256>>>(batch);
    pooled_kernel<<<(((NN + 63) / 64) * 32 + 255) / 256, 256>>>(bufB, batch);

    // classifier
    cls_kernel<<<(NB * NC + 255) / 256, 256>>>(Wc, bc, out);
}

// round 6
// speedup vs baseline: 2.2560x; 1.1420x over previous
#include <cuda_runtime.h>
#include <cuda_fp16.h>
#include <math.h>

#define NN 100000
#define NE 1600000
#define NB 64
#define FD 128
#define NC 16
#define NPB 196  // ceil(NN/512) scan blocks
#define LDSH 136 // padded smem leading dim (halves) for conflict-free ldmatrix

// ---------------- scratch (device globals; no allocations) ----------------
__device__ __half   g_h16[NN * FD];   // fp16 intermediate h = X@W (gather target)
__device__ float    g_bufB[NN * FD];  // fp32 Z = relu(LN(agg))
__device__ float    g_dinv[NN];
__device__ int      g_indeg[NN];
__device__ int      g_ctr[NN];
__device__ int      g_rowptr[NN + 1];
__device__ int      g_part[NPB];
__device__ int      g_partoff[NPB];
__device__ int      g_esrc[NE];
__device__ float    g_gate[NN];
__device__ unsigned g_gmaxU[NB];
__device__ float    g_denom[NB];
__device__ float    g_pooled[NB * FD];

// ---------------- helpers ----------------
__device__ __forceinline__ unsigned long long pk2(float lo, float hi) {
    unsigned long long r;
    asm("mov.b64 %0, {%1,%2};" : "=l"(r) : "f"(lo), "f"(hi));
    return r;
}
__device__ __forceinline__ void upk2(unsigned long long v, float& lo, float& hi) {
    asm("mov.b64 {%0,%1}, %2;" : "=f"(lo), "=f"(hi) : "l"(v));
}
__device__ __forceinline__ void fma2(unsigned long long& acc, unsigned long long a,
                                     unsigned long long b) {
    asm("fma.rn.f32x2 %0, %1, %2, %0;" : "+l"(acc) : "l"(a), "l"(b));
}
__device__ __forceinline__ unsigned fkey(float f) {
    unsigned u = __float_as_uint(f);
    return (u & 0x80000000u) ? ~u : (u | 0x80000000u);
}
__device__ __forceinline__ float fdekey(unsigned k) {
    unsigned u = (k & 0x80000000u) ? (k ^ 0x80000000u) : ~k;
    return __uint_as_float(u);
}

// ---------------- setup kernels ----------------
__global__ __launch_bounds__(256) void init_kernel() {
    int i = blockIdx.x * blockDim.x + threadIdx.x;
    if (i < NN) { g_indeg[i] = 0; g_ctr[i] = 0; }
    if (i < NB * FD) g_pooled[i] = 0.f;
    if (i < NB) { g_denom[i] = 0.f; g_gmaxU[i] = 0x007FFFFFu; /* key(-inf) */ }
    if (i == 0) g_rowptr[NN] = NE;
}

__global__ __launch_bounds__(256) void deg_kernel(const int* __restrict__ dst) {
    int e = blockIdx.x * blockDim.x + threadIdx.x;
    if (e < NE) atomicAdd(&g_indeg[dst[e]], 1);
}

__global__ __launch_bounds__(512) void scanA_kernel() {
    int t = threadIdx.x, b = blockIdx.x;
    int idx = b * 512 + t;
    int v = (idx < NN) ? g_indeg[idx] : 0;
    if (idx < NN) g_dinv[idx] = rsqrtf((float)(v + 1));
    int x = v;
#pragma unroll
    for (int o = 16; o; o >>= 1) x += __shfl_xor_sync(0xffffffffu, x, o);
    __shared__ int wsum[16];
    int lane = t & 31, wid = t >> 5;
    if (lane == 0) wsum[wid] = x;
    __syncthreads();
    if (t == 0) {
        int s = 0;
#pragma unroll
        for (int w = 0; w < 16; w++) s += wsum[w];
        g_part[b] = s;
    }
}

__global__ __launch_bounds__(256) void scanB_kernel() {
    int t = threadIdx.x;
    int v = (t < NPB) ? g_part[t] : 0;
    int lane = t & 31, wid = t >> 5;
    int x = v;
#pragma unroll
    for (int o = 1; o < 32; o <<= 1) {
        int y = __shfl_up_sync(0xffffffffu, x, o);
        if (lane >= o) x += y;
    }
    __shared__ int wsum[8];
    if (lane == 31) wsum[wid] = x;
    __syncthreads();
    if (wid == 0) {
        int s = (lane < 8) ? wsum[lane] : 0;
#pragma unroll
        for (int o = 1; o < 8; o <<= 1) {
            int y = __shfl_up_sync(0xffffffffu, s, o);
            if (lane >= o) s += y;
        }
        if (lane < 8) wsum[lane] = s;
    }
    __syncthreads();
    int excl = x - v + (wid > 0 ? wsum[wid - 1] : 0);
    if (t < NPB) g_partoff[t] = excl;
}

__global__ __launch_bounds__(512) void scanC_kernel() {
    int t = threadIdx.x, b = blockIdx.x;
    int idx = b * 512 + t;
    int v = (idx < NN) ? g_indeg[idx] : 0;
    int lane = t & 31, wid = t >> 5;
    int x = v;
#pragma unroll
    for (int o = 1; o < 32; o <<= 1) {
        int y = __shfl_up_sync(0xffffffffu, x, o);
        if (lane >= o) x += y;
    }
    __shared__ int wsum[16];
    if (lane == 31) wsum[wid] = x;
    __syncthreads();
    if (wid == 0) {
        int s = (lane < 16) ? wsum[lane] : 0;
#pragma unroll
        for (int o = 1; o < 16; o <<= 1) {
            int y = __shfl_up_sync(0xffffffffu, s, o);
            if (lane >= o) s += y;
        }
        if (lane < 16) wsum[lane] = s;
    }
    __syncthreads();
    int excl = x - v + (wid > 0 ? wsum[wid - 1] : 0);
    if (idx < NN) g_rowptr[idx] = g_partoff[b] + excl;
}

__global__ __launch_bounds__(256) void fill_kernel(const int* __restrict__ src,
                                                   const int* __restrict__ dst) {
    int e = blockIdx.x * blockDim.x + threadIdx.x;
    if (e < NE) {
        int d = dst[e];
        int p = g_rowptr[d] + atomicAdd(&g_ctr[d], 1);
        g_esrc[p] = src[e];
    }
}

// ---------------- GEMM: H16 = X @ W (tensor cores, fp16 in / fp32 acc) ----------------
// block = 256 thr = 8 warps; each block: 128 rows x 128 cols, K=128.
__global__ __launch_bounds__(256, 2) void gemm_mma_kernel(const float* __restrict__ X,
                                                          const float* __restrict__ W,
                                                          __half* __restrict__ Y) {
    extern __shared__ __half smemh[];
    __half* sA = smemh;               // [128][LDSH]
    __half* sB = smemh + 128 * LDSH;  // [128][LDSH]  (W, row = k, col = n)
    int tid = threadIdx.x;
    int m0 = blockIdx.x * 128;

    // stage W -> sB (fp32 -> fp16)
    {
        const float4* W4 = (const float4*)W;
        for (int i = tid; i < 128 * 32; i += 256) {
            int row = i >> 5, j = i & 31;
            float4 v = W4[i];
            *(__half2*)&sB[row * LDSH + j * 4]     = __floats2half2_rn(v.x, v.y);
            *(__half2*)&sB[row * LDSH + j * 4 + 2] = __floats2half2_rn(v.z, v.w);
        }
    }
    // stage X rows [m0, m0+128) -> sA (zero-fill OOB)
    {
        const float4* X4 = (const float4*)X;
        for (int i = tid; i < 128 * 32; i += 256) {
            int row = i >> 5, j = i & 31;
            int gr = m0 + row;
            float4 v = (gr < NN) ? X4[gr * 32 + j] : make_float4(0.f, 0.f, 0.f, 0.f);
            *(__half2*)&sA[row * LDSH + j * 4]     = __floats2half2_rn(v.x, v.y);
            *(__half2*)&sA[row * LDSH + j * 4 + 2] = __floats2half2_rn(v.z, v.w);
        }
    }
    __syncthreads();

    int warp = tid >> 5, lane = tid & 31;
    int mrow = warp * 16;

    float acc[16][4];
#pragma unroll
    for (int nt = 0; nt < 16; nt++) {
        acc[nt][0] = acc[nt][1] = acc[nt][2] = acc[nt][3] = 0.f;
    }

#pragma unroll
    for (int k0 = 0; k0 < 128; k0 += 16) {
        unsigned a0, a1, a2, a3;
        {
            int arow = mrow + (lane & 15);
            int acol = k0 + ((lane >> 4) << 3);
            unsigned aaddr = (unsigned)__cvta_generic_to_shared(&sA[arow * LDSH + acol]);
            asm volatile("ldmatrix.sync.aligned.m8n8.x4.shared.b16 {%0,%1,%2,%3}, [%4];"
                         : "=r"(a0), "=r"(a1), "=r"(a2), "=r"(a3) : "r"(aaddr));
        }
#pragma unroll
        for (int nt = 0; nt < 16; nt++) {
            unsigned b0, b1;
            unsigned baddr = (unsigned)__cvta_generic_to_shared(
                &sB[(k0 + (lane & 15)) * LDSH + nt * 8]);
            asm volatile("ldmatrix.sync.aligned.m8n8.x2.trans.shared.b16 {%0,%1}, [%2];"
                         : "=r"(b0), "=r"(b1) : "r"(baddr));
            asm volatile(
                "mma.sync.aligned.m16n8k16.row.col.f32.f16.f16.f32 "
                "{%0,%1,%2,%3}, {%4,%5,%6,%7}, {%8,%9}, {%0,%1,%2,%3};"
                : "+f"(acc[nt][0]), "+f"(acc[nt][1]), "+f"(acc[nt][2]), "+f"(acc[nt][3])
                : "r"(a0), "r"(a1), "r"(a2), "r"(a3), "r"(b0), "r"(b1));
        }
    }

    // store: lane l holds (r, c), (r, c+1), (r+8, c), (r+8, c+1); r = l>>2, c = 2*(l&3)
    int r = lane >> 2, c = (lane & 3) * 2;
    int gr0 = m0 + mrow + r;
    int gr1 = gr0 + 8;
#pragma unroll
    for (int nt = 0; nt < 16; nt++) {
        int col = nt * 8 + c;
        if (gr0 < NN) *(__half2*)&Y[gr0 * FD + col] = __floats2half2_rn(acc[nt][0], acc[nt][1]);
        if (gr1 < NN) *(__half2*)&Y[gr1 * FD + col] = __floats2half2_rn(acc[nt][2], acc[nt][3]);
    }
}

// ---------------- per-node CSR aggregation (fp16 gathers) + bias + LN + ReLU ----------------
__global__ __launch_bounds__(256) void agg_ln_relu_kernel(const __half* __restrict__ H,
                                                          float* __restrict__ Z,
                                                          const float* __restrict__ bias,
                                                          const float* __restrict__ gam,
                                                          const float* __restrict__ bet) {
    int gw = (blockIdx.x * blockDim.x + threadIdx.x) >> 5;
    if (gw >= NN) return;
    int lane = threadIdx.x & 31;
    int n = gw;
    int r0 = g_rowptr[n], r1 = g_rowptr[n + 1];
    float dn = g_dinv[n];
    const uint2* H2 = (const uint2*)H;

    uint2 sv = H2[n * 32 + lane];
    float2 sf0 = __half22float2(*(__half2*)&sv.x);
    float2 sf1 = __half22float2(*(__half2*)&sv.y);
    float4 acc;
    acc.x = dn * sf0.x; acc.y = dn * sf0.y; acc.z = dn * sf1.x; acc.w = dn * sf1.y;

    int i = r0;
    for (; i + 4 <= r1; i += 4) {
        int s0 = g_esrc[i], s1 = g_esrc[i + 1], s2 = g_esrc[i + 2], s3 = g_esrc[i + 3];
        float w0 = g_dinv[s0], w1 = g_dinv[s1], w2 = g_dinv[s2], w3 = g_dinv[s3];
        uint2 v0 = H2[s0 * 32 + lane];
        uint2 v1 = H2[s1 * 32 + lane];
        uint2 v2 = H2[s2 * 32 + lane];
        uint2 v3 = H2[s3 * 32 + lane];
        float2 f0a = __half22float2(*(__half2*)&v0.x), f0b = __half22float2(*(__half2*)&v0.y);
        float2 f1a = __half22float2(*(__half2*)&v1.x), f1b = __half22float2(*(__half2*)&v1.y);
        float2 f2a = __half22float2(*(__half2*)&v2.x), f2b = __half22float2(*(__half2*)&v2.y);
        float2 f3a = __half22float2(*(__half2*)&v3.x), f3b = __half22float2(*(__half2*)&v3.y);
        acc.x += w0 * f0a.x + w1 * f1a.x + w2 * f2a.x + w3 * f3a.x;
        acc.y += w0 * f0a.y + w1 * f1a.y + w2 * f2a.y + w3 * f3a.y;
        acc.z += w0 * f0b.x + w1 * f1b.x + w2 * f2b.x + w3 * f3b.x;
        acc.w += w0 * f0b.y + w1 * f1b.y + w2 * f2b.y + w3 * f3b.y;
    }
    for (; i < r1; i++) {
        int s = g_esrc[i];
        float w = g_dinv[s];
        uint2 v = H2[s * 32 + lane];
        float2 fa = __half22float2(*(__half2*)&v.x), fb = __half22float2(*(__half2*)&v.y);
        acc.x += w * fa.x; acc.y += w * fa.y; acc.z += w * fb.x; acc.w += w * fb.y;
    }

    const float4* b4p = (const float4*)bias;
    float4 b4 = b4p[lane];
    acc.x = acc.x * dn + b4.x;
    acc.y = acc.y * dn + b4.y;
    acc.z = acc.z * dn + b4.z;
    acc.w = acc.w * dn + b4.w;

    float s = acc.x + acc.y + acc.z + acc.w;
#pragma unroll
    for (int o = 16; o; o >>= 1) s += __shfl_xor_sync(0xffffffffu, s, o);
    float mean = s * (1.0f / FD);
    float dx = acc.x - mean, dy = acc.y - mean, dz = acc.z - mean, dw = acc.w - mean;
    float ss = dx * dx + dy * dy + dz * dz + dw * dw;
#pragma unroll
    for (int o = 16; o; o >>= 1) ss += __shfl_xor_sync(0xffffffffu, ss, o);
    float rstd = rsqrtf(ss * (1.0f / FD) + 1e-5f);

    const float4* g4p = (const float4*)gam;
    const float4* e4p = (const float4*)bet;
    float4 g4 = g4p[lane], e4 = e4p[lane];
    float4 out;
    out.x = fmaxf(dx * rstd * g4.x + e4.x, 0.f);
    out.y = fmaxf(dy * rstd * g4.y + e4.y, 0.f);
    out.z = fmaxf(dz * rstd * g4.z + e4.z, 0.f);
    out.w = fmaxf(dw * rstd * g4.w + e4.w, 0.f);
    ((float4*)Z)[n * 32 + lane] = out;
}

// ---------------- gate MLP (4 rows per warp per iter) ----------------
__global__ __launch_bounds__(256) void gate_kernel(const float* __restrict__ Z,
                                                   const float* __restrict__ Wg1,
                                                   const float* __restrict__ bg1,
                                                   const float* __restrict__ Wg2,
                                                   const float* __restrict__ bg2,
                                                   const int* __restrict__ batch) {
    __shared__ float sW1[FD * 64];
    __shared__ float sW2[64];
    __shared__ float sB1[64];
    int tid = threadIdx.x;
    for (int i = tid; i < FD * 64; i += 256) sW1[i] = Wg1[i];
    if (tid < 64) { sW2[tid] = Wg2[tid]; sB1[tid] = bg1[tid]; }
    __syncthreads();

    int warp = (blockIdx.x * 256 + tid) >> 5;
    int nwarps = (gridDim.x * 256) >> 5;
    int lane = tid & 31;
    int j0 = lane * 2;
    const float4* Z4 = (const float4*)Z;
    float bg2v = bg2[0];
    float s2a = sW2[j0], s2b = sW2[j0 + 1];
    float b1a = sB1[j0], b1b = sB1[j0 + 1];

    for (int base = warp * 4; base < NN; base += nwarps * 4) {
        float4 xv[4];
#pragma unroll
        for (int r = 0; r < 4; r++) xv[r] = Z4[(base + r) * 32 + lane];
        unsigned long long acc[4];
#pragma unroll
        for (int r = 0; r < 4; r++) acc[r] = pk2(0.f, 0.f);

#pragma unroll
        for (int kl = 0; kl < 32; kl++) {
            float2 w0 = *(const float2*)&sW1[(kl * 4 + 0) * 64 + j0];
            float2 w1 = *(const float2*)&sW1[(kl * 4 + 1) * 64 + j0];
            float2 w2 = *(const float2*)&sW1[(kl * 4 + 2) * 64 + j0];
            float2 w3 = *(const float2*)&sW1[(kl * 4 + 3) * 64 + j0];
            unsigned long long p0 = pk2(w0.x, w0.y), p1 = pk2(w1.x, w1.y);
            unsigned long long p2 = pk2(w2.x, w2.y), p3 = pk2(w3.x, w3.y);
#pragma unroll
            for (int r = 0; r < 4; r++) {
                float b0 = __shfl_sync(0xffffffffu, xv[r].x, kl);
                float b1 = __shfl_sync(0xffffffffu, xv[r].y, kl);
                float b2 = __shfl_sync(0xffffffffu, xv[r].z, kl);
                float b3 = __shfl_sync(0xffffffffu, xv[r].w, kl);
                fma2(acc[r], p0, pk2(b0, b0));
                fma2(acc[r], p1, pk2(b1, b1));
                fma2(acc[r], p2, pk2(b2, b2));
                fma2(acc[r], p3, pk2(b3, b3));
            }
        }
#pragma unroll
        for (int r = 0; r < 4; r++) {
            float h0, h1;
            upk2(acc[r], h0, h1);
            h0 = fmaxf(h0 + b1a, 0.f);
            h1 = fmaxf(h1 + b1b, 0.f);
            float part = h0 * s2a + h1 * s2b;
#pragma unroll
            for (int o = 16; o; o >>= 1) part += __shfl_xor_sync(0xffffffffu, part, o);
            if (lane == 0) {
                float gt = part + bg2v;
                g_gate[base + r] = gt;
                atomicMax(&g_gmaxU[batch[base + r]], fkey(gt));
            }
        }
    }
}

__global__ __launch_bounds__(256) void denom_kernel(const int* __restrict__ batch) {
    int n = blockIdx.x * blockDim.x + threadIdx.x;
    if (n < NN) {
        int b = batch[n];
        float m = fdekey(g_gmaxU[b]);
        atomicAdd(&g_denom[b], expf(g_gate[n] - m));
    }
}

__global__ __launch_bounds__(256) void pooled_kernel(const float* __restrict__ Z,
                                                     const int* __restrict__ batch) {
    const int C = 64;
    int warp = (blockIdx.x * blockDim.x + threadIdx.x) >> 5;
    int lane = threadIdx.x & 31;
    int n0 = warp * C;
    if (n0 >= NN) return;
    int nend = min(n0 + C, NN);
    const float4* Z4 = (const float4*)Z;

    float4 acc = make_float4(0.f, 0.f, 0.f, 0.f);
    int curb = -1;
    float m = 0.f, den = 1.f;
    for (int n = n0; n < nend; n++) {
        int b = batch[n];
        if (b != curb) {
            if (curb >= 0) {
                float* p = &g_pooled[curb * FD + lane * 4];
                atomicAdd(p + 0, acc.x); atomicAdd(p + 1, acc.y);
                atomicAdd(p + 2, acc.z); atomicAdd(p + 3, acc.w);
                acc = make_float4(0.f, 0.f, 0.f, 0.f);
            }
            curb = b;
            m = fdekey(g_gmaxU[b]);
            den = g_denom[b];
        }
        float alpha = expf(g_gate[n] - m) / den;
        float4 z = Z4[n * 32 + lane];
        acc.x += alpha * z.x; acc.y += alpha * z.y;
        acc.z += alpha * z.z; acc.w += alpha * z.w;
    }
    if (curb >= 0) {
        float* p = &g_pooled[curb * FD + lane * 4];
        atomicAdd(p + 0, acc.x); atomicAdd(p + 1, acc.y);
        atomicAdd(p + 2, acc.z); atomicAdd(p + 3, acc.w);
    }
}

__global__ __launch_bounds__(256) void cls_kernel(const float* __restrict__ Wc,
                                                  const float* __restrict__ bc,
                                                  float* __restrict__ out) {
    int t = blockIdx.x * blockDim.x + threadIdx.x;
    if (t < NB * NC) {
        int b = t >> 4, c = t & 15;
        float s = bc[c];
        const float* p = &g_pooled[b * FD];
#pragma unroll 16
        for (int j = 0; j < FD; j++) s += p[j] * Wc[j * NC + c];
        out[t] = s;
    }
}

// ---------------- launch ----------------
extern "C" void kernel_launch(void* const* d_in, const int* in_sizes, int n_in,
                              void* d_out, int out_size) {
    const float* x    = (const float*)d_in[0];
    const int*   ei   = (const int*)d_in[1];
    const int*   batch= (const int*)d_in[2];
    const float* W1   = (const float*)d_in[3];
    const float* b1   = (const float*)d_in[4];
    const float* g1   = (const float*)d_in[5];
    const float* be1  = (const float*)d_in[6];
    const float* W2   = (const float*)d_in[7];
    const float* b2   = (const float*)d_in[8];
    const float* g2   = (const float*)d_in[9];
    const float* be2  = (const float*)d_in[10];
    const float* Wg1  = (const float*)d_in[11];
    const float* bg1  = (const float*)d_in[12];
    const float* Wg2  = (const float*)d_in[13];
    const float* bg2  = (const float*)d_in[14];
    const float* Wc   = (const float*)d_in[15];
    const float* bc   = (const float*)d_in[16];
    float* out = (float*)d_out;

    const int* src = ei;
    const int* dst = ei + NE;

    const int GEMM_SMEM = 2 * 128 * LDSH * (int)sizeof(__half);  // 69632 B

    static cudaStream_t s1 = nullptr;
    static cudaEvent_t evFork = nullptr, evJoin = nullptr;
    static bool attr_done = false;
    if (!attr_done) {
        cudaFuncSetAttribute(gemm_mma_kernel, cudaFuncAttributeMaxDynamicSharedMemorySize,
                             GEMM_SMEM);
        cudaStreamCreateWithFlags(&s1, cudaStreamNonBlocking);
        cudaEventCreateWithFlags(&evFork, cudaEventDisableTiming);
        cudaEventCreateWithFlags(&evJoin, cudaEventDisableTiming);
        attr_done = true;
    }

    __half* h16; cudaGetSymbolAddress((void**)&h16, g_h16);
    float* bufB; cudaGetSymbolAddress((void**)&bufB, g_bufB);

    const int GEMM_GRID = (NN + 127) / 128;  // 782

    // fork: GEMM-1 (independent of CSR build) runs on s1
    cudaEventRecord(evFork, 0);
    cudaStreamWaitEvent(s1, evFork, 0);
    gemm_mma_kernel<<<GEMM_GRID, 256, GEMM_SMEM, s1>>>(x, W1, h16);
    cudaEventRecord(evJoin, s1);

    // CSR build chain on the main (capture-origin) stream
    init_kernel<<<(NN + 255) / 256, 256>>>();
    deg_kernel<<<(NE + 255) / 256, 256>>>(dst);
    scanA_kernel<<<NPB, 512>>>();
    scanB_kernel<<<1, 256>>>();
    scanC_kernel<<<NPB, 512>>>();
    fill_kernel<<<(NE + 255) / 256, 256>>>(src, dst);

    // join: agg1 needs both CSR and GEMM-1 output
    cudaStreamWaitEvent(0, evJoin, 0);
    agg_ln_relu_kernel<<<(NN * 32 + 255) / 256, 256>>>(h16, bufB, b1, g1, be1);
    // layer 2
    gemm_mma_kernel<<<GEMM_GRID, 256, GEMM_SMEM>>>(bufB, W2, h16);
    agg_ln_relu_kernel<<<(NN * 32 + 255) / 256, 256>>>(h16, bufB, b2, g2, be2);

    // attention pooling
    gate_kernel<<<592, 256>>>(bufB, Wg1, bg1, Wg2, bg2, batch);
    denom_kernel<<<(NN + 255) / 256, 256>>>(batch);
    pooled_kernel<<<(((NN + 63) / 64) * 32 + 255) / 256, 256>>>(bufB, batch);

    // classifier
    cls_kernel<<<(NB * NC + 255) / 256, 256>>>(Wc, bc, out);
}

// round 7
// speedup vs baseline: 2.3530x; 1.0430x over previous
#include <cuda_runtime.h>
#include <cuda_fp16.h>
#include <math.h>

#define NN 100000
#define NE 1600000
#define NB 64
#define FD 128
#define NC 16
#define NPB 196  // ceil(NN/512) scan blocks
#define LDSH 136 // padded smem leading dim (halves) for conflict-free ldmatrix

// ---------------- scratch (device globals; no allocations) ----------------
__device__ __half   g_h16[NN * FD];   // fp16 scaled intermediate h~ = dinv * (X@W)
__device__ float    g_bufB[NN * FD];  // fp32 Z = relu(LN(agg))
__device__ float    g_dinv[NN];
__device__ int      g_indeg[NN];
__device__ int      g_ctr[NN];
__device__ int      g_rowptr[NN + 1];
__device__ int      g_part[NPB];
__device__ int      g_partoff[NPB];
__device__ int      g_esrc[NE];
__device__ float    g_gate[NN];
__device__ unsigned g_gmaxU[NB];
__device__ float    g_denom[NB];
__device__ float    g_pooled[NB * FD];

// ---------------- helpers ----------------
__device__ __forceinline__ unsigned long long pk2(float lo, float hi) {
    unsigned long long r;
    asm("mov.b64 %0, {%1,%2};" : "=l"(r) : "f"(lo), "f"(hi));
    return r;
}
__device__ __forceinline__ void upk2(unsigned long long v, float& lo, float& hi) {
    asm("mov.b64 {%0,%1}, %2;" : "=f"(lo), "=f"(hi) : "l"(v));
}
__device__ __forceinline__ void fma2(unsigned long long& acc, unsigned long long a,
                                     unsigned long long b) {
    asm("fma.rn.f32x2 %0, %1, %2, %0;" : "+l"(acc) : "l"(a), "l"(b));
}
__device__ __forceinline__ unsigned fkey(float f) {
    unsigned u = __float_as_uint(f);
    return (u & 0x80000000u) ? ~u : (u | 0x80000000u);
}
__device__ __forceinline__ float fdekey(unsigned k) {
    unsigned u = (k & 0x80000000u) ? (k ^ 0x80000000u) : ~k;
    return __uint_as_float(u);
}

// ---------------- setup kernels ----------------
__global__ __launch_bounds__(256) void init_kernel() {
    int i = blockIdx.x * blockDim.x + threadIdx.x;
    if (i < NN) { g_indeg[i] = 0; g_ctr[i] = 0; }
    if (i < NB * FD) g_pooled[i] = 0.f;
    if (i < NB) { g_denom[i] = 0.f; g_gmaxU[i] = 0x007FFFFFu; /* key(-inf) */ }
    if (i == 0) g_rowptr[NN] = NE;
}

__global__ __launch_bounds__(256) void deg_kernel(const int* __restrict__ dst) {
    int e = blockIdx.x * blockDim.x + threadIdx.x;
    if (e < NE) atomicAdd(&g_indeg[dst[e]], 1);
}

__global__ __launch_bounds__(512) void scanA_kernel() {
    int t = threadIdx.x, b = blockIdx.x;
    int idx = b * 512 + t;
    int v = (idx < NN) ? g_indeg[idx] : 0;
    if (idx < NN) g_dinv[idx] = rsqrtf((float)(v + 1));
    int x = v;
#pragma unroll
    for (int o = 16; o; o >>= 1) x += __shfl_xor_sync(0xffffffffu, x, o);
    __shared__ int wsum[16];
    int lane = t & 31, wid = t >> 5;
    if (lane == 0) wsum[wid] = x;
    __syncthreads();
    if (t == 0) {
        int s = 0;
#pragma unroll
        for (int w = 0; w < 16; w++) s += wsum[w];
        g_part[b] = s;
    }
}

__global__ __launch_bounds__(256) void scanB_kernel() {
    int t = threadIdx.x;
    int v = (t < NPB) ? g_part[t] : 0;
    int lane = t & 31, wid = t >> 5;
    int x = v;
#pragma unroll
    for (int o = 1; o < 32; o <<= 1) {
        int y = __shfl_up_sync(0xffffffffu, x, o);
        if (lane >= o) x += y;
    }
    __shared__ int wsum[8];
    if (lane == 31) wsum[wid] = x;
    __syncthreads();
    if (wid == 0) {
        int s = (lane < 8) ? wsum[lane] : 0;
#pragma unroll
        for (int o = 1; o < 8; o <<= 1) {
            int y = __shfl_up_sync(0xffffffffu, s, o);
            if (lane >= o) s += y;
        }
        if (lane < 8) wsum[lane] = s;
    }
    __syncthreads();
    int excl = x - v + (wid > 0 ? wsum[wid - 1] : 0);
    if (t < NPB) g_partoff[t] = excl;
}

__global__ __launch_bounds__(512) void scanC_kernel() {
    int t = threadIdx.x, b = blockIdx.x;
    int idx = b * 512 + t;
    int v = (idx < NN) ? g_indeg[idx] : 0;
    int lane = t & 31, wid = t >> 5;
    int x = v;
#pragma unroll
    for (int o = 1; o < 32; o <<= 1) {
        int y = __shfl_up_sync(0xffffffffu, x, o);
        if (lane >= o) x += y;
    }
    __shared__ int wsum[16];
    if (lane == 31) wsum[wid] = x;
    __syncthreads();
    if (wid == 0) {
        int s = (lane < 16) ? wsum[lane] : 0;
#pragma unroll
        for (int o = 1; o < 16; o <<= 1) {
            int y = __shfl_up_sync(0xffffffffu, s, o);
            if (lane >= o) s += y;
        }
        if (lane < 16) wsum[lane] = s;
    }
    __syncthreads();
    int excl = x - v + (wid > 0 ? wsum[wid - 1] : 0);
    if (idx < NN) g_rowptr[idx] = g_partoff[b] + excl;
}

__global__ __launch_bounds__(256) void fill_kernel(const int* __restrict__ src,
                                                   const int* __restrict__ dst) {
    int e = blockIdx.x * blockDim.x + threadIdx.x;
    if (e < NE) {
        int d = dst[e];
        int p = g_rowptr[d] + atomicAdd(&g_ctr[d], 1);
        g_esrc[p] = src[e];
    }
}

// ---------------- GEMM: H~ = dinv * (X @ W) (tensor cores, fp16 in / fp32 acc) ----------------
__global__ __launch_bounds__(256, 2) void gemm_mma_kernel(const float* __restrict__ X,
                                                          const float* __restrict__ W,
                                                          __half* __restrict__ Y) {
    extern __shared__ __half smemh[];
    __half* sA = smemh;               // [128][LDSH]
    __half* sB = smemh + 128 * LDSH;  // [128][LDSH]  (W, row = k, col = n)
    int tid = threadIdx.x;
    int m0 = blockIdx.x * 128;

    {
        const float4* W4 = (const float4*)W;
        for (int i = tid; i < 128 * 32; i += 256) {
            int row = i >> 5, j = i & 31;
            float4 v = W4[i];
            *(__half2*)&sB[row * LDSH + j * 4]     = __floats2half2_rn(v.x, v.y);
            *(__half2*)&sB[row * LDSH + j * 4 + 2] = __floats2half2_rn(v.z, v.w);
        }
    }
    {
        const float4* X4 = (const float4*)X;
        for (int i = tid; i < 128 * 32; i += 256) {
            int row = i >> 5, j = i & 31;
            int gr = m0 + row;
            float4 v = (gr < NN) ? X4[gr * 32 + j] : make_float4(0.f, 0.f, 0.f, 0.f);
            *(__half2*)&sA[row * LDSH + j * 4]     = __floats2half2_rn(v.x, v.y);
            *(__half2*)&sA[row * LDSH + j * 4 + 2] = __floats2half2_rn(v.z, v.w);
        }
    }
    __syncthreads();

    int warp = tid >> 5, lane = tid & 31;
    int mrow = warp * 16;

    float acc[16][4];
#pragma unroll
    for (int nt = 0; nt < 16; nt++) {
        acc[nt][0] = acc[nt][1] = acc[nt][2] = acc[nt][3] = 0.f;
    }

#pragma unroll
    for (int k0 = 0; k0 < 128; k0 += 16) {
        unsigned a0, a1, a2, a3;
        {
            int arow = mrow + (lane & 15);
            int acol = k0 + ((lane >> 4) << 3);
            unsigned aaddr = (unsigned)__cvta_generic_to_shared(&sA[arow * LDSH + acol]);
            asm volatile("ldmatrix.sync.aligned.m8n8.x4.shared.b16 {%0,%1,%2,%3}, [%4];"
                         : "=r"(a0), "=r"(a1), "=r"(a2), "=r"(a3) : "r"(aaddr));
        }
#pragma unroll
        for (int nt = 0; nt < 16; nt++) {
            unsigned b0, b1;
            unsigned baddr = (unsigned)__cvta_generic_to_shared(
                &sB[(k0 + (lane & 15)) * LDSH + nt * 8]);
            asm volatile("ldmatrix.sync.aligned.m8n8.x2.trans.shared.b16 {%0,%1}, [%2];"
                         : "=r"(b0), "=r"(b1) : "r"(baddr));
            asm volatile(
                "mma.sync.aligned.m16n8k16.row.col.f32.f16.f16.f32 "
                "{%0,%1,%2,%3}, {%4,%5,%6,%7}, {%8,%9}, {%0,%1,%2,%3};"
                : "+f"(acc[nt][0]), "+f"(acc[nt][1]), "+f"(acc[nt][2]), "+f"(acc[nt][3])
                : "r"(a0), "r"(a1), "r"(a2), "r"(a3), "r"(b0), "r"(b1));
        }
    }

    int r = lane >> 2, c = (lane & 3) * 2;
    int gr0 = m0 + mrow + r;
    int gr1 = gr0 + 8;
    float d0 = (gr0 < NN) ? g_dinv[gr0] : 0.f;
    float d1 = (gr1 < NN) ? g_dinv[gr1] : 0.f;
#pragma unroll
    for (int nt = 0; nt < 16; nt++) {
        int col = nt * 8 + c;
        if (gr0 < NN)
            *(__half2*)&Y[gr0 * FD + col] = __floats2half2_rn(acc[nt][0] * d0, acc[nt][1] * d0);
        if (gr1 < NN)
            *(__half2*)&Y[gr1 * FD + col] = __floats2half2_rn(acc[nt][2] * d1, acc[nt][3] * d1);
    }
}

// ---------------- per-node CSR aggregation (pre-scaled fp16 gathers) + bias + LN + ReLU ----------------
__global__ __launch_bounds__(256) void agg_ln_relu_kernel(const __half* __restrict__ H,
                                                          float* __restrict__ Z,
                                                          const float* __restrict__ bias,
                                                          const float* __restrict__ gam,
                                                          const float* __restrict__ bet) {
    int gw = (blockIdx.x * blockDim.x + threadIdx.x) >> 5;
    if (gw >= NN) return;
    int lane = threadIdx.x & 31;
    int n = gw;
    int r0 = g_rowptr[n], r1 = g_rowptr[n + 1];
    float dn = g_dinv[n];
    const uint2* H2 = (const uint2*)H;

    // self term: h~[n] = dinv[n]*h[n] contributes exactly once
    uint2 sv = H2[n * 32 + lane];
    float2 sf0 = __half22float2(*(__half2*)&sv.x);
    float2 sf1 = __half22float2(*(__half2*)&sv.y);
    float4 acc = make_float4(sf0.x, sf0.y, sf1.x, sf1.y);

    int i = r0;
    for (; i + 8 <= r1; i += 8) {
        uint2 v0 = H2[g_esrc[i]     * 32 + lane];
        uint2 v1 = H2[g_esrc[i + 1] * 32 + lane];
        uint2 v2 = H2[g_esrc[i + 2] * 32 + lane];
        uint2 v3 = H2[g_esrc[i + 3] * 32 + lane];
        uint2 v4 = H2[g_esrc[i + 4] * 32 + lane];
        uint2 v5 = H2[g_esrc[i + 5] * 32 + lane];
        uint2 v6 = H2[g_esrc[i + 6] * 32 + lane];
        uint2 v7 = H2[g_esrc[i + 7] * 32 + lane];
#define ACC8(v)                                                      \
        {                                                            \
            float2 fa = __half22float2(*(__half2*)&(v).x);           \
            float2 fb = __half22float2(*(__half2*)&(v).y);           \
            acc.x += fa.x; acc.y += fa.y; acc.z += fb.x; acc.w += fb.y; \
        }
        ACC8(v0) ACC8(v1) ACC8(v2) ACC8(v3) ACC8(v4) ACC8(v5) ACC8(v6) ACC8(v7)
    }
    for (; i < r1; i++) {
        uint2 v = H2[g_esrc[i] * 32 + lane];
        ACC8(v)
    }
#undef ACC8

    const float4* b4p = (const float4*)bias;
    float4 b4 = b4p[lane];
    acc.x = acc.x * dn + b4.x;
    acc.y = acc.y * dn + b4.y;
    acc.z = acc.z * dn + b4.z;
    acc.w = acc.w * dn + b4.w;

    float s = acc.x + acc.y + acc.z + acc.w;
#pragma unroll
    for (int o = 16; o; o >>= 1) s += __shfl_xor_sync(0xffffffffu, s, o);
    float mean = s * (1.0f / FD);
    float dx = acc.x - mean, dy = acc.y - mean, dz = acc.z - mean, dw = acc.w - mean;
    float ss = dx * dx + dy * dy + dz * dz + dw * dw;
#pragma unroll
    for (int o = 16; o; o >>= 1) ss += __shfl_xor_sync(0xffffffffu, ss, o);
    float rstd = rsqrtf(ss * (1.0f / FD) + 1e-5f);

    const float4* g4p = (const float4*)gam;
    const float4* e4p = (const float4*)bet;
    float4 g4 = g4p[lane], e4 = e4p[lane];
    float4 out;
    out.x = fmaxf(dx * rstd * g4.x + e4.x, 0.f);
    out.y = fmaxf(dy * rstd * g4.y + e4.y, 0.f);
    out.z = fmaxf(dz * rstd * g4.z + e4.z, 0.f);
    out.w = fmaxf(dw * rstd * g4.w + e4.w, 0.f);
    ((float4*)Z)[n * 32 + lane] = out;
}

// ---------------- gate MLP (4 rows per warp per iter) ----------------
__global__ __launch_bounds__(256) void gate_kernel(const float* __restrict__ Z,
                                                   const float* __restrict__ Wg1,
                                                   const float* __restrict__ bg1,
                                                   const float* __restrict__ Wg2,
                                                   const float* __restrict__ bg2,
                                                   const int* __restrict__ batch) {
    __shared__ float sW1[FD * 64];
    __shared__ float sW2[64];
    __shared__ float sB1[64];
    int tid = threadIdx.x;
    for (int i = tid; i < FD * 64; i += 256) sW1[i] = Wg1[i];
    if (tid < 64) { sW2[tid] = Wg2[tid]; sB1[tid] = bg1[tid]; }
    __syncthreads();

    int warp = (blockIdx.x * 256 + tid) >> 5;
    int nwarps = (gridDim.x * 256) >> 5;
    int lane = tid & 31;
    int j0 = lane * 2;
    const float4* Z4 = (const float4*)Z;
    float bg2v = bg2[0];
    float s2a = sW2[j0], s2b = sW2[j0 + 1];
    float b1a = sB1[j0], b1b = sB1[j0 + 1];

    for (int base = warp * 4; base < NN; base += nwarps * 4) {
        float4 xv[4];
#pragma unroll
        for (int r = 0; r < 4; r++) xv[r] = Z4[(base + r) * 32 + lane];
        unsigned long long acc[4];
#pragma unroll
        for (int r = 0; r < 4; r++) acc[r] = pk2(0.f, 0.f);

#pragma unroll
        for (int kl = 0; kl < 32; kl++) {
            float2 w0 = *(const float2*)&sW1[(kl * 4 + 0) * 64 + j0];
            float2 w1 = *(const float2*)&sW1[(kl * 4 + 1) * 64 + j0];
            float2 w2 = *(const float2*)&sW1[(kl * 4 + 2) * 64 + j0];
            float2 w3 = *(const float2*)&sW1[(kl * 4 + 3) * 64 + j0];
            unsigned long long p0 = pk2(w0.x, w0.y), p1 = pk2(w1.x, w1.y);
            unsigned long long p2 = pk2(w2.x, w2.y), p3 = pk2(w3.x, w3.y);
#pragma unroll
            for (int r = 0; r < 4; r++) {
                float b0 = __shfl_sync(0xffffffffu, xv[r].x, kl);
                float b1 = __shfl_sync(0xffffffffu, xv[r].y, kl);
                float b2 = __shfl_sync(0xffffffffu, xv[r].z, kl);
                float b3 = __shfl_sync(0xffffffffu, xv[r].w, kl);
                fma2(acc[r], p0, pk2(b0, b0));
                fma2(acc[r], p1, pk2(b1, b1));
                fma2(acc[r], p2, pk2(b2, b2));
                fma2(acc[r], p3, pk2(b3, b3));
            }
        }
#pragma unroll
        for (int r = 0; r < 4; r++) {
            float h0, h1;
            upk2(acc[r], h0, h1);
            h0 = fmaxf(h0 + b1a, 0.f);
            h1 = fmaxf(h1 + b1b, 0.f);
            float part = h0 * s2a + h1 * s2b;
#pragma unroll
            for (int o = 16; o; o >>= 1) part += __shfl_xor_sync(0xffffffffu, part, o);
            if (lane == 0) {
                float gt = part + bg2v;
                g_gate[base + r] = gt;
                atomicMax(&g_gmaxU[batch[base + r]], fkey(gt));
            }
        }
    }
}

__global__ __launch_bounds__(256) void denom_kernel(const int* __restrict__ batch) {
    int n = blockIdx.x * blockDim.x + threadIdx.x;
    if (n < NN) {
        int b = batch[n];
        float m = fdekey(g_gmaxU[b]);
        atomicAdd(&g_denom[b], expf(g_gate[n] - m));
    }
}

__global__ __launch_bounds__(256) void pooled_kernel(const float* __restrict__ Z,
                                                     const int* __restrict__ batch) {
    const int C = 64;
    int warp = (blockIdx.x * blockDim.x + threadIdx.x) >> 5;
    int lane = threadIdx.x & 31;
    int n0 = warp * C;
    if (n0 >= NN) return;
    int nend = min(n0 + C, NN);
    const float4* Z4 = (const float4*)Z;

    float4 acc = make_float4(0.f, 0.f, 0.f, 0.f);
    int curb = -1;
    float m = 0.f, den = 1.f;
    for (int n = n0; n < nend; n++) {
        int b = batch[n];
        if (b != curb) {
            if (curb >= 0) {
                float* p = &g_pooled[curb * FD + lane * 4];
                atomicAdd(p + 0, acc.x); atomicAdd(p + 1, acc.y);
                atomicAdd(p + 2, acc.z); atomicAdd(p + 3, acc.w);
                acc = make_float4(0.f, 0.f, 0.f, 0.f);
            }
            curb = b;
            m = fdekey(g_gmaxU[b]);
            den = g_denom[b];
        }
        float alpha = expf(g_gate[n] - m) / den;
        float4 z = Z4[n * 32 + lane];
        acc.x += alpha * z.x; acc.y += alpha * z.y;
        acc.z += alpha * z.z; acc.w += alpha * z.w;
    }
    if (curb >= 0) {
        float* p = &g_pooled[curb * FD + lane * 4];
        atomicAdd(p + 0, acc.x); atomicAdd(p + 1, acc.y);
        atomicAdd(p + 2, acc.z); atomicAdd(p + 3, acc.w);
    }
}

__global__ __launch_bounds__(256) void cls_kernel(const float* __restrict__ Wc,
                                                  const float* __restrict__ bc,
                                                  float* __restrict__ out) {
    int t = blockIdx.x * blockDim.x + threadIdx.x;
    if (t < NB * NC) {
        int b = t >> 4, c = t & 15;
        float s = bc[c];
        const float* p = &g_pooled[b * FD];
#pragma unroll 16
        for (int j = 0; j < FD; j++) s += p[j] * Wc[j * NC + c];
        out[t] = s;
    }
}

// ---------------- launch ----------------
extern "C" void kernel_launch(void* const* d_in, const int* in_sizes, int n_in,
                              void* d_out, int out_size) {
    const float* x    = (const float*)d_in[0];
    const int*   ei   = (const int*)d_in[1];
    const int*   batch= (const int*)d_in[2];
    const float* W1   = (const float*)d_in[3];
    const float* b1   = (const float*)d_in[4];
    const float* g1   = (const float*)d_in[5];
    const float* be1  = (const float*)d_in[6];
    const float* W2   = (const float*)d_in[7];
    const float* b2   = (const float*)d_in[8];
    const float* g2   = (const float*)d_in[9];
    const float* be2  = (const float*)d_in[10];
    const float* Wg1  = (const float*)d_in[11];
    const float* bg1  = (const float*)d_in[12];
    const float* Wg2  = (const float*)d_in[13];
    const float* bg2  = (const float*)d_in[14];
    const float* Wc   = (const float*)d_in[15];
    const float* bc   = (const float*)d_in[16];
    float* out = (float*)d_out;

    const int* src = ei;
    const int* dst = ei + NE;

    const int GEMM_SMEM = 2 * 128 * LDSH * (int)sizeof(__half);  // 69632 B

    static cudaStream_t s1 = nullptr;
    static cudaEvent_t evFork = nullptr, evJoin = nullptr;
    static bool attr_done = false;
    if (!attr_done) {
        cudaFuncSetAttribute(gemm_mma_kernel, cudaFuncAttributeMaxDynamicSharedMemorySize,
                             GEMM_SMEM);
        cudaStreamCreateWithFlags(&s1, cudaStreamNonBlocking);
        cudaEventCreateWithFlags(&evFork, cudaEventDisableTiming);
        cudaEventCreateWithFlags(&evJoin, cudaEventDisableTiming);
        attr_done = true;
    }

    __half* h16; cudaGetSymbolAddress((void**)&h16, g_h16);
    float* bufB; cudaGetSymbolAddress((void**)&bufB, g_bufB);

    const int GEMM_GRID = (NN + 127) / 128;  // 782

    // dinv production chain on main stream (gemm now needs dinv for its epilogue)
    init_kernel<<<(NN + 255) / 256, 256>>>();
    deg_kernel<<<(NE + 255) / 256, 256>>>(dst);
    scanA_kernel<<<NPB, 512>>>();

    // fork: GEMM-1 (needs x, W1, dinv) overlaps rest of CSR build
    cudaEventRecord(evFork, 0);
    cudaStreamWaitEvent(s1, evFork, 0);
    gemm_mma_kernel<<<GEMM_GRID, 256, GEMM_SMEM, s1>>>(x, W1, h16);
    cudaEventRecord(evJoin, s1);

    scanB_kernel<<<1, 256>>>();
    scanC_kernel<<<NPB, 512>>>();
    fill_kernel<<<(NE + 255) / 256, 256>>>(src, dst);

    // join: agg1 needs both CSR and GEMM-1 output
    cudaStreamWaitEvent(0, evJoin, 0);
    agg_ln_relu_kernel<<<(NN * 32 + 255) / 256, 256>>>(h16, bufB, b1, g1, be1);
    // layer 2
    gemm_mma_kernel<<<GEMM_GRID, 256, GEMM_SMEM>>>(bufB, W2, h16);
    agg_ln_relu_kernel<<<(NN * 32 + 255) / 256, 256>>>(h16, bufB, b2, g2, be2);

    // attention pooling
    gate_kernel<<<592, 256>>>(bufB, Wg1, bg1, Wg2, bg2, batch);
    denom_kernel<<<(NN + 255) / 256, 256>>>(batch);
    pooled_kernel<<<(((NN + 63) / 64) * 32 + 255) / 256, 256>>>(bufB, batch);

    // classifier
    cls_kernel<<<(NB * NC + 255) / 256, 256>>>(Wc, bc, out);
}

// round 8
// speedup vs baseline: 2.4015x; 1.0206x over previous
#include <cuda_runtime.h>
#include <cuda_fp16.h>
#include <math.h>

#define NN 100000
#define NE 1600000
#define NB 64
#define FD 128
#define NC 16
#define NPB 196  // ceil(NN/512) scan blocks
#define LDSH 136 // padded smem leading dim (halves) for conflict-free ldmatrix

// ---------------- scratch (device globals; no allocations) ----------------
__device__ __half   g_h16[NN * FD];   // fp16 scaled intermediate h~ = dinv * (X@W)
__device__ float    g_bufB[NN * FD];  // fp32 Z = relu(LN(agg))
__device__ float    g_dinv[NN];
__device__ int      g_indeg[NN];
__device__ int      g_ctr[NN];
__device__ int      g_rowptr[NN + 1];
__device__ int      g_part[NPB];
__device__ int      g_partoff[NPB];
__device__ int      g_esrc[NE];
__device__ float    g_gate[NN];
__device__ unsigned g_gmaxU[NB];
__device__ float    g_denom[NB];
__device__ float    g_pooled[NB * FD];

// ---------------- helpers ----------------
__device__ __forceinline__ unsigned long long pk2(float lo, float hi) {
    unsigned long long r;
    asm("mov.b64 %0, {%1,%2};" : "=l"(r) : "f"(lo), "f"(hi));
    return r;
}
__device__ __forceinline__ void upk2(unsigned long long v, float& lo, float& hi) {
    asm("mov.b64 {%0,%1}, %2;" : "=f"(lo), "=f"(hi) : "l"(v));
}
__device__ __forceinline__ void fma2(unsigned long long& acc, unsigned long long a,
                                     unsigned long long b) {
    asm("fma.rn.f32x2 %0, %1, %2, %0;" : "+l"(acc) : "l"(a), "l"(b));
}
__device__ __forceinline__ unsigned fkey(float f) {
    unsigned u = __float_as_uint(f);
    return (u & 0x80000000u) ? ~u : (u | 0x80000000u);
}
__device__ __forceinline__ float fdekey(unsigned k) {
    unsigned u = (k & 0x80000000u) ? (k ^ 0x80000000u) : ~k;
    return __uint_as_float(u);
}

// ---------------- setup kernels ----------------
__global__ __launch_bounds__(256) void init_kernel() {
    int i = blockIdx.x * blockDim.x + threadIdx.x;
    if (i < NN) { g_indeg[i] = 0; g_ctr[i] = 0; }
    if (i < NB * FD) g_pooled[i] = 0.f;
    if (i < NB) { g_denom[i] = 0.f; g_gmaxU[i] = 0x007FFFFFu; /* key(-inf) */ }
    if (i == 0) g_rowptr[NN] = NE;
}

__global__ __launch_bounds__(256) void deg_kernel(const int* __restrict__ dst) {
    int e = blockIdx.x * blockDim.x + threadIdx.x;
    if (e < NE) atomicAdd(&g_indeg[dst[e]], 1);
}

__global__ __launch_bounds__(512) void scanA_kernel() {
    int t = threadIdx.x, b = blockIdx.x;
    int idx = b * 512 + t;
    int v = (idx < NN) ? g_indeg[idx] : 0;
    if (idx < NN) g_dinv[idx] = rsqrtf((float)(v + 1));
    int x = v;
#pragma unroll
    for (int o = 16; o; o >>= 1) x += __shfl_xor_sync(0xffffffffu, x, o);
    __shared__ int wsum[16];
    int lane = t & 31, wid = t >> 5;
    if (lane == 0) wsum[wid] = x;
    __syncthreads();
    if (t == 0) {
        int s = 0;
#pragma unroll
        for (int w = 0; w < 16; w++) s += wsum[w];
        g_part[b] = s;
    }
}

__global__ __launch_bounds__(256) void scanB_kernel() {
    int t = threadIdx.x;
    int v = (t < NPB) ? g_part[t] : 0;
    int lane = t & 31, wid = t >> 5;
    int x = v;
#pragma unroll
    for (int o = 1; o < 32; o <<= 1) {
        int y = __shfl_up_sync(0xffffffffu, x, o);
        if (lane >= o) x += y;
    }
    __shared__ int wsum[8];
    if (lane == 31) wsum[wid] = x;
    __syncthreads();
    if (wid == 0) {
        int s = (lane < 8) ? wsum[lane] : 0;
#pragma unroll
        for (int o = 1; o < 8; o <<= 1) {
            int y = __shfl_up_sync(0xffffffffu, s, o);
            if (lane >= o) s += y;
        }
        if (lane < 8) wsum[lane] = s;
    }
    __syncthreads();
    int excl = x - v + (wid > 0 ? wsum[wid - 1] : 0);
    if (t < NPB) g_partoff[t] = excl;
}

__global__ __launch_bounds__(512) void scanC_kernel() {
    int t = threadIdx.x, b = blockIdx.x;
    int idx = b * 512 + t;
    int v = (idx < NN) ? g_indeg[idx] : 0;
    int lane = t & 31, wid = t >> 5;
    int x = v;
#pragma unroll
    for (int o = 1; o < 32; o <<= 1) {
        int y = __shfl_up_sync(0xffffffffu, x, o);
        if (lane >= o) x += y;
    }
    __shared__ int wsum[16];
    if (lane == 31) wsum[wid] = x;
    __syncthreads();
    if (wid == 0) {
        int s = (lane < 16) ? wsum[lane] : 0;
#pragma unroll
        for (int o = 1; o < 16; o <<= 1) {
            int y = __shfl_up_sync(0xffffffffu, s, o);
            if (lane >= o) s += y;
        }
        if (lane < 16) wsum[lane] = s;
    }
    __syncthreads();
    int excl = x - v + (wid > 0 ? wsum[wid - 1] : 0);
    if (idx < NN) g_rowptr[idx] = g_partoff[b] + excl;
}

__global__ __launch_bounds__(256) void fill_kernel(const int* __restrict__ src,
                                                   const int* __restrict__ dst) {
    int e = blockIdx.x * blockDim.x + threadIdx.x;
    if (e < NE) {
        int d = dst[e];
        int p = g_rowptr[d] + atomicAdd(&g_ctr[d], 1);
        g_esrc[p] = src[e];
    }
}

// ---------------- GEMM: H~ = dinv * (X @ W) (tensor cores) ----------------
// block = 256 thr (8 warps), tile m64 x n128 x k128.
// warps: 4 m-warps x 2 n-warps; warp tile m16 x n64.
__global__ __launch_bounds__(256, 3) void gemm_mma_kernel(const float* __restrict__ X,
                                                          const float* __restrict__ W,
                                                          __half* __restrict__ Y) {
    extern __shared__ __half smemh[];
    __half* sB = smemh;              // [128][LDSH] W: row=k, col=n
    __half* sA = smemh + 128 * LDSH; // [64][LDSH]
    int tid = threadIdx.x;
    int m0 = blockIdx.x * 64;

    {
        const float4* W4 = (const float4*)W;
        for (int i = tid; i < 128 * 32; i += 256) {
            int row = i >> 5, j = i & 31;
            float4 v = W4[i];
            *(__half2*)&sB[row * LDSH + j * 4]     = __floats2half2_rn(v.x, v.y);
            *(__half2*)&sB[row * LDSH + j * 4 + 2] = __floats2half2_rn(v.z, v.w);
        }
    }
    {
        const float4* X4 = (const float4*)X;
        for (int i = tid; i < 64 * 32; i += 256) {
            int row = i >> 5, j = i & 31;
            int gr = m0 + row;
            float4 v = (gr < NN) ? X4[gr * 32 + j] : make_float4(0.f, 0.f, 0.f, 0.f);
            *(__half2*)&sA[row * LDSH + j * 4]     = __floats2half2_rn(v.x, v.y);
            *(__half2*)&sA[row * LDSH + j * 4 + 2] = __floats2half2_rn(v.z, v.w);
        }
    }
    __syncthreads();

    int warp = tid >> 5, lane = tid & 31;
    int wm = warp >> 1;          // 0..3
    int wn = warp & 1;           // 0..1
    int mrow = wm * 16;
    int ncol0 = wn * 64;

    float acc[8][4];
#pragma unroll
    for (int nt = 0; nt < 8; nt++)
        acc[nt][0] = acc[nt][1] = acc[nt][2] = acc[nt][3] = 0.f;

#pragma unroll
    for (int k0 = 0; k0 < 128; k0 += 16) {
        unsigned a0, a1, a2, a3;
        {
            int arow = mrow + (lane & 15);
            int acol = k0 + ((lane >> 4) << 3);
            unsigned aaddr = (unsigned)__cvta_generic_to_shared(&sA[arow * LDSH + acol]);
            asm volatile("ldmatrix.sync.aligned.m8n8.x4.shared.b16 {%0,%1,%2,%3}, [%4];"
                         : "=r"(a0), "=r"(a1), "=r"(a2), "=r"(a3) : "r"(aaddr));
        }
#pragma unroll
        for (int np = 0; np < 4; np++) {  // each x4.trans covers n16 (2 n-tiles)
            unsigned b0, b1, b2, b3;
            unsigned baddr = (unsigned)__cvta_generic_to_shared(
                &sB[(k0 + (lane & 15)) * LDSH + ncol0 + np * 16 + ((lane >> 4) << 3)]);
            asm volatile("ldmatrix.sync.aligned.m8n8.x4.trans.shared.b16 {%0,%1,%2,%3}, [%4];"
                         : "=r"(b0), "=r"(b1), "=r"(b2), "=r"(b3) : "r"(baddr));
            asm volatile(
                "mma.sync.aligned.m16n8k16.row.col.f32.f16.f16.f32 "
                "{%0,%1,%2,%3}, {%4,%5,%6,%7}, {%8,%9}, {%0,%1,%2,%3};"
                : "+f"(acc[np * 2][0]), "+f"(acc[np * 2][1]),
                  "+f"(acc[np * 2][2]), "+f"(acc[np * 2][3])
                : "r"(a0), "r"(a1), "r"(a2), "r"(a3), "r"(b0), "r"(b1));
            asm volatile(
                "mma.sync.aligned.m16n8k16.row.col.f32.f16.f16.f32 "
                "{%0,%1,%2,%3}, {%4,%5,%6,%7}, {%8,%9}, {%0,%1,%2,%3};"
                : "+f"(acc[np * 2 + 1][0]), "+f"(acc[np * 2 + 1][1]),
                  "+f"(acc[np * 2 + 1][2]), "+f"(acc[np * 2 + 1][3])
                : "r"(a0), "r"(a1), "r"(a2), "r"(a3), "r"(b2), "r"(b3));
        }
    }

    int r = lane >> 2, c = (lane & 3) * 2;
    int gr0 = m0 + mrow + r;
    int gr1 = gr0 + 8;
    float d0 = (gr0 < NN) ? g_dinv[gr0] : 0.f;
    float d1 = (gr1 < NN) ? g_dinv[gr1] : 0.f;
#pragma unroll
    for (int nt = 0; nt < 8; nt++) {
        int col = ncol0 + nt * 8 + c;
        if (gr0 < NN)
            *(__half2*)&Y[gr0 * FD + col] = __floats2half2_rn(acc[nt][0] * d0, acc[nt][1] * d0);
        if (gr1 < NN)
            *(__half2*)&Y[gr1 * FD + col] = __floats2half2_rn(acc[nt][2] * d1, acc[nt][3] * d1);
    }
}

// ---------------- per-node CSR aggregation (pre-scaled fp16 gathers) + bias + LN + ReLU ----------------
__global__ __launch_bounds__(256) void agg_ln_relu_kernel(const __half* __restrict__ H,
                                                          float* __restrict__ Z,
                                                          const float* __restrict__ bias,
                                                          const float* __restrict__ gam,
                                                          const float* __restrict__ bet) {
    int gw = (blockIdx.x * blockDim.x + threadIdx.x) >> 5;
    if (gw >= NN) return;
    int lane = threadIdx.x & 31;
    int n = gw;
    int r0 = g_rowptr[n], r1 = g_rowptr[n + 1];
    float dn = g_dinv[n];
    const uint2* H2 = (const uint2*)H;

    uint2 sv = H2[n * 32 + lane];
    float2 sf0 = __half22float2(*(__half2*)&sv.x);
    float2 sf1 = __half22float2(*(__half2*)&sv.y);
    float4 acc = make_float4(sf0.x, sf0.y, sf1.x, sf1.y);

    int i = r0;
    for (; i + 8 <= r1; i += 8) {
        uint2 v0 = H2[g_esrc[i]     * 32 + lane];
        uint2 v1 = H2[g_esrc[i + 1] * 32 + lane];
        uint2 v2 = H2[g_esrc[i + 2] * 32 + lane];
        uint2 v3 = H2[g_esrc[i + 3] * 32 + lane];
        uint2 v4 = H2[g_esrc[i + 4] * 32 + lane];
        uint2 v5 = H2[g_esrc[i + 5] * 32 + lane];
        uint2 v6 = H2[g_esrc[i + 6] * 32 + lane];
        uint2 v7 = H2[g_esrc[i + 7] * 32 + lane];
#define ACC8(v)                                                      \
        {                                                            \
            float2 fa = __half22float2(*(__half2*)&(v).x);           \
            float2 fb = __half22float2(*(__half2*)&(v).y);           \
            acc.x += fa.x; acc.y += fa.y; acc.z += fb.x; acc.w += fb.y; \
        }
        ACC8(v0) ACC8(v1) ACC8(v2) ACC8(v3) ACC8(v4) ACC8(v5) ACC8(v6) ACC8(v7)
    }
    for (; i < r1; i++) {
        uint2 v = H2[g_esrc[i] * 32 + lane];
        ACC8(v)
    }
#undef ACC8

    const float4* b4p = (const float4*)bias;
    float4 b4 = b4p[lane];
    acc.x = acc.x * dn + b4.x;
    acc.y = acc.y * dn + b4.y;
    acc.z = acc.z * dn + b4.z;
    acc.w = acc.w * dn + b4.w;

    float s = acc.x + acc.y + acc.z + acc.w;
#pragma unroll
    for (int o = 16; o; o >>= 1) s += __shfl_xor_sync(0xffffffffu, s, o);
    float mean = s * (1.0f / FD);
    float dx = acc.x - mean, dy = acc.y - mean, dz = acc.z - mean, dw = acc.w - mean;
    float ss = dx * dx + dy * dy + dz * dz + dw * dw;
#pragma unroll
    for (int o = 16; o; o >>= 1) ss += __shfl_xor_sync(0xffffffffu, ss, o);
    float rstd = rsqrtf(ss * (1.0f / FD) + 1e-5f);

    const float4* g4p = (const float4*)gam;
    const float4* e4p = (const float4*)bet;
    float4 g4 = g4p[lane], e4 = e4p[lane];
    float4 out;
    out.x = fmaxf(dx * rstd * g4.x + e4.x, 0.f);
    out.y = fmaxf(dy * rstd * g4.y + e4.y, 0.f);
    out.z = fmaxf(dz * rstd * g4.z + e4.z, 0.f);
    out.w = fmaxf(dw * rstd * g4.w + e4.w, 0.f);
    ((float4*)Z)[n * 32 + lane] = out;
}

// ---------------- gate MLP (4 rows per warp per iter) ----------------
__global__ __launch_bounds__(256) void gate_kernel(const float* __restrict__ Z,
                                                   const float* __restrict__ Wg1,
                                                   const float* __restrict__ bg1,
                                                   const float* __restrict__ Wg2,
                                                   const float* __restrict__ bg2,
                                                   const int* __restrict__ batch) {
    __shared__ float sW1[FD * 64];
    __shared__ float sW2[64];
    __shared__ float sB1[64];
    int tid = threadIdx.x;
    for (int i = tid; i < FD * 64; i += 256) sW1[i] = Wg1[i];
    if (tid < 64) { sW2[tid] = Wg2[tid]; sB1[tid] = bg1[tid]; }
    __syncthreads();

    int warp = (blockIdx.x * 256 + tid) >> 5;
    int nwarps = (gridDim.x * 256) >> 5;
    int lane = tid & 31;
    int j0 = lane * 2;
    const float4* Z4 = (const float4*)Z;
    float bg2v = bg2[0];
    float s2a = sW2[j0], s2b = sW2[j0 + 1];
    float b1a = sB1[j0], b1b = sB1[j0 + 1];

    for (int base = warp * 4; base < NN; base += nwarps * 4) {
        float4 xv[4];
#pragma unroll
        for (int r = 0; r < 4; r++) xv[r] = Z4[(base + r) * 32 + lane];
        unsigned long long acc[4];
#pragma unroll
        for (int r = 0; r < 4; r++) acc[r] = pk2(0.f, 0.f);

#pragma unroll
        for (int kl = 0; kl < 32; kl++) {
            float2 w0 = *(const float2*)&sW1[(kl * 4 + 0) * 64 + j0];
            float2 w1 = *(const float2*)&sW1[(kl * 4 + 1) * 64 + j0];
            float2 w2 = *(const float2*)&sW1[(kl * 4 + 2) * 64 + j0];
            float2 w3 = *(const float2*)&sW1[(kl * 4 + 3) * 64 + j0];
            unsigned long long p0 = pk2(w0.x, w0.y), p1 = pk2(w1.x, w1.y);
            unsigned long long p2 = pk2(w2.x, w2.y), p3 = pk2(w3.x, w3.y);
#pragma unroll
            for (int r = 0; r < 4; r++) {
                float b0 = __shfl_sync(0xffffffffu, xv[r].x, kl);
                float b1 = __shfl_sync(0xffffffffu, xv[r].y, kl);
                float b2 = __shfl_sync(0xffffffffu, xv[r].z, kl);
                float b3 = __shfl_sync(0xffffffffu, xv[r].w, kl);
                fma2(acc[r], p0, pk2(b0, b0));
                fma2(acc[r], p1, pk2(b1, b1));
                fma2(acc[r], p2, pk2(b2, b2));
                fma2(acc[r], p3, pk2(b3, b3));
            }
        }
#pragma unroll
        for (int r = 0; r < 4; r++) {
            float h0, h1;
            upk2(acc[r], h0, h1);
            h0 = fmaxf(h0 + b1a, 0.f);
            h1 = fmaxf(h1 + b1b, 0.f);
            float part = h0 * s2a + h1 * s2b;
#pragma unroll
            for (int o = 16; o; o >>= 1) part += __shfl_xor_sync(0xffffffffu, part, o);
            if (lane == 0) {
                float gt = part + bg2v;
                g_gate[base + r] = gt;
                atomicMax(&g_gmaxU[batch[base + r]], fkey(gt));
            }
        }
    }
}

__global__ __launch_bounds__(256) void denom_kernel(const int* __restrict__ batch) {
    int n = blockIdx.x * blockDim.x + threadIdx.x;
    if (n < NN) {
        int b = batch[n];
        float m = fdekey(g_gmaxU[b]);
        atomicAdd(&g_denom[b], expf(g_gate[n] - m));
    }
}

__global__ __launch_bounds__(256) void pooled_kernel(const float* __restrict__ Z,
                                                     const int* __restrict__ batch) {
    const int C = 64;
    int warp = (blockIdx.x * blockDim.x + threadIdx.x) >> 5;
    int lane = threadIdx.x & 31;
    int n0 = warp * C;
    if (n0 >= NN) return;
    int nend = min(n0 + C, NN);
    const float4* Z4 = (const float4*)Z;

    float4 acc = make_float4(0.f, 0.f, 0.f, 0.f);
    int curb = -1;
    float m = 0.f, den = 1.f;
    for (int n = n0; n < nend; n++) {
        int b = batch[n];
        if (b != curb) {
            if (curb >= 0) {
                float* p = &g_pooled[curb * FD + lane * 4];
                atomicAdd(p + 0, acc.x); atomicAdd(p + 1, acc.y);
                atomicAdd(p + 2, acc.z); atomicAdd(p + 3, acc.w);
                acc = make_float4(0.f, 0.f, 0.f, 0.f);
            }
            curb = b;
            m = fdekey(g_gmaxU[b]);
            den = g_denom[b];
        }
        float alpha = expf(g_gate[n] - m) / den;
        float4 z = Z4[n * 32 + lane];
        acc.x += alpha * z.x; acc.y += alpha * z.y;
        acc.z += alpha * z.z; acc.w += alpha * z.w;
    }
    if (curb >= 0) {
        float* p = &g_pooled[curb * FD + lane * 4];
        atomicAdd(p + 0, acc.x); atomicAdd(p + 1, acc.y);
        atomicAdd(p + 2, acc.z); atomicAdd(p + 3, acc.w);
    }
}

__global__ __launch_bounds__(256) void cls_kernel(const float* __restrict__ Wc,
                                                  const float* __restrict__ bc,
                                                  float* __restrict__ out) {
    int t = blockIdx.x * blockDim.x + threadIdx.x;
    if (t < NB * NC) {
        int b = t >> 4, c = t & 15;
        float s = bc[c];
        const float* p = &g_pooled[b * FD];
#pragma unroll 16
        for (int j = 0; j < FD; j++) s += p[j] * Wc[j * NC + c];
        out[t] = s;
    }
}

// ---------------- launch ----------------
extern "C" void kernel_launch(void* const* d_in, const int* in_sizes, int n_in,
                              void* d_out, int out_size) {
    const float* x    = (const float*)d_in[0];
    const int*   ei   = (const int*)d_in[1];
    const int*   batch= (const int*)d_in[2];
    const float* W1   = (const float*)d_in[3];
    const float* b1   = (const float*)d_in[4];
    const float* g1   = (const float*)d_in[5];
    const float* be1  = (const float*)d_in[6];
    const float* W2   = (const float*)d_in[7];
    const float* b2   = (const float*)d_in[8];
    const float* g2   = (const float*)d_in[9];
    const float* be2  = (const float*)d_in[10];
    const float* Wg1  = (const float*)d_in[11];
    const float* bg1  = (const float*)d_in[12];
    const float* Wg2  = (const float*)d_in[13];
    const float* bg2  = (const float*)d_in[14];
    const float* Wc   = (const float*)d_in[15];
    const float* bc   = (const float*)d_in[16];
    float* out = (float*)d_out;

    const int* src = ei;
    const int* dst = ei + NE;

    const int GEMM_SMEM = (128 + 64) * LDSH * (int)sizeof(__half);  // 52224 B

    static cudaStream_t s1 = nullptr;
    static cudaEvent_t evFork = nullptr, evJoin = nullptr;
    static bool attr_done = false;
    if (!attr_done) {
        cudaFuncSetAttribute(gemm_mma_kernel, cudaFuncAttributeMaxDynamicSharedMemorySize,
                             GEMM_SMEM);
        cudaStreamCreateWithFlags(&s1, cudaStreamNonBlocking);
        cudaEventCreateWithFlags(&evFork, cudaEventDisableTiming);
        cudaEventCreateWithFlags(&evJoin, cudaEventDisableTiming);
        attr_done = true;
    }

    __half* h16; cudaGetSymbolAddress((void**)&h16, g_h16);
    float* bufB; cudaGetSymbolAddress((void**)&bufB, g_bufB);

    const int GEMM_GRID = (NN + 63) / 64;  // 1563

    // dinv production chain on main stream (gemm epilogue needs dinv)
    init_kernel<<<(NN + 255) / 256, 256>>>();
    deg_kernel<<<(NE + 255) / 256, 256>>>(dst);
    scanA_kernel<<<NPB, 512>>>();

    // fork: GEMM-1 (needs x, W1, dinv) overlaps rest of CSR build
    cudaEventRecord(evFork, 0);
    cudaStreamWaitEvent(s1, evFork, 0);
    gemm_mma_kernel<<<GEMM_GRID, 256, GEMM_SMEM, s1>>>(x, W1, h16);
    cudaEventRecord(evJoin, s1);

    scanB_kernel<<<1, 256>>>();
    scanC_kernel<<<NPB, 512>>>();
    fill_kernel<<<(NE + 255) / 256, 256>>>(src, dst);

    // join: agg1 needs both CSR and GEMM-1 output
    cudaStreamWaitEvent(0, evJoin, 0);
    agg_ln_relu_kernel<<<(NN * 32 + 255) / 256, 256>>>(h16, bufB, b1, g1, be1);
    // layer 2
    gemm_mma_kernel<<<GEMM_GRID, 256, GEMM_SMEM>>>(bufB, W2, h16);
    agg_ln_relu_kernel<<<(NN * 32 + 255) / 256, 256>>>(h16, bufB, b2, g2, be2);

    // attention pooling
    gate_kernel<<<592, 256>>>(bufB, Wg1, bg1, Wg2, bg2, batch);
    denom_kernel<<<(NN + 255) / 256, 256>>>(batch);
    pooled_kernel<<<(((NN + 63) / 64) * 32 + 255) / 256, 256>>>(bufB, batch);

    // classifier
    cls_kernel<<<(NB * NC + 255) / 256, 256>>>(Wc, bc, out);
}

// round 9
// speedup vs baseline: 2.6461x; 1.1019x over previous
#include <cuda_runtime.h>
#include <cuda_fp16.h>
#include <math.h>

#define NN 100000
#define NE 1600000
#define NB 64
#define FD 128
#define NC 16
#define NPB 196  // ceil(NN/512) scan blocks
#define LDSH 136 // padded smem leading dim (halves) for conflict-free ldmatrix

// ---------------- scratch (device globals; no allocations) ----------------
__device__ __half   g_h16[NN * FD];   // fp16 scaled intermediate h~ = dinv * (X@W)
__device__ float    g_bufB[NN * FD];  // fp32 Z = relu(LN(agg))
__device__ __half   g_W16a[FD * FD];  // W1 in fp16
__device__ __half   g_W16b[FD * FD];  // W2 in fp16
__device__ float    g_dinv[NN];
__device__ int      g_indeg[NN];
__device__ int      g_ctr[NN];
__device__ int      g_rowptr[NN + 1];
__device__ int      g_part[NPB];
__device__ int      g_partoff[NPB];
__device__ int      g_esrc[NE];
__device__ float    g_gate[NN];
__device__ unsigned g_gmaxU[NB];
__device__ float    g_denom[NB];
__device__ float    g_pooled[NB * FD];

// ---------------- helpers ----------------
__device__ __forceinline__ unsigned long long pk2(float lo, float hi) {
    unsigned long long r;
    asm("mov.b64 %0, {%1,%2};" : "=l"(r) : "f"(lo), "f"(hi));
    return r;
}
__device__ __forceinline__ void upk2(unsigned long long v, float& lo, float& hi) {
    asm("mov.b64 {%0,%1}, %2;" : "=f"(lo), "=f"(hi) : "l"(v));
}
__device__ __forceinline__ void fma2(unsigned long long& acc, unsigned long long a,
                                     unsigned long long b) {
    asm("fma.rn.f32x2 %0, %1, %2, %0;" : "+l"(acc) : "l"(a), "l"(b));
}
__device__ __forceinline__ unsigned fkey(float f) {
    unsigned u = __float_as_uint(f);
    return (u & 0x80000000u) ? ~u : (u | 0x80000000u);
}
__device__ __forceinline__ float fdekey(unsigned k) {
    unsigned u = (k & 0x80000000u) ? (k ^ 0x80000000u) : ~k;
    return __uint_as_float(u);
}

// ---------------- setup kernels ----------------
__global__ __launch_bounds__(256) void init_kernel() {
    int i = blockIdx.x * blockDim.x + threadIdx.x;
    if (i < NN) { g_indeg[i] = 0; g_ctr[i] = 0; }
    if (i < NB * FD) g_pooled[i] = 0.f;
    if (i < NB) { g_denom[i] = 0.f; g_gmaxU[i] = 0x007FFFFFu; /* key(-inf) */ }
    if (i == 0) g_rowptr[NN] = NE;
}

__global__ __launch_bounds__(256) void w16_kernel(const float* __restrict__ W,
                                                  __half* __restrict__ O) {
    int i = blockIdx.x * 256 + threadIdx.x;  // FD*FD/2 = 8192 half2
    if (i < FD * FD / 2) {
        float2 v = ((const float2*)W)[i];
        ((__half2*)O)[i] = __floats2half2_rn(v.x, v.y);
    }
}

__global__ __launch_bounds__(256) void deg_kernel(const int* __restrict__ dst) {
    int e = blockIdx.x * blockDim.x + threadIdx.x;
    if (e < NE) atomicAdd(&g_indeg[dst[e]], 1);
}

__global__ __launch_bounds__(512) void scanA_kernel() {
    int t = threadIdx.x, b = blockIdx.x;
    int idx = b * 512 + t;
    int v = (idx < NN) ? g_indeg[idx] : 0;
    if (idx < NN) g_dinv[idx] = rsqrtf((float)(v + 1));
    int x = v;
#pragma unroll
    for (int o = 16; o; o >>= 1) x += __shfl_xor_sync(0xffffffffu, x, o);
    __shared__ int wsum[16];
    int lane = t & 31, wid = t >> 5;
    if (lane == 0) wsum[wid] = x;
    __syncthreads();
    if (t == 0) {
        int s = 0;
#pragma unroll
        for (int w = 0; w < 16; w++) s += wsum[w];
        g_part[b] = s;
    }
}

__global__ __launch_bounds__(256) void scanB_kernel() {
    int t = threadIdx.x;
    int v = (t < NPB) ? g_part[t] : 0;
    int lane = t & 31, wid = t >> 5;
    int x = v;
#pragma unroll
    for (int o = 1; o < 32; o <<= 1) {
        int y = __shfl_up_sync(0xffffffffu, x, o);
        if (lane >= o) x += y;
    }
    __shared__ int wsum[8];
    if (lane == 31) wsum[wid] = x;
    __syncthreads();
    if (wid == 0) {
        int s = (lane < 8) ? wsum[lane] : 0;
#pragma unroll
        for (int o = 1; o < 8; o <<= 1) {
            int y = __shfl_up_sync(0xffffffffu, s, o);
            if (lane >= o) s += y;
        }
        if (lane < 8) wsum[lane] = s;
    }
    __syncthreads();
    int excl = x - v + (wid > 0 ? wsum[wid - 1] : 0);
    if (t < NPB) g_partoff[t] = excl;
}

__global__ __launch_bounds__(512) void scanC_kernel() {
    int t = threadIdx.x, b = blockIdx.x;
    int idx = b * 512 + t;
    int v = (idx < NN) ? g_indeg[idx] : 0;
    int lane = t & 31, wid = t >> 5;
    int x = v;
#pragma unroll
    for (int o = 1; o < 32; o <<= 1) {
        int y = __shfl_up_sync(0xffffffffu, x, o);
        if (lane >= o) x += y;
    }
    __shared__ int wsum[16];
    if (lane == 31) wsum[wid] = x;
    __syncthreads();
    if (wid == 0) {
        int s = (lane < 16) ? wsum[lane] : 0;
#pragma unroll
        for (int o = 1; o < 16; o <<= 1) {
            int y = __shfl_up_sync(0xffffffffu, s, o);
            if (lane >= o) s += y;
        }
        if (lane < 16) wsum[lane] = s;
    }
    __syncthreads();
    int excl = x - v + (wid > 0 ? wsum[wid - 1] : 0);
    if (idx < NN) g_rowptr[idx] = g_partoff[b] + excl;
}

__global__ __launch_bounds__(256) void fill_kernel(const int* __restrict__ src,
                                                   const int* __restrict__ dst) {
    int e = blockIdx.x * blockDim.x + threadIdx.x;
    if (e < NE) {
        int d = dst[e];
        int p = g_rowptr[d] + atomicAdd(&g_ctr[d], 1);
        g_esrc[p] = src[e];
    }
}

// ---------------- persistent GEMM: H~ = dinv * (X @ W16) ----------------
// grid 296 (2/SM). Each block: stage fp16 W once, loop m64-tiles with reg-prefetch.
__global__ __launch_bounds__(256, 2) void gemm_pers_kernel(const float* __restrict__ X,
                                                           const __half* __restrict__ W16,
                                                           __half* __restrict__ Y) {
    extern __shared__ __half smemh[];
    __half* sW = smemh;               // [128][LDSH]
    __half* sA = smemh + 128 * LDSH;  // [64][LDSH]
    int tid = threadIdx.x;

    // stage W (fp16, no conversion): 128 rows x 16 uint4
    {
        const uint4* W4 = (const uint4*)W16;
        for (int i = tid; i < 128 * 16; i += 256) {
            int row = i >> 4, j = i & 15;
            *(uint4*)&sW[row * LDSH + j * 8] = W4[i];
        }
    }

    const int nt_total = (NN + 63) >> 6;  // 1563
    const float4* X4 = (const float4*)X;

    int warp = tid >> 5, lane = tid & 31;
    int wm = warp >> 1;   // 0..3
    int wn = warp & 1;    // 0..1
    int mrow = wm * 16;
    int ncol0 = wn * 64;

    // prologue: load first tile into regs
    float4 xreg[8];
    {
        int t = blockIdx.x;
#pragma unroll
        for (int k = 0; k < 8; k++) {
            int i = tid + k * 256;
            int row = i >> 5, j = i & 31;
            int gr = t * 64 + row;
            xreg[k] = (gr < NN) ? X4[gr * 32 + j] : make_float4(0.f, 0.f, 0.f, 0.f);
        }
    }

    for (int t = blockIdx.x; t < nt_total; t += gridDim.x) {
        // convert prefetched regs -> sA
#pragma unroll
        for (int k = 0; k < 8; k++) {
            int i = tid + k * 256;
            int row = i >> 5, j = i & 31;
            *(__half2*)&sA[row * LDSH + j * 4]     = __floats2half2_rn(xreg[k].x, xreg[k].y);
            *(__half2*)&sA[row * LDSH + j * 4 + 2] = __floats2half2_rn(xreg[k].z, xreg[k].w);
        }
        __syncthreads();

        // issue next tile's loads (latency hidden by compute below)
        int tn = t + gridDim.x;
        if (tn < nt_total) {
#pragma unroll
            for (int k = 0; k < 8; k++) {
                int i = tid + k * 256;
                int row = i >> 5, j = i & 31;
                int gr = tn * 64 + row;
                xreg[k] = (gr < NN) ? X4[gr * 32 + j] : make_float4(0.f, 0.f, 0.f, 0.f);
            }
        }

        // compute m64 x n128 from sA x sW
        float acc[8][4];
#pragma unroll
        for (int nt = 0; nt < 8; nt++)
            acc[nt][0] = acc[nt][1] = acc[nt][2] = acc[nt][3] = 0.f;

#pragma unroll
        for (int k0 = 0; k0 < 128; k0 += 16) {
            unsigned a0, a1, a2, a3;
            {
                int arow = mrow + (lane & 15);
                int acol = k0 + ((lane >> 4) << 3);
                unsigned aaddr = (unsigned)__cvta_generic_to_shared(&sA[arow * LDSH + acol]);
                asm volatile("ldmatrix.sync.aligned.m8n8.x4.shared.b16 {%0,%1,%2,%3}, [%4];"
                             : "=r"(a0), "=r"(a1), "=r"(a2), "=r"(a3) : "r"(aaddr));
            }
#pragma unroll
            for (int np = 0; np < 4; np++) {
                unsigned b0, b1, b2, b3;
                unsigned baddr = (unsigned)__cvta_generic_to_shared(
                    &sW[(k0 + (lane & 15)) * LDSH + ncol0 + np * 16 + ((lane >> 4) << 3)]);
                asm volatile("ldmatrix.sync.aligned.m8n8.x4.trans.shared.b16 {%0,%1,%2,%3}, [%4];"
                             : "=r"(b0), "=r"(b1), "=r"(b2), "=r"(b3) : "r"(baddr));
                asm volatile(
                    "mma.sync.aligned.m16n8k16.row.col.f32.f16.f16.f32 "
                    "{%0,%1,%2,%3}, {%4,%5,%6,%7}, {%8,%9}, {%0,%1,%2,%3};"
                    : "+f"(acc[np * 2][0]), "+f"(acc[np * 2][1]),
                      "+f"(acc[np * 2][2]), "+f"(acc[np * 2][3])
                    : "r"(a0), "r"(a1), "r"(a2), "r"(a3), "r"(b0), "r"(b1));
                asm volatile(
                    "mma.sync.aligned.m16n8k16.row.col.f32.f16.f16.f32 "
                    "{%0,%1,%2,%3}, {%4,%5,%6,%7}, {%8,%9}, {%0,%1,%2,%3};"
                    : "+f"(acc[np * 2 + 1][0]), "+f"(acc[np * 2 + 1][1]),
                      "+f"(acc[np * 2 + 1][2]), "+f"(acc[np * 2 + 1][3])
                    : "r"(a0), "r"(a1), "r"(a2), "r"(a3), "r"(b2), "r"(b3));
            }
        }

        // epilogue: scale by dinv and store fp16
        int r = lane >> 2, c = (lane & 3) * 2;
        int gr0 = t * 64 + mrow + r;
        int gr1 = gr0 + 8;
        float d0 = (gr0 < NN) ? g_dinv[gr0] : 0.f;
        float d1 = (gr1 < NN) ? g_dinv[gr1] : 0.f;
#pragma unroll
        for (int nt = 0; nt < 8; nt++) {
            int col = ncol0 + nt * 8 + c;
            if (gr0 < NN)
                *(__half2*)&Y[gr0 * FD + col] =
                    __floats2half2_rn(acc[nt][0] * d0, acc[nt][1] * d0);
            if (gr1 < NN)
                *(__half2*)&Y[gr1 * FD + col] =
                    __floats2half2_rn(acc[nt][2] * d1, acc[nt][3] * d1);
        }
        __syncthreads();  // sA reuse next iteration
    }
}

// ---------------- per-node CSR aggregation (pre-scaled fp16 gathers) + bias + LN + ReLU ----------------
__global__ __launch_bounds__(256) void agg_ln_relu_kernel(const __half* __restrict__ H,
                                                          float* __restrict__ Z,
                                                          const float* __restrict__ bias,
                                                          const float* __restrict__ gam,
                                                          const float* __restrict__ bet) {
    int gw = (blockIdx.x * blockDim.x + threadIdx.x) >> 5;
    if (gw >= NN) return;
    int lane = threadIdx.x & 31;
    int n = gw;
    int r0 = g_rowptr[n], r1 = g_rowptr[n + 1];
    float dn = g_dinv[n];
    const uint2* H2 = (const uint2*)H;

    uint2 sv = H2[n * 32 + lane];
    float2 sf0 = __half22float2(*(__half2*)&sv.x);
    float2 sf1 = __half22float2(*(__half2*)&sv.y);
    float4 acc = make_float4(sf0.x, sf0.y, sf1.x, sf1.y);

    int i = r0;
    for (; i + 8 <= r1; i += 8) {
        uint2 v0 = H2[g_esrc[i]     * 32 + lane];
        uint2 v1 = H2[g_esrc[i + 1] * 32 + lane];
        uint2 v2 = H2[g_esrc[i + 2] * 32 + lane];
        uint2 v3 = H2[g_esrc[i + 3] * 32 + lane];
        uint2 v4 = H2[g_esrc[i + 4] * 32 + lane];
        uint2 v5 = H2[g_esrc[i + 5] * 32 + lane];
        uint2 v6 = H2[g_esrc[i + 6] * 32 + lane];
        uint2 v7 = H2[g_esrc[i + 7] * 32 + lane];
#define ACC8(v)                                                      \
        {                                                            \
            float2 fa = __half22float2(*(__half2*)&(v).x);           \
            float2 fb = __half22float2(*(__half2*)&(v).y);           \
            acc.x += fa.x; acc.y += fa.y; acc.z += fb.x; acc.w += fb.y; \
        }
        ACC8(v0) ACC8(v1) ACC8(v2) ACC8(v3) ACC8(v4) ACC8(v5) ACC8(v6) ACC8(v7)
    }
    for (; i < r1; i++) {
        uint2 v = H2[g_esrc[i] * 32 + lane];
        ACC8(v)
    }
#undef ACC8

    const float4* b4p = (const float4*)bias;
    float4 b4 = b4p[lane];
    acc.x = acc.x * dn + b4.x;
    acc.y = acc.y * dn + b4.y;
    acc.z = acc.z * dn + b4.z;
    acc.w = acc.w * dn + b4.w;

    float s = acc.x + acc.y + acc.z + acc.w;
#pragma unroll
    for (int o = 16; o; o >>= 1) s += __shfl_xor_sync(0xffffffffu, s, o);
    float mean = s * (1.0f / FD);
    float dx = acc.x - mean, dy = acc.y - mean, dz = acc.z - mean, dw = acc.w - mean;
    float ss = dx * dx + dy * dy + dz * dz + dw * dw;
#pragma unroll
    for (int o = 16; o; o >>= 1) ss += __shfl_xor_sync(0xffffffffu, ss, o);
    float rstd = rsqrtf(ss * (1.0f / FD) + 1e-5f);

    const float4* g4p = (const float4*)gam;
    const float4* e4p = (const float4*)bet;
    float4 g4 = g4p[lane], e4 = e4p[lane];
    float4 out;
    out.x = fmaxf(dx * rstd * g4.x + e4.x, 0.f);
    out.y = fmaxf(dy * rstd * g4.y + e4.y, 0.f);
    out.z = fmaxf(dz * rstd * g4.z + e4.z, 0.f);
    out.w = fmaxf(dw * rstd * g4.w + e4.w, 0.f);
    ((float4*)Z)[n * 32 + lane] = out;
}

// ---------------- gate MLP (4 rows per warp per iter) ----------------
__global__ __launch_bounds__(256) void gate_kernel(const float* __restrict__ Z,
                                                   const float* __restrict__ Wg1,
                                                   const float* __restrict__ bg1,
                                                   const float* __restrict__ Wg2,
                                                   const float* __restrict__ bg2,
                                                   const int* __restrict__ batch) {
    __shared__ float sW1[FD * 64];
    __shared__ float sW2[64];
    __shared__ float sB1[64];
    int tid = threadIdx.x;
    for (int i = tid; i < FD * 64; i += 256) sW1[i] = Wg1[i];
    if (tid < 64) { sW2[tid] = Wg2[tid]; sB1[tid] = bg1[tid]; }
    __syncthreads();

    int warp = (blockIdx.x * 256 + tid) >> 5;
    int nwarps = (gridDim.x * 256) >> 5;
    int lane = tid & 31;
    int j0 = lane * 2;
    const float4* Z4 = (const float4*)Z;
    float bg2v = bg2[0];
    float s2a = sW2[j0], s2b = sW2[j0 + 1];
    float b1a = sB1[j0], b1b = sB1[j0 + 1];

    for (int base = warp * 4; base < NN; base += nwarps * 4) {
        float4 xv[4];
#pragma unroll
        for (int r = 0; r < 4; r++) xv[r] = Z4[(base + r) * 32 + lane];
        unsigned long long acc[4];
#pragma unroll
        for (int r = 0; r < 4; r++) acc[r] = pk2(0.f, 0.f);

#pragma unroll
        for (int kl = 0; kl < 32; kl++) {
            float2 w0 = *(const float2*)&sW1[(kl * 4 + 0) * 64 + j0];
            float2 w1 = *(const float2*)&sW1[(kl * 4 + 1) * 64 + j0];
            float2 w2 = *(const float2*)&sW1[(kl * 4 + 2) * 64 + j0];
            float2 w3 = *(const float2*)&sW1[(kl * 4 + 3) * 64 + j0];
            unsigned long long p0 = pk2(w0.x, w0.y), p1 = pk2(w1.x, w1.y);
            unsigned long long p2 = pk2(w2.x, w2.y), p3 = pk2(w3.x, w3.y);
#pragma unroll
            for (int r = 0; r < 4; r++) {
                float b0 = __shfl_sync(0xffffffffu, xv[r].x, kl);
                float b1 = __shfl_sync(0xffffffffu, xv[r].y, kl);
                float b2 = __shfl_sync(0xffffffffu, xv[r].z, kl);
                float b3 = __shfl_sync(0xffffffffu, xv[r].w, kl);
                fma2(acc[r], p0, pk2(b0, b0));
                fma2(acc[r], p1, pk2(b1, b1));
                fma2(acc[r], p2, pk2(b2, b2));
                fma2(acc[r], p3, pk2(b3, b3));
            }
        }
#pragma unroll
        for (int r = 0; r < 4; r++) {
            float h0, h1;
            upk2(acc[r], h0, h1);
            h0 = fmaxf(h0 + b1a, 0.f);
            h1 = fmaxf(h1 + b1b, 0.f);
            float part = h0 * s2a + h1 * s2b;
#pragma unroll
            for (int o = 16; o; o >>= 1) part += __shfl_xor_sync(0xffffffffu, part, o);
            if (lane == 0) {
                float gt = part + bg2v;
                g_gate[base + r] = gt;
                atomicMax(&g_gmaxU[batch[base + r]], fkey(gt));
            }
        }
    }
}

__global__ __launch_bounds__(256) void denom_kernel(const int* __restrict__ batch) {
    int n = blockIdx.x * blockDim.x + threadIdx.x;
    if (n < NN) {
        int b = batch[n];
        float m = fdekey(g_gmaxU[b]);
        atomicAdd(&g_denom[b], expf(g_gate[n] - m));
    }
}

__global__ __launch_bounds__(256) void pooled_kernel(const float* __restrict__ Z,
                                                     const int* __restrict__ batch) {
    const int C = 64;
    int warp = (blockIdx.x * blockDim.x + threadIdx.x) >> 5;
    int lane = threadIdx.x & 31;
    int n0 = warp * C;
    if (n0 >= NN) return;
    int nend = min(n0 + C, NN);
    const float4* Z4 = (const float4*)Z;

    float4 acc = make_float4(0.f, 0.f, 0.f, 0.f);
    int curb = -1;
    float m = 0.f, den = 1.f;
    for (int n = n0; n < nend; n++) {
        int b = batch[n];
        if (b != curb) {
            if (curb >= 0) {
                float* p = &g_pooled[curb * FD + lane * 4];
                atomicAdd(p + 0, acc.x); atomicAdd(p + 1, acc.y);
                atomicAdd(p + 2, acc.z); atomicAdd(p + 3, acc.w);
                acc = make_float4(0.f, 0.f, 0.f, 0.f);
            }
            curb = b;
            m = fdekey(g_gmaxU[b]);
            den = g_denom[b];
        }
        float alpha = expf(g_gate[n] - m) / den;
        float4 z = Z4[n * 32 + lane];
        acc.x += alpha * z.x; acc.y += alpha * z.y;
        acc.z += alpha * z.z; acc.w += alpha * z.w;
    }
    if (curb >= 0) {
        float* p = &g_pooled[curb * FD + lane * 4];
        atomicAdd(p + 0, acc.x); atomicAdd(p + 1, acc.y);
        atomicAdd(p + 2, acc.z); atomicAdd(p + 3, acc.w);
    }
}

__global__ __launch_bounds__(256) void cls_kernel(const float* __restrict__ Wc,
                                                  const float* __restrict__ bc,
                                                  float* __restrict__ out) {
    int t = blockIdx.x * blockDim.x + threadIdx.x;
    if (t < NB * NC) {
        int b = t >> 4, c = t & 15;
        float s = bc[c];
        const float* p = &g_pooled[b * FD];
#pragma unroll 16
        for (int j = 0; j < FD; j++) s += p[j] * Wc[j * NC + c];
        out[t] = s;
    }
}

// ---------------- launch ----------------
extern "C" void kernel_launch(void* const* d_in, const int* in_sizes, int n_in,
                              void* d_out, int out_size) {
    const float* x    = (const float*)d_in[0];
    const int*   ei   = (const int*)d_in[1];
    const int*   batch= (const int*)d_in[2];
    const float* W1   = (const float*)d_in[3];
    const float* b1   = (const float*)d_in[4];
    const float* g1   = (const float*)d_in[5];
    const float* be1  = (const float*)d_in[6];
    const float* W2   = (const float*)d_in[7];
    const float* b2   = (const float*)d_in[8];
    const float* g2   = (const float*)d_in[9];
    const float* be2  = (const float*)d_in[10];
    const float* Wg1  = (const float*)d_in[11];
    const float* bg1  = (const float*)d_in[12];
    const float* Wg2  = (const float*)d_in[13];
    const float* bg2  = (const float*)d_in[14];
    const float* Wc   = (const float*)d_in[15];
    const float* bc   = (const float*)d_in[16];
    float* out = (float*)d_out;

    const int* src = ei;
    const int* dst = ei + NE;

    const int GEMM_SMEM = (128 + 64) * LDSH * (int)sizeof(__half);  // 52224 B

    static cudaStream_t s1 = nullptr;
    static cudaEvent_t evFork = nullptr, evDinv = nullptr, evJoin = nullptr;
    static bool attr_done = false;
    if (!attr_done) {
        cudaFuncSetAttribute(gemm_pers_kernel, cudaFuncAttributeMaxDynamicSharedMemorySize,
                             GEMM_SMEM);
        cudaStreamCreateWithFlags(&s1, cudaStreamNonBlocking);
        cudaEventCreateWithFlags(&evFork, cudaEventDisableTiming);
        cudaEventCreateWithFlags(&evDinv, cudaEventDisableTiming);
        cudaEventCreateWithFlags(&evJoin, cudaEventDisableTiming);
        attr_done = true;
    }

    __half* h16;  cudaGetSymbolAddress((void**)&h16, g_h16);
    float*  bufB; cudaGetSymbolAddress((void**)&bufB, g_bufB);
    __half* w16a; cudaGetSymbolAddress((void**)&w16a, g_W16a);
    __half* w16b; cudaGetSymbolAddress((void**)&w16b, g_W16b);

    const int GEMM_GRID = 296;  // 2 blocks/SM persistent

    // fork immediately: W conversions are independent of everything
    cudaEventRecord(evFork, 0);
    cudaStreamWaitEvent(s1, evFork, 0);
    w16_kernel<<<32, 256, 0, s1>>>(W1, w16a);
    w16_kernel<<<32, 256, 0, s1>>>(W2, w16b);

    // dinv production chain on main stream
    init_kernel<<<(NN + 255) / 256, 256>>>();
    deg_kernel<<<(NE + 255) / 256, 256>>>(dst);
    scanA_kernel<<<NPB, 512>>>();
    cudaEventRecord(evDinv, 0);

    // s1: GEMM-1 (needs x, W16a, dinv) overlaps rest of CSR build
    cudaStreamWaitEvent(s1, evDinv, 0);
    gemm_pers_kernel<<<GEMM_GRID, 256, GEMM_SMEM, s1>>>(x, w16a, h16);
    cudaEventRecord(evJoin, s1);

    scanB_kernel<<<1, 256>>>();
    scanC_kernel<<<NPB, 512>>>();
    fill_kernel<<<(NE + 255) / 256, 256>>>(src, dst);

    // join: agg1 needs both CSR and GEMM-1 output
    cudaStreamWaitEvent(0, evJoin, 0);
    agg_ln_relu_kernel<<<(NN * 32 + 255) / 256, 256>>>(h16, bufB, b1, g1, be1);
    // layer 2
    gemm_pers_kernel<<<GEMM_GRID, 256, GEMM_SMEM>>>(bufB, w16b, h16);
    agg_ln_relu_kernel<<<(NN * 32 + 255) / 256, 256>>>(h16, bufB, b2, g2, be2);

    // attention pooling
    gate_kernel<<<592, 256>>>(bufB, Wg1, bg1, Wg2, bg2, batch);
    denom_kernel<<<(NN + 255) / 256, 256>>>(batch);
    pooled_kernel<<<(((NN + 63) / 64) * 32 + 255) / 256, 256>>>(bufB, batch);

    // classifier
    cls_kernel<<<(NB * NC + 255) / 256, 256>>>(Wc, bc, out);
}

// round 10
// speedup vs baseline: 3.2069x; 1.2119x over previous
#include <cuda_runtime.h>
#include <cuda_fp16.h>
#include <math.h>

#define NN 100000
#define NE 1600000
#define NB 64
#define FD 128
#define NC 16
#define NPB 196  // ceil(NN/512) scan blocks
#define LDSH 136 // padded smem leading dim (halves) for conflict-free ldmatrix
#define NCHUNK ((NN + 63) / 64)  // 1563 pooling chunks

// ---------------- scratch (device globals; no allocations) ----------------
__device__ __half   g_h16[NN * FD];   // fp16 scaled intermediate h~ = dinv * (X@W)
__device__ float    g_bufB[NN * FD];  // fp32 Z = relu(LN(agg))
__device__ __half   g_W16a[FD * FD];  // W1 in fp16
__device__ __half   g_W16b[FD * FD];  // W2 in fp16
__device__ float    g_dinv[NN];
__device__ int      g_indeg[NN];
__device__ int      g_ctr[NN];
__device__ int      g_rowptr[NN + 1];
__device__ int      g_part[NPB];
__device__ int      g_partoff[NPB];
__device__ int      g_esrc[NE];
__device__ float    g_denom[NB];
__device__ float    g_pooled[NB * FD];   // unnormalized: sum of exp(gate)*z

// ---------------- helpers ----------------
__device__ __forceinline__ unsigned long long pk2(float lo, float hi) {
    unsigned long long r;
    asm("mov.b64 %0, {%1,%2};" : "=l"(r) : "f"(lo), "f"(hi));
    return r;
}
__device__ __forceinline__ void upk2(unsigned long long v, float& lo, float& hi) {
    asm("mov.b64 {%0,%1}, %2;" : "=f"(lo), "=f"(hi) : "l"(v));
}
__device__ __forceinline__ void fma2(unsigned long long& acc, unsigned long long a,
                                     unsigned long long b) {
    asm("fma.rn.f32x2 %0, %1, %2, %0;" : "+l"(acc) : "l"(a), "l"(b));
}

// ---------------- setup kernels ----------------
__global__ __launch_bounds__(256) void init_kernel() {
    int i = blockIdx.x * blockDim.x + threadIdx.x;
    if (i < NN) { g_indeg[i] = 0; g_ctr[i] = 0; }
    if (i < NB * FD) g_pooled[i] = 0.f;
    if (i < NB) g_denom[i] = 0.f;
    if (i == 0) g_rowptr[NN] = NE;
}

__global__ __launch_bounds__(256) void w16_kernel(const float* __restrict__ W,
                                                  __half* __restrict__ O) {
    int i = blockIdx.x * 256 + threadIdx.x;  // FD*FD/2 = 8192 half2
    if (i < FD * FD / 2) {
        float2 v = ((const float2*)W)[i];
        ((__half2*)O)[i] = __floats2half2_rn(v.x, v.y);
    }
}

__global__ __launch_bounds__(256) void deg_kernel(const int* __restrict__ dst) {
    int e = blockIdx.x * blockDim.x + threadIdx.x;
    if (e < NE) atomicAdd(&g_indeg[dst[e]], 1);
}

__global__ __launch_bounds__(512) void scanA_kernel() {
    int t = threadIdx.x, b = blockIdx.x;
    int idx = b * 512 + t;
    int v = (idx < NN) ? g_indeg[idx] : 0;
    if (idx < NN) g_dinv[idx] = rsqrtf((float)(v + 1));
    int x = v;
#pragma unroll
    for (int o = 16; o; o >>= 1) x += __shfl_xor_sync(0xffffffffu, x, o);
    __shared__ int wsum[16];
    int lane = t & 31, wid = t >> 5;
    if (lane == 0) wsum[wid] = x;
    __syncthreads();
    if (t == 0) {
        int s = 0;
#pragma unroll
        for (int w = 0; w < 16; w++) s += wsum[w];
        g_part[b] = s;
    }
}

__global__ __launch_bounds__(256) void scanB_kernel() {
    int t = threadIdx.x;
    int v = (t < NPB) ? g_part[t] : 0;
    int lane = t & 31, wid = t >> 5;
    int x = v;
#pragma unroll
    for (int o = 1; o < 32; o <<= 1) {
        int y = __shfl_up_sync(0xffffffffu, x, o);
        if (lane >= o) x += y;
    }
    __shared__ int wsum[8];
    if (lane == 31) wsum[wid] = x;
    __syncthreads();
    if (wid == 0) {
        int s = (lane < 8) ? wsum[lane] : 0;
#pragma unroll
        for (int o = 1; o < 8; o <<= 1) {
            int y = __shfl_up_sync(0xffffffffu, s, o);
            if (lane >= o) s += y;
        }
        if (lane < 8) wsum[lane] = s;
    }
    __syncthreads();
    int excl = x - v + (wid > 0 ? wsum[wid - 1] : 0);
    if (t < NPB) g_partoff[t] = excl;
}

__global__ __launch_bounds__(512) void scanC_kernel() {
    int t = threadIdx.x, b = blockIdx.x;
    int idx = b * 512 + t;
    int v = (idx < NN) ? g_indeg[idx] : 0;
    int lane = t & 31, wid = t >> 5;
    int x = v;
#pragma unroll
    for (int o = 1; o < 32; o <<= 1) {
        int y = __shfl_up_sync(0xffffffffu, x, o);
        if (lane >= o) x += y;
    }
    __shared__ int wsum[16];
    if (lane == 31) wsum[wid] = x;
    __syncthreads();
    if (wid == 0) {
        int s = (lane < 16) ? wsum[lane] : 0;
#pragma unroll
        for (int o = 1; o < 16; o <<= 1) {
            int y = __shfl_up_sync(0xffffffffu, s, o);
            if (lane >= o) s += y;
        }
        if (lane < 16) wsum[lane] = s;
    }
    __syncthreads();
    int excl = x - v + (wid > 0 ? wsum[wid - 1] : 0);
    if (idx < NN) g_rowptr[idx] = g_partoff[b] + excl;
}

__global__ __launch_bounds__(256) void fill_kernel(const int* __restrict__ src,
                                                   const int* __restrict__ dst) {
    int e = blockIdx.x * blockDim.x + threadIdx.x;
    if (e < NE) {
        int d = dst[e];
        int p = g_rowptr[d] + atomicAdd(&g_ctr[d], 1);
        g_esrc[p] = src[e];
    }
}

// ---------------- persistent GEMM: H~ = dinv * (X @ W16) ----------------
__global__ __launch_bounds__(256, 2) void gemm_pers_kernel(const float* __restrict__ X,
                                                           const __half* __restrict__ W16,
                                                           __half* __restrict__ Y) {
    extern __shared__ __half smemh[];
    __half* sW = smemh;               // [128][LDSH]
    __half* sA = smemh + 128 * LDSH;  // [64][LDSH]
    int tid = threadIdx.x;

    {
        const uint4* W4 = (const uint4*)W16;
        for (int i = tid; i < 128 * 16; i += 256) {
            int row = i >> 4, j = i & 15;
            *(uint4*)&sW[row * LDSH + j * 8] = W4[i];
        }
    }

    const int nt_total = (NN + 63) >> 6;  // 1563
    const float4* X4 = (const float4*)X;

    int warp = tid >> 5, lane = tid & 31;
    int wm = warp >> 1;
    int wn = warp & 1;
    int mrow = wm * 16;
    int ncol0 = wn * 64;

    float4 xreg[8];
    {
        int t = blockIdx.x;
#pragma unroll
        for (int k = 0; k < 8; k++) {
            int i = tid + k * 256;
            int row = i >> 5, j = i & 31;
            int gr = t * 64 + row;
            xreg[k] = (gr < NN) ? X4[gr * 32 + j] : make_float4(0.f, 0.f, 0.f, 0.f);
        }
    }

    for (int t = blockIdx.x; t < nt_total; t += gridDim.x) {
#pragma unroll
        for (int k = 0; k < 8; k++) {
            int i = tid + k * 256;
            int row = i >> 5, j = i & 31;
            *(__half2*)&sA[row * LDSH + j * 4]     = __floats2half2_rn(xreg[k].x, xreg[k].y);
            *(__half2*)&sA[row * LDSH + j * 4 + 2] = __floats2half2_rn(xreg[k].z, xreg[k].w);
        }
        __syncthreads();

        int tn = t + gridDim.x;
        if (tn < nt_total) {
#pragma unroll
            for (int k = 0; k < 8; k++) {
                int i = tid + k * 256;
                int row = i >> 5, j = i & 31;
                int gr = tn * 64 + row;
                xreg[k] = (gr < NN) ? X4[gr * 32 + j] : make_float4(0.f, 0.f, 0.f, 0.f);
            }
        }

        float acc[8][4];
#pragma unroll
        for (int nt = 0; nt < 8; nt++)
            acc[nt][0] = acc[nt][1] = acc[nt][2] = acc[nt][3] = 0.f;

#pragma unroll
        for (int k0 = 0; k0 < 128; k0 += 16) {
            unsigned a0, a1, a2, a3;
            {
                int arow = mrow + (lane & 15);
                int acol = k0 + ((lane >> 4) << 3);
                unsigned aaddr = (unsigned)__cvta_generic_to_shared(&sA[arow * LDSH + acol]);
                asm volatile("ldmatrix.sync.aligned.m8n8.x4.shared.b16 {%0,%1,%2,%3}, [%4];"
                             : "=r"(a0), "=r"(a1), "=r"(a2), "=r"(a3) : "r"(aaddr));
            }
#pragma unroll
            for (int np = 0; np < 4; np++) {
                unsigned b0, b1, b2, b3;
                unsigned baddr = (unsigned)__cvta_generic_to_shared(
                    &sW[(k0 + (lane & 15)) * LDSH + ncol0 + np * 16 + ((lane >> 4) << 3)]);
                asm volatile("ldmatrix.sync.aligned.m8n8.x4.trans.shared.b16 {%0,%1,%2,%3}, [%4];"
                             : "=r"(b0), "=r"(b1), "=r"(b2), "=r"(b3) : "r"(baddr));
                asm volatile(
                    "mma.sync.aligned.m16n8k16.row.col.f32.f16.f16.f32 "
                    "{%0,%1,%2,%3}, {%4,%5,%6,%7}, {%8,%9}, {%0,%1,%2,%3};"
                    : "+f"(acc[np * 2][0]), "+f"(acc[np * 2][1]),
                      "+f"(acc[np * 2][2]), "+f"(acc[np * 2][3])
                    : "r"(a0), "r"(a1), "r"(a2), "r"(a3), "r"(b0), "r"(b1));
                asm volatile(
                    "mma.sync.aligned.m16n8k16.row.col.f32.f16.f16.f32 "
                    "{%0,%1,%2,%3}, {%4,%5,%6,%7}, {%8,%9}, {%0,%1,%2,%3};"
                    : "+f"(acc[np * 2 + 1][0]), "+f"(acc[np * 2 + 1][1]),
                      "+f"(acc[np * 2 + 1][2]), "+f"(acc[np * 2 + 1][3])
                    : "r"(a0), "r"(a1), "r"(a2), "r"(a3), "r"(b2), "r"(b3));
            }
        }

        int r = lane >> 2, c = (lane & 3) * 2;
        int gr0 = t * 64 + mrow + r;
        int gr1 = gr0 + 8;
        float d0 = (gr0 < NN) ? g_dinv[gr0] : 0.f;
        float d1 = (gr1 < NN) ? g_dinv[gr1] : 0.f;
#pragma unroll
        for (int nt = 0; nt < 8; nt++) {
            int col = ncol0 + nt * 8 + c;
            if (gr0 < NN)
                *(__half2*)&Y[gr0 * FD + col] =
                    __floats2half2_rn(acc[nt][0] * d0, acc[nt][1] * d0);
            if (gr1 < NN)
                *(__half2*)&Y[gr1 * FD + col] =
                    __floats2half2_rn(acc[nt][2] * d1, acc[nt][3] * d1);
        }
        __syncthreads();
    }
}

// ---------------- agg + bias + LN + ReLU: half-warp uint4 gathers ----------------
// warp per node; lane = (half = lane>>4, fg = lane&15); one uint4 load covers 2 edges.
__global__ __launch_bounds__(256) void agg_ln_relu_kernel(const __half* __restrict__ H,
                                                          float* __restrict__ Z,
                                                          const float* __restrict__ bias,
                                                          const float* __restrict__ gam,
                                                          const float* __restrict__ bet) {
    int gw = (blockIdx.x * blockDim.x + threadIdx.x) >> 5;
    if (gw >= NN) return;
    int lane = threadIdx.x & 31;
    int half = lane >> 4;
    int fg = lane & 15;
    int n = gw;
    int r0 = g_rowptr[n], r1 = g_rowptr[n + 1];
    float dn = g_dinv[n];
    const uint4* Hq = (const uint4*)H;

    float f[8];
#pragma unroll
    for (int j = 0; j < 8; j++) f[j] = 0.f;

#define ADDV(v)                                                        \
    {                                                                  \
        float2 t0 = __half22float2(*(__half2*)&(v).x);                 \
        float2 t1 = __half22float2(*(__half2*)&(v).y);                 \
        float2 t2 = __half22float2(*(__half2*)&(v).z);                 \
        float2 t3 = __half22float2(*(__half2*)&(v).w);                 \
        f[0] += t0.x; f[1] += t0.y; f[2] += t1.x; f[3] += t1.y;        \
        f[4] += t2.x; f[5] += t2.y; f[6] += t3.x; f[7] += t3.y;        \
    }

    int i = r0;
    for (; i + 8 <= r1; i += 8) {
        int s0 = g_esrc[i + 0 + half];
        int s1 = g_esrc[i + 2 + half];
        int s2 = g_esrc[i + 4 + half];
        int s3 = g_esrc[i + 6 + half];
        uint4 v0 = Hq[s0 * 16 + fg];
        uint4 v1 = Hq[s1 * 16 + fg];
        uint4 v2 = Hq[s2 * 16 + fg];
        uint4 v3 = Hq[s3 * 16 + fg];
        ADDV(v0) ADDV(v1) ADDV(v2) ADDV(v3)
    }
    for (; i + 2 <= r1; i += 2) {
        int s = g_esrc[i + half];
        uint4 v = Hq[s * 16 + fg];
        ADDV(v)
    }
    if (i < r1 && half == 0) {
        int s = g_esrc[i];
        uint4 v = Hq[s * 16 + fg];
        ADDV(v)
    }

    // combine even/odd halves (every lane ends with the full per-fg sum)
#pragma unroll
    for (int j = 0; j < 8; j++) f[j] += __shfl_xor_sync(0xffffffffu, f[j], 16);

    // self term once (post-combine so it isn't doubled)
    uint4 sv = Hq[n * 16 + fg];
    ADDV(sv)
#undef ADDV

    const float4* b4p = (const float4*)bias;
    float4 b0 = b4p[2 * fg], b1 = b4p[2 * fg + 1];
    f[0] = f[0] * dn + b0.x; f[1] = f[1] * dn + b0.y;
    f[2] = f[2] * dn + b0.z; f[3] = f[3] * dn + b0.w;
    f[4] = f[4] * dn + b1.x; f[5] = f[5] * dn + b1.y;
    f[6] = f[6] * dn + b1.z; f[7] = f[7] * dn + b1.w;

    // LN over 128 features; each feature appears in 2 lanes -> divide by 256
    float s = 0.f;
#pragma unroll
    for (int j = 0; j < 8; j++) s += f[j];
#pragma unroll
    for (int o = 16; o; o >>= 1) s += __shfl_xor_sync(0xffffffffu, s, o);
    float mean = s * (1.0f / 256.0f);
    float ss = 0.f;
#pragma unroll
    for (int j = 0; j < 8; j++) { f[j] -= mean; ss += f[j] * f[j]; }
#pragma unroll
    for (int o = 16; o; o >>= 1) ss += __shfl_xor_sync(0xffffffffu, ss, o);
    float rstd = rsqrtf(ss * (1.0f / 256.0f) + 1e-5f);

    const float4* g4p = (const float4*)gam;
    const float4* e4p = (const float4*)bet;
    float4 g0 = g4p[2 * fg], g1 = g4p[2 * fg + 1];
    float4 e0 = e4p[2 * fg], e1 = e4p[2 * fg + 1];
    if (half == 0) {
        float4 o0, o1;
        o0.x = fmaxf(f[0] * rstd * g0.x + e0.x, 0.f);
        o0.y = fmaxf(f[1] * rstd * g0.y + e0.y, 0.f);
        o0.z = fmaxf(f[2] * rstd * g0.z + e0.z, 0.f);
        o0.w = fmaxf(f[3] * rstd * g0.w + e0.w, 0.f);
        o1.x = fmaxf(f[4] * rstd * g1.x + e1.x, 0.f);
        o1.y = fmaxf(f[5] * rstd * g1.y + e1.y, 0.f);
        o1.z = fmaxf(f[6] * rstd * g1.z + e1.z, 0.f);
        o1.w = fmaxf(f[7] * rstd * g1.w + e1.w, 0.f);
        ((float4*)Z)[n * 32 + 2 * fg]     = o0;
        ((float4*)Z)[n * 32 + 2 * fg + 1] = o1;
    }
}

// ---------------- fused gate MLP + exp + pooled accumulation ----------------
// warp per 64-node contiguous chunk; no max-subtraction (gate values are O(1)).
__global__ __launch_bounds__(256) void gate_pool_kernel(const float* __restrict__ Z,
                                                        const float* __restrict__ Wg1,
                                                        const float* __restrict__ bg1,
                                                        const float* __restrict__ Wg2,
                                                        const float* __restrict__ bg2,
                                                        const int* __restrict__ batch) {
    __shared__ float sW1[FD * 64];
    __shared__ float sW2[64];
    __shared__ float sB1[64];
    int tid = threadIdx.x;
    for (int i = tid; i < FD * 64; i += 256) sW1[i] = Wg1[i];
    if (tid < 64) { sW2[tid] = Wg2[tid]; sB1[tid] = bg1[tid]; }
    __syncthreads();

    int warp = blockIdx.x * 8 + (tid >> 5);
    if (warp >= NCHUNK) return;
    int lane = tid & 31;
    int j0 = lane * 2;
    const float4* Z4 = (const float4*)Z;
    float bg2v = bg2[0];
    float s2a = sW2[j0], s2b = sW2[j0 + 1];
    float b1a = sB1[j0], b1b = sB1[j0 + 1];

    int n0 = warp * 64;
    int nend = min(n0 + 64, NN);

    float4 pacc = make_float4(0.f, 0.f, 0.f, 0.f);
    float eacc = 0.f;
    int curb = -1;

    for (int base = n0; base < nend; base += 4) {
        float4 xv[4];
#pragma unroll
        for (int r = 0; r < 4; r++)
            xv[r] = (base + r < nend) ? Z4[(base + r) * 32 + lane]
                                      : make_float4(0.f, 0.f, 0.f, 0.f);
        unsigned long long acc[4];
#pragma unroll
        for (int r = 0; r < 4; r++) acc[r] = pk2(0.f, 0.f);

#pragma unroll
        for (int kl = 0; kl < 32; kl++) {
            float2 w0 = *(const float2*)&sW1[(kl * 4 + 0) * 64 + j0];
            float2 w1 = *(const float2*)&sW1[(kl * 4 + 1) * 64 + j0];
            float2 w2 = *(const float2*)&sW1[(kl * 4 + 2) * 64 + j0];
            float2 w3 = *(const float2*)&sW1[(kl * 4 + 3) * 64 + j0];
            unsigned long long p0 = pk2(w0.x, w0.y), p1 = pk2(w1.x, w1.y);
            unsigned long long p2 = pk2(w2.x, w2.y), p3 = pk2(w3.x, w3.y);
#pragma unroll
            for (int r = 0; r < 4; r++) {
                float b0 = __shfl_sync(0xffffffffu, xv[r].x, kl);
                float b1 = __shfl_sync(0xffffffffu, xv[r].y, kl);
                float b2 = __shfl_sync(0xffffffffu, xv[r].z, kl);
                float b3 = __shfl_sync(0xffffffffu, xv[r].w, kl);
                fma2(acc[r], p0, pk2(b0, b0));
                fma2(acc[r], p1, pk2(b1, b1));
                fma2(acc[r], p2, pk2(b2, b2));
                fma2(acc[r], p3, pk2(b3, b3));
            }
        }
#pragma unroll
        for (int r = 0; r < 4; r++) {
            int n = base + r;
            if (n >= nend) break;
            float h0, h1;
            upk2(acc[r], h0, h1);
            h0 = fmaxf(h0 + b1a, 0.f);
            h1 = fmaxf(h1 + b1b, 0.f);
            float part = h0 * s2a + h1 * s2b;
#pragma unroll
            for (int o = 16; o; o >>= 1) part += __shfl_xor_sync(0xffffffffu, part, o);
            float e = expf(part + bg2v);
            int b = batch[n];
            if (b != curb) {
                if (curb >= 0) {
                    float* p = &g_pooled[curb * FD + lane * 4];
                    atomicAdd(p + 0, pacc.x); atomicAdd(p + 1, pacc.y);
                    atomicAdd(p + 2, pacc.z); atomicAdd(p + 3, pacc.w);
                    if (lane == 0) atomicAdd(&g_denom[curb], eacc);
                    pacc = make_float4(0.f, 0.f, 0.f, 0.f);
                    eacc = 0.f;
                }
                curb = b;
            }
            pacc.x += e * xv[r].x; pacc.y += e * xv[r].y;
            pacc.z += e * xv[r].z; pacc.w += e * xv[r].w;
            eacc += e;
        }
    }
    if (curb >= 0) {
        float* p = &g_pooled[curb * FD + lane * 4];
        atomicAdd(p + 0, pacc.x); atomicAdd(p + 1, pacc.y);
        atomicAdd(p + 2, pacc.z); atomicAdd(p + 3, pacc.w);
        if (lane == 0) atomicAdd(&g_denom[curb], eacc);
    }
}

__global__ __launch_bounds__(256) void cls_kernel(const float* __restrict__ Wc,
                                                  const float* __restrict__ bc,
                                                  float* __restrict__ out) {
    int t = blockIdx.x * blockDim.x + threadIdx.x;
    if (t < NB * NC) {
        int b = t >> 4, c = t & 15;
        float s = 0.f;
        const float* p = &g_pooled[b * FD];
#pragma unroll 16
        for (int j = 0; j < FD; j++) s += p[j] * Wc[j * NC + c];
        out[t] = s / g_denom[b] + bc[c];
    }
}

// ---------------- launch ----------------
extern "C" void kernel_launch(void* const* d_in, const int* in_sizes, int n_in,
                              void* d_out, int out_size) {
    const float* x    = (const float*)d_in[0];
    const int*   ei   = (const int*)d_in[1];
    const int*   batch= (const int*)d_in[2];
    const float* W1   = (const float*)d_in[3];
    const float* b1   = (const float*)d_in[4];
    const float* g1   = (const float*)d_in[5];
    const float* be1  = (const float*)d_in[6];
    const float* W2   = (const float*)d_in[7];
    const float* b2   = (const float*)d_in[8];
    const float* g2   = (const float*)d_in[9];
    const float* be2  = (const float*)d_in[10];
    const float* Wg1  = (const float*)d_in[11];
    const float* bg1  = (const float*)d_in[12];
    const float* Wg2  = (const float*)d_in[13];
    const float* bg2  = (const float*)d_in[14];
    const float* Wc   = (const float*)d_in[15];
    const float* bc   = (const float*)d_in[16];
    float* out = (float*)d_out;

    const int* src = ei;
    const int* dst = ei + NE;

    const int GEMM_SMEM = (128 + 64) * LDSH * (int)sizeof(__half);  // 52224 B

    static cudaStream_t s1 = nullptr;
    static cudaEvent_t evFork = nullptr, evDinv = nullptr, evJoin = nullptr;
    static bool attr_done = false;
    if (!attr_done) {
        cudaFuncSetAttribute(gemm_pers_kernel, cudaFuncAttributeMaxDynamicSharedMemorySize,
                             GEMM_SMEM);
        cudaStreamCreateWithFlags(&s1, cudaStreamNonBlocking);
        cudaEventCreateWithFlags(&evFork, cudaEventDisableTiming);
        cudaEventCreateWithFlags(&evDinv, cudaEventDisableTiming);
        cudaEventCreateWithFlags(&evJoin, cudaEventDisableTiming);
        attr_done = true;
    }

    __half* h16;  cudaGetSymbolAddress((void**)&h16, g_h16);
    float*  bufB; cudaGetSymbolAddress((void**)&bufB, g_bufB);
    __half* w16a; cudaGetSymbolAddress((void**)&w16a, g_W16a);
    __half* w16b; cudaGetSymbolAddress((void**)&w16b, g_W16b);

    const int GEMM_GRID = 296;

    // fork immediately: W conversions are independent of everything
    cudaEventRecord(evFork, 0);
    cudaStreamWaitEvent(s1, evFork, 0);
    w16_kernel<<<32, 256, 0, s1>>>(W1, w16a);
    w16_kernel<<<32, 256, 0, s1>>>(W2, w16b);

    // dinv production chain on main stream
    init_kernel<<<(NN + 255) / 256, 256>>>();
    deg_kernel<<<(NE + 255) / 256, 256>>>(dst);
    scanA_kernel<<<NPB, 512>>>();
    cudaEventRecord(evDinv, 0);

    // s1: GEMM-1 (needs x, W16a, dinv) overlaps rest of CSR build
    cudaStreamWaitEvent(s1, evDinv, 0);
    gemm_pers_kernel<<<GEMM_GRID, 256, GEMM_SMEM, s1>>>(x, w16a, h16);
    cudaEventRecord(evJoin, s1);

    scanB_kernel<<<1, 256>>>();
    scanC_kernel<<<NPB, 512>>>();
    fill_kernel<<<(NE + 255) / 256, 256>>>(src, dst);

    // join: agg1 needs both CSR and GEMM-1 output
    cudaStreamWaitEvent(0, evJoin, 0);
    agg_ln_relu_kernel<<<(NN * 32 + 255) / 256, 256>>>(h16, bufB, b1, g1, be1);
    // layer 2
    gemm_pers_kernel<<<GEMM_GRID, 256, GEMM_SMEM>>>(bufB, w16b, h16);
    agg_ln_relu_kernel<<<(NN * 32 + 255) / 256, 256>>>(h16, bufB, b2, g2, be2);

    // fused attention pooling
    gate_pool_kernel<<<(NCHUNK + 7) / 8, 256>>>(bufB, Wg1, bg1, Wg2, bg2, batch);

    // classifier (divides by denom)
    cls_kernel<<<(NB * NC + 255) / 256, 256>>>(Wc, bc, out);
}

// round 11
// speedup vs baseline: 3.2979x; 1.0284x over previous
#include <cuda_runtime.h>
#include <cuda_fp16.h>
#include <math.h>

#define NN 100000
#define NE 1600000
#define NB 64
#define FD 128
#define NC 16
#define NPB 196  // ceil(NN/512) scan blocks
#define LDSH 136 // padded smem leading dim (halves) for conflict-free ldmatrix
#define NCHUNK ((NN + 63) / 64)  // 1563 pooling chunks

// ---------------- scratch (device globals; no allocations) ----------------
__device__ __half   g_h16[NN * FD];   // fp16 scaled intermediate h~ = dinv * (X@W)
__device__ __half   g_z16[NN * FD];   // fp16 Z = relu(LN(agg))
__device__ __half   g_W16a[FD * FD];  // W1 in fp16
__device__ __half   g_W16b[FD * FD];  // W2 in fp16
__device__ float    g_dinv[NN];
__device__ int      g_indeg[NN];
__device__ int      g_ctr[NN];
__device__ int      g_rowptr[NN + 1];
__device__ int      g_part[NPB];
__device__ int      g_partoff[NPB];
__device__ int      g_esrc[NE];
__device__ float    g_denom[NB];
__device__ float    g_pooled[NB * FD];   // unnormalized: sum of exp(gate)*z

// ---------------- helpers ----------------
__device__ __forceinline__ unsigned long long pk2(float lo, float hi) {
    unsigned long long r;
    asm("mov.b64 %0, {%1,%2};" : "=l"(r) : "f"(lo), "f"(hi));
    return r;
}
__device__ __forceinline__ void upk2(unsigned long long v, float& lo, float& hi) {
    asm("mov.b64 {%0,%1}, %2;" : "=f"(lo), "=f"(hi) : "l"(v));
}
__device__ __forceinline__ void fma2(unsigned long long& acc, unsigned long long a,
                                     unsigned long long b) {
    asm("fma.rn.f32x2 %0, %1, %2, %0;" : "+l"(acc) : "l"(a), "l"(b));
}

// ---------------- setup kernels ----------------
__global__ __launch_bounds__(256) void init_kernel() {
    int i = blockIdx.x * blockDim.x + threadIdx.x;
    if (i < NN) { g_indeg[i] = 0; g_ctr[i] = 0; }
    if (i < NB * FD) g_pooled[i] = 0.f;
    if (i < NB) g_denom[i] = 0.f;
    if (i == 0) g_rowptr[NN] = NE;
}

__global__ __launch_bounds__(256) void w16_kernel(const float* __restrict__ W,
                                                  __half* __restrict__ O) {
    int i = blockIdx.x * 256 + threadIdx.x;
    if (i < FD * FD / 2) {
        float2 v = ((const float2*)W)[i];
        ((__half2*)O)[i] = __floats2half2_rn(v.x, v.y);
    }
}

__global__ __launch_bounds__(256) void deg_kernel(const int* __restrict__ dst) {
    int idx = blockIdx.x * blockDim.x + threadIdx.x;
    if (idx < NE / 4) {
        int4 d = ((const int4*)dst)[idx];
        atomicAdd(&g_indeg[d.x], 1);
        atomicAdd(&g_indeg[d.y], 1);
        atomicAdd(&g_indeg[d.z], 1);
        atomicAdd(&g_indeg[d.w], 1);
    }
}

__global__ __launch_bounds__(512) void scanA_kernel() {
    int t = threadIdx.x, b = blockIdx.x;
    int idx = b * 512 + t;
    int v = (idx < NN) ? g_indeg[idx] : 0;
    if (idx < NN) g_dinv[idx] = rsqrtf((float)(v + 1));
    int x = v;
#pragma unroll
    for (int o = 16; o; o >>= 1) x += __shfl_xor_sync(0xffffffffu, x, o);
    __shared__ int wsum[16];
    int lane = t & 31, wid = t >> 5;
    if (lane == 0) wsum[wid] = x;
    __syncthreads();
    if (t == 0) {
        int s = 0;
#pragma unroll
        for (int w = 0; w < 16; w++) s += wsum[w];
        g_part[b] = s;
    }
}

__global__ __launch_bounds__(256) void scanB_kernel() {
    int t = threadIdx.x;
    int v = (t < NPB) ? g_part[t] : 0;
    int lane = t & 31, wid = t >> 5;
    int x = v;
#pragma unroll
    for (int o = 1; o < 32; o <<= 1) {
        int y = __shfl_up_sync(0xffffffffu, x, o);
        if (lane >= o) x += y;
    }
    __shared__ int wsum[8];
    if (lane == 31) wsum[wid] = x;
    __syncthreads();
    if (wid == 0) {
        int s = (lane < 8) ? wsum[lane] : 0;
#pragma unroll
        for (int o = 1; o < 8; o <<= 1) {
            int y = __shfl_up_sync(0xffffffffu, s, o);
            if (lane >= o) s += y;
        }
        if (lane < 8) wsum[lane] = s;
    }
    __syncthreads();
    int excl = x - v + (wid > 0 ? wsum[wid - 1] : 0);
    if (t < NPB) g_partoff[t] = excl;
}

__global__ __launch_bounds__(512) void scanC_kernel() {
    int t = threadIdx.x, b = blockIdx.x;
    int idx = b * 512 + t;
    int v = (idx < NN) ? g_indeg[idx] : 0;
    int lane = t & 31, wid = t >> 5;
    int x = v;
#pragma unroll
    for (int o = 1; o < 32; o <<= 1) {
        int y = __shfl_up_sync(0xffffffffu, x, o);
        if (lane >= o) x += y;
    }
    __shared__ int wsum[16];
    if (lane == 31) wsum[wid] = x;
    __syncthreads();
    if (wid == 0) {
        int s = (lane < 16) ? wsum[lane] : 0;
#pragma unroll
        for (int o = 1; o < 16; o <<= 1) {
            int y = __shfl_up_sync(0xffffffffu, s, o);
            if (lane >= o) s += y;
        }
        if (lane < 16) wsum[lane] = s;
    }
    __syncthreads();
    int excl = x - v + (wid > 0 ? wsum[wid - 1] : 0);
    if (idx < NN) g_rowptr[idx] = g_partoff[b] + excl;
}

__global__ __launch_bounds__(256) void fill_kernel(const int* __restrict__ src,
                                                   const int* __restrict__ dst) {
    int e = blockIdx.x * blockDim.x + threadIdx.x;
    if (e < NE) {
        int d = dst[e];
        int p = g_rowptr[d] + atomicAdd(&g_ctr[d], 1);
        g_esrc[p] = src[e];
    }
}

// ---------------- shared GEMM core (sA/sW staged fp16) ----------------
__device__ __forceinline__ void gemm_tile_compute(const __half* sA, const __half* sW,
                                                  int mrow, int ncol0, int lane,
                                                  float acc[8][4]) {
#pragma unroll
    for (int nt = 0; nt < 8; nt++)
        acc[nt][0] = acc[nt][1] = acc[nt][2] = acc[nt][3] = 0.f;
#pragma unroll
    for (int k0 = 0; k0 < 128; k0 += 16) {
        unsigned a0, a1, a2, a3;
        {
            int arow = mrow + (lane & 15);
            int acol = k0 + ((lane >> 4) << 3);
            unsigned aaddr = (unsigned)__cvta_generic_to_shared(&sA[arow * LDSH + acol]);
            asm volatile("ldmatrix.sync.aligned.m8n8.x4.shared.b16 {%0,%1,%2,%3}, [%4];"
                         : "=r"(a0), "=r"(a1), "=r"(a2), "=r"(a3) : "r"(aaddr));
        }
#pragma unroll
        for (int np = 0; np < 4; np++) {
            unsigned b0, b1, b2, b3;
            unsigned baddr = (unsigned)__cvta_generic_to_shared(
                &sW[(k0 + (lane & 15)) * LDSH + ncol0 + np * 16 + ((lane >> 4) << 3)]);
            asm volatile("ldmatrix.sync.aligned.m8n8.x4.trans.shared.b16 {%0,%1,%2,%3}, [%4];"
                         : "=r"(b0), "=r"(b1), "=r"(b2), "=r"(b3) : "r"(baddr));
            asm volatile(
                "mma.sync.aligned.m16n8k16.row.col.f32.f16.f16.f32 "
                "{%0,%1,%2,%3}, {%4,%5,%6,%7}, {%8,%9}, {%0,%1,%2,%3};"
                : "+f"(acc[np * 2][0]), "+f"(acc[np * 2][1]),
                  "+f"(acc[np * 2][2]), "+f"(acc[np * 2][3])
                : "r"(a0), "r"(a1), "r"(a2), "r"(a3), "r"(b0), "r"(b1));
            asm volatile(
                "mma.sync.aligned.m16n8k16.row.col.f32.f16.f16.f32 "
                "{%0,%1,%2,%3}, {%4,%5,%6,%7}, {%8,%9}, {%0,%1,%2,%3};"
                : "+f"(acc[np * 2 + 1][0]), "+f"(acc[np * 2 + 1][1]),
                  "+f"(acc[np * 2 + 1][2]), "+f"(acc[np * 2 + 1][3])
                : "r"(a0), "r"(a1), "r"(a2), "r"(a3), "r"(b2), "r"(b3));
        }
    }
}

__device__ __forceinline__ void gemm_epilogue(float acc[8][4], __half* Y,
                                              int t, int mrow, int ncol0, int lane) {
    int r = lane >> 2, c = (lane & 3) * 2;
    int gr0 = t * 64 + mrow + r;
    int gr1 = gr0 + 8;
    float d0 = (gr0 < NN) ? g_dinv[gr0] : 0.f;
    float d1 = (gr1 < NN) ? g_dinv[gr1] : 0.f;
#pragma unroll
    for (int nt = 0; nt < 8; nt++) {
        int col = ncol0 + nt * 8 + c;
        if (gr0 < NN)
            *(__half2*)&Y[gr0 * FD + col] = __floats2half2_rn(acc[nt][0] * d0, acc[nt][1] * d0);
        if (gr1 < NN)
            *(__half2*)&Y[gr1 * FD + col] = __floats2half2_rn(acc[nt][2] * d1, acc[nt][3] * d1);
    }
}

// ---------------- persistent GEMM, fp32 input: H~ = dinv * (X @ W16) ----------------
__global__ __launch_bounds__(256, 2) void gemm_pers_kernel(const float* __restrict__ X,
                                                           const __half* __restrict__ W16,
                                                           __half* __restrict__ Y) {
    extern __shared__ __half smemh[];
    __half* sW = smemh;               // [128][LDSH]
    __half* sA = smemh + 128 * LDSH;  // [64][LDSH]
    int tid = threadIdx.x;

    {
        const uint4* W4 = (const uint4*)W16;
        for (int i = tid; i < 128 * 16; i += 256) {
            int row = i >> 4, j = i & 15;
            *(uint4*)&sW[row * LDSH + j * 8] = W4[i];
        }
    }

    const int nt_total = (NN + 63) >> 6;
    const float4* X4 = (const float4*)X;
    int warp = tid >> 5, lane = tid & 31;
    int mrow = (warp >> 1) * 16;
    int ncol0 = (warp & 1) * 64;

    float4 xreg[8];
    {
        int t = blockIdx.x;
#pragma unroll
        for (int k = 0; k < 8; k++) {
            int i = tid + k * 256;
            int row = i >> 5, j = i & 31;
            int gr = t * 64 + row;
            xreg[k] = (gr < NN) ? X4[gr * 32 + j] : make_float4(0.f, 0.f, 0.f, 0.f);
        }
    }

    for (int t = blockIdx.x; t < nt_total; t += gridDim.x) {
#pragma unroll
        for (int k = 0; k < 8; k++) {
            int i = tid + k * 256;
            int row = i >> 5, j = i & 31;
            *(__half2*)&sA[row * LDSH + j * 4]     = __floats2half2_rn(xreg[k].x, xreg[k].y);
            *(__half2*)&sA[row * LDSH + j * 4 + 2] = __floats2half2_rn(xreg[k].z, xreg[k].w);
        }
        __syncthreads();

        int tn = t + gridDim.x;
        if (tn < nt_total) {
#pragma unroll
            for (int k = 0; k < 8; k++) {
                int i = tid + k * 256;
                int row = i >> 5, j = i & 31;
                int gr = tn * 64 + row;
                xreg[k] = (gr < NN) ? X4[gr * 32 + j] : make_float4(0.f, 0.f, 0.f, 0.f);
            }
        }

        float acc[8][4];
        gemm_tile_compute(sA, sW, mrow, ncol0, lane, acc);
        gemm_epilogue(acc, Y, t, mrow, ncol0, lane);
        __syncthreads();
    }
}

// ---------------- persistent GEMM, fp16 input: H~ = dinv * (Z16 @ W16) ----------------
__global__ __launch_bounds__(256, 2) void gemm_pers16_kernel(const __half* __restrict__ X16,
                                                             const __half* __restrict__ W16,
                                                             __half* __restrict__ Y) {
    extern __shared__ __half smemh[];
    __half* sW = smemh;
    __half* sA = smemh + 128 * LDSH;
    int tid = threadIdx.x;

    {
        const uint4* W4 = (const uint4*)W16;
        for (int i = tid; i < 128 * 16; i += 256) {
            int row = i >> 4, j = i & 15;
            *(uint4*)&sW[row * LDSH + j * 8] = W4[i];
        }
    }

    const int nt_total = (NN + 63) >> 6;
    const uint4* Xq = (const uint4*)X16;  // 16 uint4 per row
    int warp = tid >> 5, lane = tid & 31;
    int mrow = (warp >> 1) * 16;
    int ncol0 = (warp & 1) * 64;

    uint4 xreg[4];
    {
        int t = blockIdx.x;
#pragma unroll
        for (int k = 0; k < 4; k++) {
            int i = tid + k * 256;
            int row = i >> 4, j = i & 15;
            int gr = t * 64 + row;
            xreg[k] = (gr < NN) ? Xq[gr * 16 + j] : make_uint4(0u, 0u, 0u, 0u);
        }
    }

    for (int t = blockIdx.x; t < nt_total; t += gridDim.x) {
#pragma unroll
        for (int k = 0; k < 4; k++) {
            int i = tid + k * 256;
            int row = i >> 4, j = i & 15;
            *(uint4*)&sA[row * LDSH + j * 8] = xreg[k];
        }
        __syncthreads();

        int tn = t + gridDim.x;
        if (tn < nt_total) {
#pragma unroll
            for (int k = 0; k < 4; k++) {
                int i = tid + k * 256;
                int row = i >> 4, j = i & 15;
                int gr = tn * 64 + row;
                xreg[k] = (gr < NN) ? Xq[gr * 16 + j] : make_uint4(0u, 0u, 0u, 0u);
            }
        }

        float acc[8][4];
        gemm_tile_compute(sA, sW, mrow, ncol0, lane, acc);
        gemm_epilogue(acc, Y, t, mrow, ncol0, lane);
        __syncthreads();
    }
}

// ---------------- agg + bias + LN + ReLU: half-warp uint4 gathers, fp16 out ----------------
__global__ __launch_bounds__(256) void agg_ln_relu_kernel(const __half* __restrict__ H,
                                                          __half* __restrict__ Z,
                                                          const float* __restrict__ bias,
                                                          const float* __restrict__ gam,
                                                          const float* __restrict__ bet) {
    int gw = (blockIdx.x * blockDim.x + threadIdx.x) >> 5;
    if (gw >= NN) return;
    int lane = threadIdx.x & 31;
    int half = lane >> 4;
    int fg = lane & 15;
    int n = gw;
    int r0 = g_rowptr[n], r1 = g_rowptr[n + 1];
    float dn = g_dinv[n];
    const uint4* Hq = (const uint4*)H;

    float f[8];
#pragma unroll
    for (int j = 0; j < 8; j++) f[j] = 0.f;

#define ADDV(v)                                                        \
    {                                                                  \
        float2 t0 = __half22float2(*(__half2*)&(v).x);                 \
        float2 t1 = __half22float2(*(__half2*)&(v).y);                 \
        float2 t2 = __half22float2(*(__half2*)&(v).z);                 \
        float2 t3 = __half22float2(*(__half2*)&(v).w);                 \
        f[0] += t0.x; f[1] += t0.y; f[2] += t1.x; f[3] += t1.y;        \
        f[4] += t2.x; f[5] += t2.y; f[6] += t3.x; f[7] += t3.y;        \
    }

    int i = r0;
    for (; i + 8 <= r1; i += 8) {
        int s0 = g_esrc[i + 0 + half];
        int s1 = g_esrc[i + 2 + half];
        int s2 = g_esrc[i + 4 + half];
        int s3 = g_esrc[i + 6 + half];
        uint4 v0 = Hq[s0 * 16 + fg];
        uint4 v1 = Hq[s1 * 16 + fg];
        uint4 v2 = Hq[s2 * 16 + fg];
        uint4 v3 = Hq[s3 * 16 + fg];
        ADDV(v0) ADDV(v1) ADDV(v2) ADDV(v3)
    }
    for (; i + 2 <= r1; i += 2) {
        int s = g_esrc[i + half];
        uint4 v = Hq[s * 16 + fg];
        ADDV(v)
    }
    if (i < r1 && half == 0) {
        int s = g_esrc[i];
        uint4 v = Hq[s * 16 + fg];
        ADDV(v)
    }

#pragma unroll
    for (int j = 0; j < 8; j++) f[j] += __shfl_xor_sync(0xffffffffu, f[j], 16);

    uint4 sv = Hq[n * 16 + fg];
    ADDV(sv)
#undef ADDV

    const float4* b4p = (const float4*)bias;
    float4 b0 = b4p[2 * fg], b1 = b4p[2 * fg + 1];
    f[0] = f[0] * dn + b0.x; f[1] = f[1] * dn + b0.y;
    f[2] = f[2] * dn + b0.z; f[3] = f[3] * dn + b0.w;
    f[4] = f[4] * dn + b1.x; f[5] = f[5] * dn + b1.y;
    f[6] = f[6] * dn + b1.z; f[7] = f[7] * dn + b1.w;

    float s = 0.f;
#pragma unroll
    for (int j = 0; j < 8; j++) s += f[j];
#pragma unroll
    for (int o = 16; o; o >>= 1) s += __shfl_xor_sync(0xffffffffu, s, o);
    float mean = s * (1.0f / 256.0f);
    float ss = 0.f;
#pragma unroll
    for (int j = 0; j < 8; j++) { f[j] -= mean; ss += f[j] * f[j]; }
#pragma unroll
    for (int o = 16; o; o >>= 1) ss += __shfl_xor_sync(0xffffffffu, ss, o);
    float rstd = rsqrtf(ss * (1.0f / 256.0f) + 1e-5f);

    const float4* g4p = (const float4*)gam;
    const float4* e4p = (const float4*)bet;
    float4 g0 = g4p[2 * fg], g1 = g4p[2 * fg + 1];
    float4 e0 = e4p[2 * fg], e1 = e4p[2 * fg + 1];
    if (half == 0) {
        float o0 = fmaxf(f[0] * rstd * g0.x + e0.x, 0.f);
        float o1 = fmaxf(f[1] * rstd * g0.y + e0.y, 0.f);
        float o2 = fmaxf(f[2] * rstd * g0.z + e0.z, 0.f);
        float o3 = fmaxf(f[3] * rstd * g0.w + e0.w, 0.f);
        float o4 = fmaxf(f[4] * rstd * g1.x + e1.x, 0.f);
        float o5 = fmaxf(f[5] * rstd * g1.y + e1.y, 0.f);
        float o6 = fmaxf(f[6] * rstd * g1.z + e1.z, 0.f);
        float o7 = fmaxf(f[7] * rstd * g1.w + e1.w, 0.f);
        __half2 p0 = __floats2half2_rn(o0, o1);
        __half2 p1 = __floats2half2_rn(o2, o3);
        __half2 p2 = __floats2half2_rn(o4, o5);
        __half2 p3 = __floats2half2_rn(o6, o7);
        uint4 st;
        st.x = *(unsigned*)&p0; st.y = *(unsigned*)&p1;
        st.z = *(unsigned*)&p2; st.w = *(unsigned*)&p3;
        ((uint4*)Z)[n * 16 + fg] = st;
    }
}

// ---------------- fused gate MLP + exp + pooled accumulation (fp16 Z) ----------------
__global__ __launch_bounds__(256) void gate_pool_kernel(const __half* __restrict__ Z,
                                                        const float* __restrict__ Wg1,
                                                        const float* __restrict__ bg1,
                                                        const float* __restrict__ Wg2,
                                                        const float* __restrict__ bg2,
                                                        const int* __restrict__ batch) {
    __shared__ float sW1[FD * 64];
    __shared__ float sW2[64];
    __shared__ float sB1[64];
    int tid = threadIdx.x;
    for (int i = tid; i < FD * 64; i += 256) sW1[i] = Wg1[i];
    if (tid < 64) { sW2[tid] = Wg2[tid]; sB1[tid] = bg1[tid]; }
    __syncthreads();

    int warp = blockIdx.x * 8 + (tid >> 5);
    if (warp >= NCHUNK) return;
    int lane = tid & 31;
    int j0 = lane * 2;
    const uint2* Z2 = (const uint2*)Z;
    float bg2v = bg2[0];
    float s2a = sW2[j0], s2b = sW2[j0 + 1];
    float b1a = sB1[j0], b1b = sB1[j0 + 1];

    int n0 = warp * 64;
    int nend = min(n0 + 64, NN);

    float4 pacc = make_float4(0.f, 0.f, 0.f, 0.f);
    float eacc = 0.f;
    int curb = -1;

    for (int base = n0; base < nend; base += 4) {
        float4 xv[4];
#pragma unroll
        for (int r = 0; r < 4; r++) {
            if (base + r < nend) {
                uint2 v = Z2[(base + r) * 32 + lane];
                float2 a = __half22float2(*(__half2*)&v.x);
                float2 b = __half22float2(*(__half2*)&v.y);
                xv[r] = make_float4(a.x, a.y, b.x, b.y);
            } else {
                xv[r] = make_float4(0.f, 0.f, 0.f, 0.f);
            }
        }
        unsigned long long acc[4];
#pragma unroll
        for (int r = 0; r < 4; r++) acc[r] = pk2(0.f, 0.f);

#pragma unroll
        for (int kl = 0; kl < 32; kl++) {
            float2 w0 = *(const float2*)&sW1[(kl * 4 + 0) * 64 + j0];
            float2 w1 = *(const float2*)&sW1[(kl * 4 + 1) * 64 + j0];
            float2 w2 = *(const float2*)&sW1[(kl * 4 + 2) * 64 + j0];
            float2 w3 = *(const float2*)&sW1[(kl * 4 + 3) * 64 + j0];
            unsigned long long p0 = pk2(w0.x, w0.y), p1 = pk2(w1.x, w1.y);
            unsigned long long p2 = pk2(w2.x, w2.y), p3 = pk2(w3.x, w3.y);
#pragma unroll
            for (int r = 0; r < 4; r++) {
                float b0 = __shfl_sync(0xffffffffu, xv[r].x, kl);
                float b1 = __shfl_sync(0xffffffffu, xv[r].y, kl);
                float b2 = __shfl_sync(0xffffffffu, xv[r].z, kl);
                float b3 = __shfl_sync(0xffffffffu, xv[r].w, kl);
                fma2(acc[r], p0, pk2(b0, b0));
                fma2(acc[r], p1, pk2(b1, b1));
                fma2(acc[r], p2, pk2(b2, b2));
                fma2(acc[r], p3, pk2(b3, b3));
            }
        }
#pragma unroll
        for (int r = 0; r < 4; r++) {
            int n = base + r;
            if (n >= nend) break;
            float h0, h1;
            upk2(acc[r], h0, h1);
            h0 = fmaxf(h0 + b1a, 0.f);
            h1 = fmaxf(h1 + b1b, 0.f);
            float part = h0 * s2a + h1 * s2b;
#pragma unroll
            for (int o = 16; o; o >>= 1) part += __shfl_xor_sync(0xffffffffu, part, o);
            float e = expf(part + bg2v);
            int b = batch[n];
            if (b != curb) {
                if (curb >= 0) {
                    float* p = &g_pooled[curb * FD + lane * 4];
                    atomicAdd(p + 0, pacc.x); atomicAdd(p + 1, pacc.y);
                    atomicAdd(p + 2, pacc.z); atomicAdd(p + 3, pacc.w);
                    if (lane == 0) atomicAdd(&g_denom[curb], eacc);
                    pacc = make_float4(0.f, 0.f, 0.f, 0.f);
                    eacc = 0.f;
                }
                curb = b;
            }
            pacc.x += e * xv[r].x; pacc.y += e * xv[r].y;
            pacc.z += e * xv[r].z; pacc.w += e * xv[r].w;
            eacc += e;
        }
    }
    if (curb >= 0) {
        float* p = &g_pooled[curb * FD + lane * 4];
        atomicAdd(p + 0, pacc.x); atomicAdd(p + 1, pacc.y);
        atomicAdd(p + 2, pacc.z); atomicAdd(p + 3, pacc.w);
        if (lane == 0) atomicAdd(&g_denom[curb], eacc);
    }
}

__global__ __launch_bounds__(256) void cls_kernel(const float* __restrict__ Wc,
                                                  const float* __restrict__ bc,
                                                  float* __restrict__ out) {
    int t = blockIdx.x * blockDim.x + threadIdx.x;
    if (t < NB * NC) {
        int b = t >> 4, c = t & 15;
        float s = 0.f;
        const float* p = &g_pooled[b * FD];
#pragma unroll 16
        for (int j = 0; j < FD; j++) s += p[j] * Wc[j * NC + c];
        out[t] = s / g_denom[b] + bc[c];
    }
}

// ---------------- launch ----------------
extern "C" void kernel_launch(void* const* d_in, const int* in_sizes, int n_in,
                              void* d_out, int out_size) {
    const float* x    = (const float*)d_in[0];
    const int*   ei   = (const int*)d_in[1];
    const int*   batch= (const int*)d_in[2];
    const float* W1   = (const float*)d_in[3];
    const float* b1   = (const float*)d_in[4];
    const float* g1   = (const float*)d_in[5];
    const float* be1  = (const float*)d_in[6];
    const float* W2   = (const float*)d_in[7];
    const float* b2   = (const float*)d_in[8];
    const float* g2   = (const float*)d_in[9];
    const float* be2  = (const float*)d_in[10];
    const float* Wg1  = (const float*)d_in[11];
    const float* bg1  = (const float*)d_in[12];
    const float* Wg2  = (const float*)d_in[13];
    const float* bg2  = (const float*)d_in[14];
    const float* Wc   = (const float*)d_in[15];
    const float* bc   = (const float*)d_in[16];
    float* out = (float*)d_out;

    const int* src = ei;
    const int* dst = ei + NE;

    const int GEMM_SMEM = (128 + 64) * LDSH * (int)sizeof(__half);  // 52224 B

    static cudaStream_t s1 = nullptr;
    static cudaEvent_t evFork = nullptr, evDinv = nullptr, evJoin = nullptr;
    static bool attr_done = false;
    if (!attr_done) {
        cudaFuncSetAttribute(gemm_pers_kernel, cudaFuncAttributeMaxDynamicSharedMemorySize,
                             GEMM_SMEM);
        cudaFuncSetAttribute(gemm_pers16_kernel, cudaFuncAttributeMaxDynamicSharedMemorySize,
                             GEMM_SMEM);
        cudaStreamCreateWithFlags(&s1, cudaStreamNonBlocking);
        cudaEventCreateWithFlags(&evFork, cudaEventDisableTiming);
        cudaEventCreateWithFlags(&evDinv, cudaEventDisableTiming);
        cudaEventCreateWithFlags(&evJoin, cudaEventDisableTiming);
        attr_done = true;
    }

    __half* h16;  cudaGetSymbolAddress((void**)&h16, g_h16);
    __half* z16;  cudaGetSymbolAddress((void**)&z16, g_z16);
    __half* w16a; cudaGetSymbolAddress((void**)&w16a, g_W16a);
    __half* w16b; cudaGetSymbolAddress((void**)&w16b, g_W16b);

    const int GEMM_GRID = 296;

    // fork immediately: W conversions are independent of everything
    cudaEventRecord(evFork, 0);
    cudaStreamWaitEvent(s1, evFork, 0);
    w16_kernel<<<32, 256, 0, s1>>>(W1, w16a);
    w16_kernel<<<32, 256, 0, s1>>>(W2, w16b);

    // dinv production chain on main stream
    init_kernel<<<(NN + 255) / 256, 256>>>();
    deg_kernel<<<(NE / 4 + 255) / 256, 256>>>(dst);
    scanA_kernel<<<NPB, 512>>>();
    cudaEventRecord(evDinv, 0);

    // s1: GEMM-1 (needs x, W16a, dinv) overlaps rest of CSR build
    cudaStreamWaitEvent(s1, evDinv, 0);
    gemm_pers_kernel<<<GEMM_GRID, 256, GEMM_SMEM, s1>>>(x, w16a, h16);
    cudaEventRecord(evJoin, s1);

    scanB_kernel<<<1, 256>>>();
    scanC_kernel<<<NPB, 512>>>();
    fill_kernel<<<(NE + 255) / 256, 256>>>(src, dst);

    // join: agg1 needs both CSR and GEMM-1 output
    cudaStreamWaitEvent(0, evJoin, 0);
    agg_ln_relu_kernel<<<(NN * 32 + 255) / 256, 256>>>(h16, z16, b1, g1, be1);
    // layer 2 (fp16 input)
    gemm_pers16_kernel<<<GEMM_GRID, 256, GEMM_SMEM>>>(z16, w16b, h16);
    agg_ln_relu_kernel<<<(NN * 32 + 255) / 256, 256>>>(h16, z16, b2, g2, be2);

    // fused attention pooling (fp16 Z)
    gate_pool_kernel<<<(NCHUNK + 7) / 8, 256>>>(z16, Wg1, bg1, Wg2, bg2, batch);

    // classifier (divides by denom)
    cls_kernel<<<(NB * NC + 255) / 256, 256>>>(Wc, bc, out);
}